// round 2
// baseline (speedup 1.0000x reference)
#include <cuda_runtime.h>
#include <cstdint>

#define B_    4
#define N_    2048
#define DIM_  768
#define H_    12
#define DH_   64
#define M_TOT (B_ * N_)       // 8192
#define QKV_N (3 * DIM_)      // 2304
#define SCALE_ 0.125f         // 64^-0.5

typedef unsigned long long ull;

// ---- packed f32x2 primitives (FFMA2 path — ptxas never auto-generates) ----
__device__ __forceinline__ ull pack2(float v) {
    ull r; asm("mov.b64 %0, {%1, %1};" : "=l"(r) : "f"(v)); return r;
}
__device__ __forceinline__ ull ffma2(ull a, ull b, ull c) {
    ull d; asm("fma.rn.f32x2 %0, %1, %2, %3;" : "=l"(d) : "l"(a), "l"(b), "l"(c));
    return d;
}
__device__ __forceinline__ ull fmul2(ull a, ull b) {
    ull d; asm("mul.rn.f32x2 %0, %1, %2;" : "=l"(d) : "l"(a), "l"(b)); return d;
}
__device__ __forceinline__ float2 unpack2(ull v) {
    float2 f; asm("mov.b64 {%0, %1}, %2;" : "=f"(f.x), "=f"(f.y) : "l"(v)); return f;
}

// Scratch (device globals — allocation-free per harness rules)
__device__ float g_qkv[(size_t)M_TOT * QKV_N];   // [8192, 2304]
__device__ float g_attn[(size_t)M_TOT * DIM_];   // [8192, 768]

// ---------------------------------------------------------------------------
// SGEMM: C[M,N] = A[M,K] @ B[K,N] (+ bias). 128x128 tile, BK=8, 256 thr,
// 8x8 microtile computed as 8x4 FFMA2 pairs. Double-buffered smem.
// ---------------------------------------------------------------------------
constexpr int BM = 128, BN = 128, BK = 8, TM = 8, TN = 8;

__global__ __launch_bounds__(256) void sgemm_kernel(
    const float* __restrict__ A, const float* __restrict__ Bm,
    float* __restrict__ C, int M, int N, int K,
    const float* __restrict__ bias)
{
    __shared__ __align__(16) float As[2][BK][BM];   // transposed A tile
    __shared__ __align__(16) float Bs[2][BK][BN];

    const int tid  = threadIdx.x;
    const int bm   = blockIdx.y * BM;
    const int bn   = blockIdx.x * BN;

    const int aRow = tid >> 1;            // 0..127
    const int aCol = (tid & 1) << 2;      // 0 or 4
    const int bRow = tid >> 5;            // 0..7
    const int bCol = (tid & 31) << 2;     // 0..124

    const int tr = (tid >> 4) * TM;       // 0..120
    const int tc = (tid & 15) * TN;       // 0..120

    ull acc2[TM][TN / 2] = {};            // packed pairs along N

    // prologue: tile 0 -> smem buf 0
    {
        float4 a4 = *(const float4*)(A + (size_t)(bm + aRow) * K + aCol);
        As[0][aCol + 0][aRow] = a4.x;
        As[0][aCol + 1][aRow] = a4.y;
        As[0][aCol + 2][aRow] = a4.z;
        As[0][aCol + 3][aRow] = a4.w;
        *(float4*)&Bs[0][bRow][bCol] =
            *(const float4*)(Bm + (size_t)bRow * N + bn + bCol);
    }
    __syncthreads();

    int buf = 0;
    float4 a_nxt, b_nxt;

    for (int k0 = 0; k0 < K; k0 += BK) {
        const bool more = (k0 + BK) < K;
        if (more) {
            a_nxt = *(const float4*)(A + (size_t)(bm + aRow) * K + k0 + BK + aCol);
            b_nxt = *(const float4*)(Bm + (size_t)(k0 + BK + bRow) * N + bn + bCol);
        }

        #pragma unroll
        for (int k = 0; k < BK; k++) {
            float4 a0 = *(const float4*)&As[buf][k][tr];
            float4 a1 = *(const float4*)&As[buf][k][tr + 4];
            ulonglong2 b0 = *(const ulonglong2*)&Bs[buf][k][tc];
            ulonglong2 b1 = *(const ulonglong2*)&Bs[buf][k][tc + 4];
            ull ra2[8];
            ra2[0] = pack2(a0.x); ra2[1] = pack2(a0.y);
            ra2[2] = pack2(a0.z); ra2[3] = pack2(a0.w);
            ra2[4] = pack2(a1.x); ra2[5] = pack2(a1.y);
            ra2[6] = pack2(a1.z); ra2[7] = pack2(a1.w);
            ull rb2[4] = {b0.x, b0.y, b1.x, b1.y};
            #pragma unroll
            for (int i = 0; i < TM; i++)
                #pragma unroll
                for (int jp = 0; jp < TN / 2; jp++)
                    acc2[i][jp] = ffma2(ra2[i], rb2[jp], acc2[i][jp]);
        }

        if (more) {
            int nb = buf ^ 1;
            As[nb][aCol + 0][aRow] = a_nxt.x;
            As[nb][aCol + 1][aRow] = a_nxt.y;
            As[nb][aCol + 2][aRow] = a_nxt.z;
            As[nb][aCol + 3][aRow] = a_nxt.w;
            *(float4*)&Bs[nb][bRow][bCol] = b_nxt;
            __syncthreads();
            buf = nb;
        }
    }

    #pragma unroll
    for (int i = 0; i < TM; i++) {
        float* crow = C + (size_t)(bm + tr + i) * N + bn + tc;
        #pragma unroll
        for (int jp = 0; jp < TN / 2; jp += 2) {
            float2 p0 = unpack2(acc2[i][jp]);
            float2 p1 = unpack2(acc2[i][jp + 1]);
            float4 v;
            v.x = p0.x; v.y = p0.y; v.z = p1.x; v.w = p1.y;
            if (bias) {
                int c0 = bn + tc + jp * 2;
                v.x += bias[c0 + 0];
                v.y += bias[c0 + 1];
                v.z += bias[c0 + 2];
                v.w += bias[c0 + 3];
            }
            *(float4*)(crow + jp * 2) = v;
        }
    }
}

// ---------------------------------------------------------------------------
// Flash attention (fp32, FFMA2 inner loops). One block = 64 query rows of one
// (b,h). Q stored DUPLICATED d-major (broadcast pairs load as ulonglong2).
// K d-major, V row-major, P staged row-major.
// 256 threads: (ty,tx) 16x16, 4x4 microtile (as 4x2 packed pairs).
// ---------------------------------------------------------------------------
#define FT     64
#define SSTR   68
#define Q2STR  136
#define FLASH_SMEM ((FT * Q2STR + 3 * FT * SSTR) * (int)sizeof(float))  // 87040

__global__ __launch_bounds__(256) void flash_kernel(
    const float* __restrict__ qkv, float* __restrict__ out)
{
    extern __shared__ __align__(16) float sm[];
    float* q2_s = sm;                    // [64 d][136]  duplicated pairs
    float* k_s  = q2_s + FT * Q2STR;     // [64 d][68]
    float* v_s  = k_s + FT * SSTR;       // [64 r][68]
    float* p_s  = v_s + FT * SSTR;       // [64 r][68]

    const int tid = threadIdx.x;
    const int bh  = blockIdx.y;
    const int b   = bh / H_;
    const int h   = bh % H_;
    const int q0  = blockIdx.x * FT;

    const size_t rowbase = (size_t)b * N_ * QKV_N;
    const int qoff = h * DH_;
    const int koff = DIM_ + h * DH_;
    const int voff = 2 * DIM_ + h * DH_;

    // Load Q tile once (transposed + duplicated), pre-scaled
    #pragma unroll
    for (int i = 0; i < 16; i++) {
        int idx = tid + i * 256;
        int r = idx >> 6, d = idx & 63;
        float qv = qkv[rowbase + (size_t)(q0 + r) * QKV_N + qoff + d] * SCALE_;
        q2_s[d * Q2STR + 2 * r]     = qv;
        q2_s[d * Q2STR + 2 * r + 1] = qv;
    }

    const int ty = tid >> 4, tx = tid & 15;

    float m_i[4], l_i[4];
    ull acc2[4][2];
    #pragma unroll
    for (int i = 0; i < 4; i++) {
        m_i[i] = -1e30f;
        l_i[i] = 0.0f;
        acc2[i][0] = 0ull;
        acc2[i][1] = 0ull;
    }

    for (int t = 0; t < N_ / FT; t++) {
        __syncthreads();   // protect k_s/v_s/p_s from previous-iter readers
        const int kr0 = t * FT;
        #pragma unroll
        for (int i = 0; i < 16; i++) {
            int idx = tid + i * 256;
            int r = idx >> 6, d = idx & 63;
            size_t g = rowbase + (size_t)(kr0 + r) * QKV_N;
            k_s[d * SSTR + r] = qkv[g + koff + d];
            v_s[r * SSTR + d] = qkv[g + voff + d];
        }
        __syncthreads();

        // S = Q @ K^T  (4 rows x 2 packed col-pairs per thread)
        ull s2[4][2] = {};
        #pragma unroll 4
        for (int d = 0; d < DH_; d++) {
            ulonglong2 qa = *(const ulonglong2*)&q2_s[d * Q2STR + 8 * ty];      // i=0,1
            ulonglong2 qb = *(const ulonglong2*)&q2_s[d * Q2STR + 8 * ty + 4];  // i=2,3
            ulonglong2 kv = *(const ulonglong2*)&k_s[d * SSTR + tx * 4];        // jp=0,1
            s2[0][0] = ffma2(qa.x, kv.x, s2[0][0]);
            s2[0][1] = ffma2(qa.x, kv.y, s2[0][1]);
            s2[1][0] = ffma2(qa.y, kv.x, s2[1][0]);
            s2[1][1] = ffma2(qa.y, kv.y, s2[1][1]);
            s2[2][0] = ffma2(qb.x, kv.x, s2[2][0]);
            s2[2][1] = ffma2(qb.x, kv.y, s2[2][1]);
            s2[3][0] = ffma2(qb.y, kv.x, s2[3][0]);
            s2[3][1] = ffma2(qb.y, kv.y, s2[3][1]);
        }

        // Online softmax per row (reduce across 16 tx lanes)
        #pragma unroll
        for (int i = 0; i < 4; i++) {
            float2 sa = unpack2(s2[i][0]);
            float2 sb = unpack2(s2[i][1]);
            float s0 = sa.x, s1 = sa.y, s2f = sb.x, s3 = sb.y;

            float mm = fmaxf(fmaxf(s0, s1), fmaxf(s2f, s3));
            #pragma unroll
            for (int o = 1; o < 16; o <<= 1)
                mm = fmaxf(mm, __shfl_xor_sync(0xffffffffu, mm, o));
            float mnew = fmaxf(m_i[i], mm);
            float alpha = __expf(m_i[i] - mnew);
            m_i[i] = mnew;

            s0 = __expf(s0 - mnew);
            s1 = __expf(s1 - mnew);
            s2f = __expf(s2f - mnew);
            s3 = __expf(s3 - mnew);
            float rs = s0 + s1 + s2f + s3;
            #pragma unroll
            for (int o = 1; o < 16; o <<= 1)
                rs += __shfl_xor_sync(0xffffffffu, rs, o);
            l_i[i] = l_i[i] * alpha + rs;

            ull al2 = pack2(alpha);
            acc2[i][0] = fmul2(acc2[i][0], al2);
            acc2[i][1] = fmul2(acc2[i][1], al2);

            float4 pv;
            pv.x = s0; pv.y = s1; pv.z = s2f; pv.w = s3;
            *(float4*)&p_s[(ty * 4 + i) * SSTR + tx * 4] = pv;
        }
        __syncthreads();

        // acc += P @ V
        #pragma unroll 4
        for (int j = 0; j < FT; j++) {
            ull pb0 = pack2(p_s[(ty * 4 + 0) * SSTR + j]);
            ull pb1 = pack2(p_s[(ty * 4 + 1) * SSTR + j]);
            ull pb2 = pack2(p_s[(ty * 4 + 2) * SSTR + j]);
            ull pb3 = pack2(p_s[(ty * 4 + 3) * SSTR + j]);
            ulonglong2 vv = *(const ulonglong2*)&v_s[j * SSTR + tx * 4];
            acc2[0][0] = ffma2(pb0, vv.x, acc2[0][0]);
            acc2[0][1] = ffma2(pb0, vv.y, acc2[0][1]);
            acc2[1][0] = ffma2(pb1, vv.x, acc2[1][0]);
            acc2[1][1] = ffma2(pb1, vv.y, acc2[1][1]);
            acc2[2][0] = ffma2(pb2, vv.x, acc2[2][0]);
            acc2[2][1] = ffma2(pb2, vv.y, acc2[2][1]);
            acc2[3][0] = ffma2(pb3, vv.x, acc2[3][0]);
            acc2[3][1] = ffma2(pb3, vv.y, acc2[3][1]);
        }
    }

    // Normalize and write to [B*N, H*Dh]
    #pragma unroll
    for (int i = 0; i < 4; i++) {
        float inv = 1.0f / l_i[i];
        float2 p0 = unpack2(acc2[i][0]);
        float2 p1 = unpack2(acc2[i][1]);
        float4 o;
        o.x = p0.x * inv;
        o.y = p0.y * inv;
        o.z = p1.x * inv;
        o.w = p1.y * inv;
        size_t row = (size_t)(b * N_ + q0 + ty * 4 + i);
        *(float4*)&out[row * DIM_ + h * DH_ + tx * 4] = o;
    }
}

// ---------------------------------------------------------------------------
// Launch
// ---------------------------------------------------------------------------
extern "C" void kernel_launch(void* const* d_in, const int* in_sizes, int n_in,
                              void* d_out, int out_size)
{
    const float* x      = (const float*)d_in[0];   // [4,2048,768]
    const float* w_qkv  = (const float*)d_in[1];   // [768,2304]
    const float* w_proj = (const float*)d_in[2];   // [768,768]
    const float* b_proj = (const float*)d_in[3];   // [768]
    float* out = (float*)d_out;                    // [4,2048,768]

    float* qkv = nullptr;
    float* attn = nullptr;
    cudaGetSymbolAddress((void**)&qkv, g_qkv);
    cudaGetSymbolAddress((void**)&attn, g_attn);

    cudaFuncSetAttribute(flash_kernel,
                         cudaFuncAttributeMaxDynamicSharedMemorySize,
                         FLASH_SMEM);

    // 1) QKV = X @ Wqkv          [8192,2304]
    dim3 g1(QKV_N / BN, M_TOT / BM);
    sgemm_kernel<<<g1, 256>>>(x, w_qkv, qkv, M_TOT, QKV_N, DIM_, nullptr);

    // 2) Flash attention per (b,h), 64-row query tiles
    dim3 g2(N_ / FT, B_ * H_);
    flash_kernel<<<g2, 256, FLASH_SMEM>>>(qkv, attn);

    // 3) OUT = ATTN @ Wproj + b  [8192,768]
    dim3 g3(DIM_ / BN, M_TOT / BM);
    sgemm_kernel<<<g3, 256>>>(attn, w_proj, out, M_TOT, DIM_, DIM_, b_proj);
}

// round 4
// speedup vs baseline: 1.7234x; 1.7234x over previous
#include <cuda_runtime.h>
#include <cuda_bf16.h>
#include <cstdint>

#define B_    4
#define N_    2048
#define DIM_  768
#define H_    12
#define DH_   64
#define M_TOT (B_ * N_)       // 8192
#define QKV_N (3 * DIM_)      // 2304
#define SCALE_ 0.125f         // 64^-0.5

// Scratch (device globals — allocation-free per harness rules)
__device__ float g_qkv[(size_t)M_TOT * QKV_N];   // [8192, 2304]
__device__ float g_attn[(size_t)M_TOT * DIM_];   // [8192, 768]

// ===========================================================================
// Warp-MMA helpers (Ampere-era PTX — safe on .target sm_103)
// ===========================================================================
__device__ __forceinline__ uint32_t smem_u32(const void* p) {
    uint32_t a;
    asm("{ .reg .u64 t; cvta.to.shared.u64 t, %1; cvt.u32.u64 %0, t; }"
        : "=r"(a) : "l"(p));
    return a;
}

__device__ __forceinline__ void ldsm_x4(uint32_t* r, uint32_t addr) {
    asm volatile("ldmatrix.sync.aligned.m8n8.x4.shared.b16 {%0,%1,%2,%3}, [%4];"
                 : "=r"(r[0]), "=r"(r[1]), "=r"(r[2]), "=r"(r[3]) : "r"(addr));
}
__device__ __forceinline__ void ldsm_x4_t(uint32_t* r, uint32_t addr) {
    asm volatile("ldmatrix.sync.aligned.m8n8.x4.trans.shared.b16 {%0,%1,%2,%3}, [%4];"
                 : "=r"(r[0]), "=r"(r[1]), "=r"(r[2]), "=r"(r[3]) : "r"(addr));
}

// D += A * B  (m16n8k16, bf16 in, fp32 acc)
__device__ __forceinline__ void mma_bf16(float* d, const uint32_t* a, const uint32_t* b) {
    asm volatile("mma.sync.aligned.m16n8k16.row.col.f32.bf16.bf16.f32 "
                 "{%0,%1,%2,%3}, {%4,%5,%6,%7}, {%8,%9}, {%0,%1,%2,%3};"
                 : "+f"(d[0]), "+f"(d[1]), "+f"(d[2]), "+f"(d[3])
                 : "r"(a[0]), "r"(a[1]), "r"(a[2]), "r"(a[3]), "r"(b[0]), "r"(b[1]));
}

__device__ __forceinline__ uint32_t pack_bf16(float lo, float hi) {
    __nv_bfloat162 t = __floats2bfloat162_rn(lo, hi);   // .x = lo (low half)
    return *reinterpret_cast<uint32_t*>(&t);
}
// split x into bf16 hi + bf16 lo planes
__device__ __forceinline__ void split_bf16(float x, __nv_bfloat16& h, __nv_bfloat16& l) {
    h = __float2bfloat16_rn(x);
    l = __float2bfloat16_rn(x - __bfloat162float(h));
}

// ===========================================================================
// GEMM (tensor cores): C[M,N] = A[M,K] @ W[K,N] (+bias), split-bf16 3-plane.
// BM=128, BN=128, BK=32, 256 threads (8 warps, 2m x 4n), warp tile 64x32.
// smem: A planes [128][40] bf16 (80B rows), B planes [128 n][40 k].
// ===========================================================================
#define ASTR 40   // padded elements per row (80 bytes)

__global__ __launch_bounds__(256) void tgemm_kernel(
    const float* __restrict__ A, const float* __restrict__ W,
    float* __restrict__ C, int M, int N, int K,
    const float* __restrict__ bias)
{
    __shared__ __align__(16) __nv_bfloat16 Ah[128][ASTR], Al[128][ASTR];
    __shared__ __align__(16) __nv_bfloat16 Bh[128][ASTR], Bl[128][ASTR];

    const int tid  = threadIdx.x;
    const int lane = tid & 31;
    const int wid  = tid >> 5;
    const int wm   = (wid >> 2) * 64;   // 0 or 64
    const int wn   = (wid & 3) * 32;    // 0..96
    const int bm   = blockIdx.y * 128;
    const int bn   = blockIdx.x * 128;

    const uint32_t uAh = smem_u32(&Ah[0][0]), uAl = smem_u32(&Al[0][0]);
    const uint32_t uBh = smem_u32(&Bh[0][0]), uBl = smem_u32(&Bl[0][0]);

    float acc[4][4][4] = {};   // [mi][nj][frag]

    for (int kc = 0; kc < K; kc += 32) {
        __syncthreads();
        // ---- load A tile 128x32, split ----
        #pragma unroll
        for (int i = 0; i < 4; i++) {
            int idx = tid + i * 256;
            int row = idx >> 3, c4 = (idx & 7) * 4;
            float4 a = *(const float4*)(A + (size_t)(bm + row) * K + kc + c4);
            __nv_bfloat16 h0, l0, h1, l1, h2, l2, h3, l3;
            split_bf16(a.x, h0, l0); split_bf16(a.y, h1, l1);
            split_bf16(a.z, h2, l2); split_bf16(a.w, h3, l3);
            *(__nv_bfloat162*)&Ah[row][c4]     = __halves2bfloat162(h0, h1);
            *(__nv_bfloat162*)&Ah[row][c4 + 2] = __halves2bfloat162(h2, h3);
            *(__nv_bfloat162*)&Al[row][c4]     = __halves2bfloat162(l0, l1);
            *(__nv_bfloat162*)&Al[row][c4 + 2] = __halves2bfloat162(l2, l3);
        }
        // ---- load B tile 32x128 -> [n][k], split ----
        #pragma unroll
        for (int i = 0; i < 4; i++) {
            int idx = tid + i * 256;
            int kr = idx >> 5, nv = (idx & 31) * 4;
            float4 w = *(const float4*)(W + (size_t)(kc + kr) * N + bn + nv);
            float wv[4] = {w.x, w.y, w.z, w.w};
            #pragma unroll
            for (int j = 0; j < 4; j++) {
                __nv_bfloat16 h, l;
                split_bf16(wv[j], h, l);
                Bh[nv + j][kr] = h;
                Bl[nv + j][kr] = l;
            }
        }
        __syncthreads();

        #pragma unroll
        for (int kb = 0; kb < 2; kb++) {
            const uint32_t aoff =
                (uint32_t)((wm + (lane & 15)) * (ASTR * 2) +
                           (kb * 16 + ((lane >> 4) << 3)) * 2);
            uint32_t ah[4][4], al[4][4];
            #pragma unroll
            for (int mi = 0; mi < 4; mi++) {
                ldsm_x4(ah[mi], uAh + aoff + mi * 16 * (ASTR * 2));
                ldsm_x4(al[mi], uAl + aoff + mi * 16 * (ASTR * 2));
            }
            #pragma unroll
            for (int njp = 0; njp < 2; njp++) {
                const uint32_t boff =
                    (uint32_t)((wn + njp * 16 + (lane & 7) + ((lane >> 4) << 3)) * (ASTR * 2) +
                               (kb * 16 + (((lane >> 3) & 1) << 3)) * 2);
                uint32_t bh4[4], bl4[4];
                ldsm_x4(bh4, uBh + boff);
                ldsm_x4(bl4, uBl + boff);
                #pragma unroll
                for (int mi = 0; mi < 4; mi++) {
                    #pragma unroll
                    for (int sub = 0; sub < 2; sub++) {
                        float* d = acc[mi][njp * 2 + sub];
                        mma_bf16(d, ah[mi], &bh4[sub * 2]);
                        mma_bf16(d, ah[mi], &bl4[sub * 2]);
                        mma_bf16(d, al[mi], &bh4[sub * 2]);
                    }
                }
            }
        }
    }

    // ---- epilogue ----
    #pragma unroll
    for (int mi = 0; mi < 4; mi++) {
        #pragma unroll
        for (int nj = 0; nj < 4; nj++) {
            int row = bm + wm + mi * 16 + (lane >> 2);
            int col = bn + wn + nj * 8 + (lane & 3) * 2;
            float b0 = bias ? bias[col] : 0.f;
            float b1 = bias ? bias[col + 1] : 0.f;
            float2 v0 = {acc[mi][nj][0] + b0, acc[mi][nj][1] + b1};
            float2 v1 = {acc[mi][nj][2] + b0, acc[mi][nj][3] + b1};
            *(float2*)(C + (size_t)row * N + col) = v0;
            *(float2*)(C + (size_t)(row + 8) * N + col) = v1;
        }
    }
}

// ===========================================================================
// Flash attention (tensor cores, split-bf16). One CTA = 128 q rows of one
// (b,h). 8 warps, each owns 16 q rows. kv tiles of 64.
// smem planes (bf16, 144B rows): Qh,Ql[128][72]; Kh,Kl,Vh,Vl[64][72].
// ===========================================================================
#define FSTR 72
#define FLASH_SMEM ((128 * 2 + 64 * 4) * FSTR * 2)   // 73728 B

__global__ __launch_bounds__(256) void flash_kernel(
    const float* __restrict__ qkv, float* __restrict__ out)
{
    extern __shared__ __align__(16) __nv_bfloat16 fsm[];
    __nv_bfloat16* Qh = fsm;
    __nv_bfloat16* Ql = Qh + 128 * FSTR;
    __nv_bfloat16* Kh = Ql + 128 * FSTR;
    __nv_bfloat16* Kl = Kh + 64 * FSTR;
    __nv_bfloat16* Vh = Kl + 64 * FSTR;
    __nv_bfloat16* Vl = Vh + 64 * FSTR;
    const uint32_t uQh = smem_u32(Qh), uQl = smem_u32(Ql);
    const uint32_t uKh = smem_u32(Kh), uKl = smem_u32(Kl);
    const uint32_t uVh = smem_u32(Vh), uVl = smem_u32(Vl);

    const int tid  = threadIdx.x;
    const int lane = tid & 31;
    const int w    = tid >> 5;
    const int bh   = blockIdx.y;
    const int b    = bh / H_;
    const int h    = bh % H_;
    const int q0   = blockIdx.x * 128;

    const size_t rowbase = (size_t)b * N_ * QKV_N;
    const int qoff = h * DH_;
    const int koff = DIM_ + h * DH_;
    const int voff = 2 * DIM_ + h * DH_;

    // ---- load Q tile (pre-scaled), split ----
    #pragma unroll
    for (int i = 0; i < 8; i++) {
        int idx = tid + i * 256;
        int row = idx >> 4, c4 = (idx & 15) * 4;
        float4 q = *(const float4*)(qkv + rowbase + (size_t)(q0 + row) * QKV_N + qoff + c4);
        float qv[4] = {q.x * SCALE_, q.y * SCALE_, q.z * SCALE_, q.w * SCALE_};
        __nv_bfloat16 hh[4], ll[4];
        #pragma unroll
        for (int j = 0; j < 4; j++) split_bf16(qv[j], hh[j], ll[j]);
        *(__nv_bfloat162*)&Qh[row * FSTR + c4]     = __halves2bfloat162(hh[0], hh[1]);
        *(__nv_bfloat162*)&Qh[row * FSTR + c4 + 2] = __halves2bfloat162(hh[2], hh[3]);
        *(__nv_bfloat162*)&Ql[row * FSTR + c4]     = __halves2bfloat162(ll[0], ll[1]);
        *(__nv_bfloat162*)&Ql[row * FSTR + c4 + 2] = __halves2bfloat162(ll[2], ll[3]);
    }
    __syncthreads();

    // ---- preload Q fragments (constant across kv loop) ----
    uint32_t qh[4][4], ql[4][4];
    #pragma unroll
    for (int kb = 0; kb < 4; kb++) {
        uint32_t off = (uint32_t)((w * 16 + (lane & 15)) * (FSTR * 2) +
                                  (kb * 16 + ((lane >> 4) << 3)) * 2);
        ldsm_x4(qh[kb], uQh + off);
        ldsm_x4(ql[kb], uQl + off);
    }

    float o[8][4] = {};
    float m0 = -1e30f, m1 = -1e30f, l0 = 0.f, l1 = 0.f;

    for (int t = 0; t < N_ / 64; t++) {
        __syncthreads();
        const int kr0 = t * 64;
        // ---- load K,V tiles (64x64 each), split ----
        #pragma unroll
        for (int i = 0; i < 4; i++) {
            int idx = tid + i * 256;
            int row = idx >> 4, c4 = (idx & 15) * 4;
            size_t g = rowbase + (size_t)(kr0 + row) * QKV_N;
            float4 kv4 = *(const float4*)(qkv + g + koff + c4);
            float4 vv4 = *(const float4*)(qkv + g + voff + c4);
            float kvv[4] = {kv4.x, kv4.y, kv4.z, kv4.w};
            float vvv[4] = {vv4.x, vv4.y, vv4.z, vv4.w};
            __nv_bfloat16 kh[4], kl[4], vh[4], vl[4];
            #pragma unroll
            for (int j = 0; j < 4; j++) {
                split_bf16(kvv[j], kh[j], kl[j]);
                split_bf16(vvv[j], vh[j], vl[j]);
            }
            *(__nv_bfloat162*)&Kh[row * FSTR + c4]     = __halves2bfloat162(kh[0], kh[1]);
            *(__nv_bfloat162*)&Kh[row * FSTR + c4 + 2] = __halves2bfloat162(kh[2], kh[3]);
            *(__nv_bfloat162*)&Kl[row * FSTR + c4]     = __halves2bfloat162(kl[0], kl[1]);
            *(__nv_bfloat162*)&Kl[row * FSTR + c4 + 2] = __halves2bfloat162(kl[2], kl[3]);
            *(__nv_bfloat162*)&Vh[row * FSTR + c4]     = __halves2bfloat162(vh[0], vh[1]);
            *(__nv_bfloat162*)&Vh[row * FSTR + c4 + 2] = __halves2bfloat162(vh[2], vh[3]);
            *(__nv_bfloat162*)&Vl[row * FSTR + c4]     = __halves2bfloat162(vl[0], vl[1]);
            *(__nv_bfloat162*)&Vl[row * FSTR + c4 + 2] = __halves2bfloat162(vl[2], vl[3]);
        }
        __syncthreads();

        // ---- S = Q @ K^T : m16 x n64, fragments s[8][4] ----
        float s[8][4] = {};
        #pragma unroll
        for (int kb = 0; kb < 4; kb++) {
            #pragma unroll
            for (int njp = 0; njp < 4; njp++) {
                uint32_t off = (uint32_t)((njp * 16 + (lane & 7) + ((lane >> 4) << 3)) * (FSTR * 2) +
                                          (kb * 16 + (((lane >> 3) & 1) << 3)) * 2);
                uint32_t kbh[4], kbl[4];
                ldsm_x4(kbh, uKh + off);
                ldsm_x4(kbl, uKl + off);
                #pragma unroll
                for (int sub = 0; sub < 2; sub++) {
                    float* d = s[njp * 2 + sub];
                    mma_bf16(d, qh[kb], &kbh[sub * 2]);
                    mma_bf16(d, qh[kb], &kbl[sub * 2]);
                    mma_bf16(d, ql[kb], &kbh[sub * 2]);
                }
            }
        }

        // ---- online softmax (rows lane>>2 and lane>>2 + 8) ----
        float mx0 = -1e30f, mx1 = -1e30f;
        #pragma unroll
        for (int nj = 0; nj < 8; nj++) {
            mx0 = fmaxf(mx0, fmaxf(s[nj][0], s[nj][1]));
            mx1 = fmaxf(mx1, fmaxf(s[nj][2], s[nj][3]));
        }
        mx0 = fmaxf(mx0, __shfl_xor_sync(0xffffffffu, mx0, 1));
        mx0 = fmaxf(mx0, __shfl_xor_sync(0xffffffffu, mx0, 2));
        mx1 = fmaxf(mx1, __shfl_xor_sync(0xffffffffu, mx1, 1));
        mx1 = fmaxf(mx1, __shfl_xor_sync(0xffffffffu, mx1, 2));
        float mn0 = fmaxf(m0, mx0), mn1 = fmaxf(m1, mx1);
        float a0 = __expf(m0 - mn0), a1 = __expf(m1 - mn1);
        m0 = mn0; m1 = mn1;

        float sum0 = 0.f, sum1 = 0.f;
        #pragma unroll
        for (int nj = 0; nj < 8; nj++) {
            s[nj][0] = __expf(s[nj][0] - mn0);
            s[nj][1] = __expf(s[nj][1] - mn0);
            s[nj][2] = __expf(s[nj][2] - mn1);
            s[nj][3] = __expf(s[nj][3] - mn1);
            sum0 += s[nj][0] + s[nj][1];
            sum1 += s[nj][2] + s[nj][3];
        }
        sum0 += __shfl_xor_sync(0xffffffffu, sum0, 1);
        sum0 += __shfl_xor_sync(0xffffffffu, sum0, 2);
        sum1 += __shfl_xor_sync(0xffffffffu, sum1, 1);
        sum1 += __shfl_xor_sync(0xffffffffu, sum1, 2);
        l0 = l0 * a0 + sum0;
        l1 = l1 * a1 + sum1;

        #pragma unroll
        for (int dj = 0; dj < 8; dj++) {
            o[dj][0] *= a0; o[dj][1] *= a0;
            o[dj][2] *= a1; o[dj][3] *= a1;
        }

        // ---- P fragments (in-register C->A conversion, split) ----
        uint32_t pah[4][4], pal[4][4];
        #pragma unroll
        for (int kb = 0; kb < 4; kb++) {
            #pragma unroll
            for (int half = 0; half < 2; half++) {      // nj = 2kb+half
                const float* sc = s[2 * kb + half];
                __nv_bfloat16 h0, lo0, h1, lo1, h2, lo2, h3, lo3;
                split_bf16(sc[0], h0, lo0); split_bf16(sc[1], h1, lo1);
                split_bf16(sc[2], h2, lo2); split_bf16(sc[3], h3, lo3);
                __nv_bfloat162 t;
                t = __halves2bfloat162(h0, h1);  pah[kb][half * 2 + 0] = *(uint32_t*)&t;
                t = __halves2bfloat162(h2, h3);  pah[kb][half * 2 + 1] = *(uint32_t*)&t;
                t = __halves2bfloat162(lo0, lo1); pal[kb][half * 2 + 0] = *(uint32_t*)&t;
                t = __halves2bfloat162(lo2, lo3); pal[kb][half * 2 + 1] = *(uint32_t*)&t;
            }
        }
        // fix A-frag ordering: a = {(r,k0),(r+8,k0),(r,k8),(r+8,k8)} ->
        // our fill produced [h*2 + i] = {nj0c01, nj0c23, nj1c01, nj1c23} which is
        // exactly {a0,a1,a2,a3} required (c01 = k-pair at r, c23 = k-pair at r+8).

        // ---- O += P @ V ----
        #pragma unroll
        for (int kb = 0; kb < 4; kb++) {
            #pragma unroll
            for (int djp = 0; djp < 4; djp++) {
                uint32_t off = (uint32_t)((kb * 16 + (lane & 7) + (((lane >> 3) & 1) << 3)) * (FSTR * 2) +
                                          (djp * 16 + ((lane >> 4) << 3)) * 2);
                uint32_t vbh[4], vbl[4];
                ldsm_x4_t(vbh, uVh + off);
                ldsm_x4_t(vbl, uVl + off);
                #pragma unroll
                for (int sub = 0; sub < 2; sub++) {
                    float* d = o[djp * 2 + sub];
                    mma_bf16(d, pah[kb], &vbh[sub * 2]);
                    mma_bf16(d, pah[kb], &vbl[sub * 2]);
                    mma_bf16(d, pal[kb], &vbh[sub * 2]);
                }
            }
        }
    }

    // ---- normalize + write [B*N, H*Dh] ----
    float inv0 = 1.0f / l0, inv1 = 1.0f / l1;
    size_t row0 = (size_t)(b * N_ + q0 + w * 16 + (lane >> 2));
    #pragma unroll
    for (int dj = 0; dj < 8; dj++) {
        int col = h * DH_ + dj * 8 + (lane & 3) * 2;
        float2 v0 = {o[dj][0] * inv0, o[dj][1] * inv0};
        float2 v1 = {o[dj][2] * inv1, o[dj][3] * inv1};
        *(float2*)(out + row0 * DIM_ + col) = v0;
        *(float2*)(out + (row0 + 8) * DIM_ + col) = v1;
    }
}

// ---------------------------------------------------------------------------
// Launch
// ---------------------------------------------------------------------------
extern "C" void kernel_launch(void* const* d_in, const int* in_sizes, int n_in,
                              void* d_out, int out_size)
{
    const float* x      = (const float*)d_in[0];   // [4,2048,768]
    const float* w_qkv  = (const float*)d_in[1];   // [768,2304]
    const float* w_proj = (const float*)d_in[2];   // [768,768]
    const float* b_proj = (const float*)d_in[3];   // [768]
    float* out = (float*)d_out;                    // [4,2048,768]

    float* qkv = nullptr;
    float* attn = nullptr;
    cudaGetSymbolAddress((void**)&qkv, g_qkv);
    cudaGetSymbolAddress((void**)&attn, g_attn);

    cudaFuncSetAttribute(flash_kernel,
                         cudaFuncAttributeMaxDynamicSharedMemorySize, FLASH_SMEM);

    // 1) QKV = X @ Wqkv          [8192,2304]
    dim3 g1(QKV_N / 128, M_TOT / 128);
    tgemm_kernel<<<g1, 256>>>(x, w_qkv, qkv, M_TOT, QKV_N, DIM_, nullptr);

    // 2) Flash attention per (b,h), 128-row query tiles
    dim3 g2(N_ / 128, B_ * H_);
    flash_kernel<<<g2, 256, FLASH_SMEM>>>(qkv, attn);

    // 3) OUT = ATTN @ Wproj + b  [8192,768]
    dim3 g3(DIM_ / 128, M_TOT / 128);
    tgemm_kernel<<<g3, 256>>>(attn, w_proj, out, M_TOT, DIM_, DIM_, b_proj);
}

// round 6
// speedup vs baseline: 2.6045x; 1.5112x over previous
#include <cuda_runtime.h>
#include <cuda_bf16.h>
#include <cstdint>

#define B_    4
#define N_    2048
#define DIM_  768
#define H_    12
#define DH_   64
#define M_TOT (B_ * N_)       // 8192
#define QKV_N (3 * DIM_)      // 2304
#define SCALE_ 0.125f         // 64^-0.5

typedef __nv_bfloat16 bf16;

// --------------------------- device scratch (no allocs) --------------------
__device__ bf16 g_xh[(size_t)M_TOT * DIM_];     // X hi plane   [8192,768]
__device__ bf16 g_xl[(size_t)M_TOT * DIM_];     // X lo plane
__device__ bf16 g_wqh[(size_t)QKV_N * DIM_];    // Wqkv^T hi    [2304,768]
__device__ bf16 g_wql[(size_t)QKV_N * DIM_];
__device__ bf16 g_wph[(size_t)DIM_ * DIM_];     // Wproj^T hi   [768,768]
__device__ bf16 g_wpl[(size_t)DIM_ * DIM_];
__device__ bf16 g_qkvh[(size_t)M_TOT * QKV_N];  // QKV hi       [8192,2304]
__device__ bf16 g_qkvl[(size_t)M_TOT * QKV_N];
__device__ bf16 g_ah[(size_t)M_TOT * DIM_];     // attn-out hi  [8192,768]
__device__ bf16 g_al[(size_t)M_TOT * DIM_];

// ===========================================================================
// helpers
// ===========================================================================
__device__ __forceinline__ uint32_t smem_u32(const void* p) {
    uint32_t a;
    asm("{ .reg .u64 t; cvta.to.shared.u64 t, %1; cvt.u32.u64 %0, t; }"
        : "=r"(a) : "l"(p));
    return a;
}
__device__ __forceinline__ void ldsm_x4(uint32_t* r, uint32_t addr) {
    asm volatile("ldmatrix.sync.aligned.m8n8.x4.shared.b16 {%0,%1,%2,%3}, [%4];"
                 : "=r"(r[0]), "=r"(r[1]), "=r"(r[2]), "=r"(r[3]) : "r"(addr));
}
__device__ __forceinline__ void ldsm_x4_t(uint32_t* r, uint32_t addr) {
    asm volatile("ldmatrix.sync.aligned.m8n8.x4.trans.shared.b16 {%0,%1,%2,%3}, [%4];"
                 : "=r"(r[0]), "=r"(r[1]), "=r"(r[2]), "=r"(r[3]) : "r"(addr));
}
__device__ __forceinline__ void mma_bf16(float* d, const uint32_t* a, const uint32_t* b) {
    asm volatile("mma.sync.aligned.m16n8k16.row.col.f32.bf16.bf16.f32 "
                 "{%0,%1,%2,%3}, {%4,%5,%6,%7}, {%8,%9}, {%0,%1,%2,%3};"
                 : "+f"(d[0]), "+f"(d[1]), "+f"(d[2]), "+f"(d[3])
                 : "r"(a[0]), "r"(a[1]), "r"(a[2]), "r"(a[3]), "r"(b[0]), "r"(b[1]));
}
__device__ __forceinline__ void split_bf16(float x, bf16& h, bf16& l) {
    h = __float2bfloat16_rn(x);
    l = __float2bfloat16_rn(x - __bfloat162float(h));
}
__device__ __forceinline__ uint32_t pack2u(bf16 a, bf16 b) {
    __nv_bfloat162 t = __halves2bfloat162(a, b);
    return *reinterpret_cast<uint32_t*>(&t);
}

// ===========================================================================
// convert kernels (run once per launch; cheap, memory-bound)
// ===========================================================================
__global__ void conv_split_kernel(const float* __restrict__ X,
                                  bf16* __restrict__ Xh, bf16* __restrict__ Xl,
                                  int n4)
{
    int idx = blockIdx.x * blockDim.x + threadIdx.x;
    if (idx >= n4) return;
    float4 v = ((const float4*)X)[idx];
    bf16 h0, l0, h1, l1, h2, l2, h3, l3;
    split_bf16(v.x, h0, l0); split_bf16(v.y, h1, l1);
    split_bf16(v.z, h2, l2); split_bf16(v.w, h3, l3);
    ((uint32_t*)Xh)[idx * 2]     = pack2u(h0, h1);
    ((uint32_t*)Xh)[idx * 2 + 1] = pack2u(h2, h3);
    ((uint32_t*)Xl)[idx * 2]     = pack2u(l0, l1);
    ((uint32_t*)Xl)[idx * 2 + 1] = pack2u(l2, l3);
}

// W [K][Nw] fp32 -> Th/Tl [Nw][K] bf16 (transpose + split)
__global__ void transpose_split_kernel(const float* __restrict__ W,
                                       bf16* __restrict__ Th, bf16* __restrict__ Tl,
                                       int K, int Nw)
{
    __shared__ float t[32][33];
    const int n0 = blockIdx.x * 32, k0 = blockIdx.y * 32;
    const int tx = threadIdx.x, ty = threadIdx.y;   // (32, 8)
    #pragma unroll
    for (int i = 0; i < 32; i += 8)
        t[ty + i][tx] = W[(size_t)(k0 + ty + i) * Nw + n0 + tx];
    __syncthreads();
    #pragma unroll
    for (int i = 0; i < 32; i += 8) {
        float v = t[tx][ty + i];                    // k = k0+tx, n = n0+ty+i
        bf16 h, l;
        split_bf16(v, h, l);
        Th[(size_t)(n0 + ty + i) * K + k0 + tx] = h;
        Tl[(size_t)(n0 + ty + i) * K + k0 + tx] = l;
    }
}

// ===========================================================================
// tgemm: C[M,N] = A[M,K] @ B^T (B stored [N][K]), inputs split-bf16 planes.
// 128x128 block, BK=32, 8 warps of 64x32.  Output: fp32+bias OR split-bf16.
// ===========================================================================
#define ASTR 40   // padded bf16 per smem row (80 B)

__global__ __launch_bounds__(256) void tgemm_kernel(
    const bf16* __restrict__ Aih, const bf16* __restrict__ Ail,
    const bf16* __restrict__ Bih, const bf16* __restrict__ Bil,
    float* __restrict__ Cf, bf16* __restrict__ Ch, bf16* __restrict__ Cl,
    int M, int N, int K, const float* __restrict__ bias, int qcols)
{
    __shared__ __align__(16) bf16 Ah[128][ASTR], Al[128][ASTR];
    __shared__ __align__(16) bf16 Bh[128][ASTR], Bl[128][ASTR];

    const int tid  = threadIdx.x;
    const int lane = tid & 31;
    const int wid  = tid >> 5;
    const int wm   = (wid >> 2) * 64;
    const int wn   = (wid & 3) * 32;
    const int bm   = blockIdx.y * 128;
    const int bn   = blockIdx.x * 128;

    const uint32_t uAh = smem_u32(&Ah[0][0]), uAl = smem_u32(&Al[0][0]);
    const uint32_t uBh = smem_u32(&Bh[0][0]), uBl = smem_u32(&Bl[0][0]);

    float acc[4][4][4] = {};

    for (int kc = 0; kc < K; kc += 32) {
        __syncthreads();
        // stage A/B tiles: pure 16B copies (128 rows x 32 bf16 per plane)
        #pragma unroll
        for (int i = 0; i < 2; i++) {
            int idx = tid + i * 256;
            int row = idx >> 2, c8 = (idx & 3) * 8;
            const size_t ga = (size_t)(bm + row) * K + kc + c8;
            const size_t gb = (size_t)(bn + row) * K + kc + c8;
            *(float4*)&Ah[row][c8] = *(const float4*)(Aih + ga);
            *(float4*)&Al[row][c8] = *(const float4*)(Ail + ga);
            *(float4*)&Bh[row][c8] = *(const float4*)(Bih + gb);
            *(float4*)&Bl[row][c8] = *(const float4*)(Bil + gb);
        }
        __syncthreads();

        #pragma unroll
        for (int kb = 0; kb < 2; kb++) {
            const uint32_t aoff =
                (uint32_t)((wm + (lane & 15)) * (ASTR * 2) +
                           (kb * 16 + ((lane >> 4) << 3)) * 2);
            uint32_t ah[4][4], al[4][4];
            #pragma unroll
            for (int mi = 0; mi < 4; mi++) {
                ldsm_x4(ah[mi], uAh + aoff + mi * 16 * (ASTR * 2));
                ldsm_x4(al[mi], uAl + aoff + mi * 16 * (ASTR * 2));
            }
            #pragma unroll
            for (int njp = 0; njp < 2; njp++) {
                const uint32_t boff =
                    (uint32_t)((wn + njp * 16 + (lane & 7) + ((lane >> 4) << 3)) * (ASTR * 2) +
                               (kb * 16 + (((lane >> 3) & 1) << 3)) * 2);
                uint32_t bh4[4], bl4[4];
                ldsm_x4(bh4, uBh + boff);
                ldsm_x4(bl4, uBl + boff);
                #pragma unroll
                for (int mi = 0; mi < 4; mi++) {
                    #pragma unroll
                    for (int sub = 0; sub < 2; sub++) {
                        float* d = acc[mi][njp * 2 + sub];
                        mma_bf16(d, ah[mi], &bh4[sub * 2]);
                        mma_bf16(d, ah[mi], &bl4[sub * 2]);
                        mma_bf16(d, al[mi], &bh4[sub * 2]);
                    }
                }
            }
        }
    }

    // ---- epilogue ----
    const float sc = (bn < qcols) ? SCALE_ : 1.0f;
    #pragma unroll
    for (int mi = 0; mi < 4; mi++) {
        #pragma unroll
        for (int nj = 0; nj < 4; nj++) {
            int row = bm + wm + mi * 16 + (lane >> 2);
            int col = bn + wn + nj * 8 + (lane & 3) * 2;
            if (Cf) {
                float b0 = bias ? bias[col] : 0.f;
                float b1 = bias ? bias[col + 1] : 0.f;
                float2 v0 = {acc[mi][nj][0] + b0, acc[mi][nj][1] + b1};
                float2 v1 = {acc[mi][nj][2] + b0, acc[mi][nj][3] + b1};
                *(float2*)(Cf + (size_t)row * N + col) = v0;
                *(float2*)(Cf + (size_t)(row + 8) * N + col) = v1;
            } else {
                bf16 h0, l0, h1, l1, h2, l2, h3, l3;
                split_bf16(acc[mi][nj][0] * sc, h0, l0);
                split_bf16(acc[mi][nj][1] * sc, h1, l1);
                split_bf16(acc[mi][nj][2] * sc, h2, l2);
                split_bf16(acc[mi][nj][3] * sc, h3, l3);
                *(uint32_t*)(Ch + (size_t)row * N + col)       = pack2u(h0, h1);
                *(uint32_t*)(Ch + (size_t)(row + 8) * N + col) = pack2u(h2, h3);
                *(uint32_t*)(Cl + (size_t)row * N + col)       = pack2u(l0, l1);
                *(uint32_t*)(Cl + (size_t)(row + 8) * N + col) = pack2u(l2, l3);
            }
        }
    }
}

// ===========================================================================
// Flash attention (tensor cores, split-bf16 in AND out). One CTA = 128 q rows
// of one (b,h). 8 warps x 16 q rows. kv tiles of 64.
// ===========================================================================
#define FSTR 72
#define FLASH_SMEM ((128 * 2 + 64 * 4) * FSTR * 2)   // 73728 B

__global__ __launch_bounds__(256) void flash_kernel(
    const bf16* __restrict__ qh_g, const bf16* __restrict__ ql_g,
    bf16* __restrict__ outh, bf16* __restrict__ outl)
{
    extern __shared__ __align__(16) bf16 fsm[];
    bf16* Qh = fsm;
    bf16* Ql = Qh + 128 * FSTR;
    bf16* Kh = Ql + 128 * FSTR;
    bf16* Kl = Kh + 64 * FSTR;
    bf16* Vh = Kl + 64 * FSTR;
    bf16* Vl = Vh + 64 * FSTR;
    const uint32_t uQh = smem_u32(Qh), uQl = smem_u32(Ql);
    const uint32_t uKh = smem_u32(Kh), uKl = smem_u32(Kl);
    const uint32_t uVh = smem_u32(Vh), uVl = smem_u32(Vl);

    const int tid  = threadIdx.x;
    const int lane = tid & 31;
    const int w    = tid >> 5;
    const int bh   = blockIdx.y;
    const int b    = bh / H_;
    const int h    = bh % H_;
    const int q0   = blockIdx.x * 128;

    const size_t rowbase = (size_t)b * N_ * QKV_N;
    const int qoff = h * DH_;
    const int koff = DIM_ + h * DH_;
    const int voff = 2 * DIM_ + h * DH_;

    // ---- stage Q tile: 128x64 per plane, 16B copies ----
    #pragma unroll
    for (int i = 0; i < 4; i++) {
        int idx = tid + i * 256;
        int row = idx >> 3, c8 = (idx & 7) * 8;
        size_t g = rowbase + (size_t)(q0 + row) * QKV_N + qoff + c8;
        *(float4*)&Qh[row * FSTR + c8] = *(const float4*)(qh_g + g);
        *(float4*)&Ql[row * FSTR + c8] = *(const float4*)(ql_g + g);
    }
    __syncthreads();

    // ---- preload Q fragments ----
    uint32_t qh[4][4], ql[4][4];
    #pragma unroll
    for (int kb = 0; kb < 4; kb++) {
        uint32_t off = (uint32_t)((w * 16 + (lane & 15)) * (FSTR * 2) +
                                  (kb * 16 + ((lane >> 4) << 3)) * 2);
        ldsm_x4(qh[kb], uQh + off);
        ldsm_x4(ql[kb], uQl + off);
    }

    float o[8][4] = {};
    float m0 = -1e30f, m1 = -1e30f, l0 = 0.f, l1 = 0.f;

    for (int t = 0; t < N_ / 64; t++) {
        __syncthreads();
        const int kr0 = t * 64;
        // ---- stage K,V tiles (64x64 per plane), 16B copies ----
        #pragma unroll
        for (int i = 0; i < 2; i++) {
            int idx = tid + i * 256;
            int row = idx >> 3, c8 = (idx & 7) * 8;
            size_t gk = rowbase + (size_t)(kr0 + row) * QKV_N + koff + c8;
            size_t gv = rowbase + (size_t)(kr0 + row) * QKV_N + voff + c8;
            *(float4*)&Kh[row * FSTR + c8] = *(const float4*)(qh_g + gk);
            *(float4*)&Kl[row * FSTR + c8] = *(const float4*)(ql_g + gk);
            *(float4*)&Vh[row * FSTR + c8] = *(const float4*)(qh_g + gv);
            *(float4*)&Vl[row * FSTR + c8] = *(const float4*)(ql_g + gv);
        }
        __syncthreads();

        // ---- S = Q @ K^T ----
        float s[8][4] = {};
        #pragma unroll
        for (int kb = 0; kb < 4; kb++) {
            #pragma unroll
            for (int njp = 0; njp < 4; njp++) {
                uint32_t off = (uint32_t)((njp * 16 + (lane & 7) + ((lane >> 4) << 3)) * (FSTR * 2) +
                                          (kb * 16 + (((lane >> 3) & 1) << 3)) * 2);
                uint32_t kbh[4], kbl[4];
                ldsm_x4(kbh, uKh + off);
                ldsm_x4(kbl, uKl + off);
                #pragma unroll
                for (int sub = 0; sub < 2; sub++) {
                    float* d = s[njp * 2 + sub];
                    mma_bf16(d, qh[kb], &kbh[sub * 2]);
                    mma_bf16(d, qh[kb], &kbl[sub * 2]);
                    mma_bf16(d, ql[kb], &kbh[sub * 2]);
                }
            }
        }

        // ---- online softmax ----
        float mx0 = -1e30f, mx1 = -1e30f;
        #pragma unroll
        for (int nj = 0; nj < 8; nj++) {
            mx0 = fmaxf(mx0, fmaxf(s[nj][0], s[nj][1]));
            mx1 = fmaxf(mx1, fmaxf(s[nj][2], s[nj][3]));
        }
        mx0 = fmaxf(mx0, __shfl_xor_sync(0xffffffffu, mx0, 1));
        mx0 = fmaxf(mx0, __shfl_xor_sync(0xffffffffu, mx0, 2));
        mx1 = fmaxf(mx1, __shfl_xor_sync(0xffffffffu, mx1, 1));
        mx1 = fmaxf(mx1, __shfl_xor_sync(0xffffffffu, mx1, 2));
        float mn0 = fmaxf(m0, mx0), mn1 = fmaxf(m1, mx1);
        float a0 = __expf(m0 - mn0), a1 = __expf(m1 - mn1);
        m0 = mn0; m1 = mn1;

        float sum0 = 0.f, sum1 = 0.f;
        #pragma unroll
        for (int nj = 0; nj < 8; nj++) {
            s[nj][0] = __expf(s[nj][0] - mn0);
            s[nj][1] = __expf(s[nj][1] - mn0);
            s[nj][2] = __expf(s[nj][2] - mn1);
            s[nj][3] = __expf(s[nj][3] - mn1);
            sum0 += s[nj][0] + s[nj][1];
            sum1 += s[nj][2] + s[nj][3];
        }
        sum0 += __shfl_xor_sync(0xffffffffu, sum0, 1);
        sum0 += __shfl_xor_sync(0xffffffffu, sum0, 2);
        sum1 += __shfl_xor_sync(0xffffffffu, sum1, 1);
        sum1 += __shfl_xor_sync(0xffffffffu, sum1, 2);
        l0 = l0 * a0 + sum0;
        l1 = l1 * a1 + sum1;

        #pragma unroll
        for (int dj = 0; dj < 8; dj++) {
            o[dj][0] *= a0; o[dj][1] *= a0;
            o[dj][2] *= a1; o[dj][3] *= a1;
        }

        // ---- P fragments (in-register, split) ----
        uint32_t pah[4][4], pal[4][4];
        #pragma unroll
        for (int kb = 0; kb < 4; kb++) {
            #pragma unroll
            for (int half = 0; half < 2; half++) {
                const float* sc = s[2 * kb + half];
                bf16 h0, lo0, h1, lo1, h2, lo2, h3, lo3;
                split_bf16(sc[0], h0, lo0); split_bf16(sc[1], h1, lo1);
                split_bf16(sc[2], h2, lo2); split_bf16(sc[3], h3, lo3);
                pah[kb][half * 2 + 0] = pack2u(h0, h1);
                pah[kb][half * 2 + 1] = pack2u(h2, h3);
                pal[kb][half * 2 + 0] = pack2u(lo0, lo1);
                pal[kb][half * 2 + 1] = pack2u(lo2, lo3);
            }
        }

        // ---- O += P @ V ----
        #pragma unroll
        for (int kb = 0; kb < 4; kb++) {
            #pragma unroll
            for (int djp = 0; djp < 4; djp++) {
                uint32_t off = (uint32_t)((kb * 16 + (lane & 7) + (((lane >> 3) & 1) << 3)) * (FSTR * 2) +
                                          (djp * 16 + ((lane >> 4) << 3)) * 2);
                uint32_t vbh[4], vbl[4];
                ldsm_x4_t(vbh, uVh + off);
                ldsm_x4_t(vbl, uVl + off);
                #pragma unroll
                for (int sub = 0; sub < 2; sub++) {
                    float* d = o[djp * 2 + sub];
                    mma_bf16(d, pah[kb], &vbh[sub * 2]);
                    mma_bf16(d, pah[kb], &vbl[sub * 2]);
                    mma_bf16(d, pal[kb], &vbh[sub * 2]);
                }
            }
        }
    }

    // ---- normalize + split-bf16 write to attn planes [B*N, 768] ----
    float inv0 = 1.0f / l0, inv1 = 1.0f / l1;
    size_t row0 = (size_t)(b * N_ + q0 + w * 16 + (lane >> 2));
    #pragma unroll
    for (int dj = 0; dj < 8; dj++) {
        int col = h * DH_ + dj * 8 + (lane & 3) * 2;
        bf16 h0, lo0, h1, lo1, h2, lo2, h3, lo3;
        split_bf16(o[dj][0] * inv0, h0, lo0);
        split_bf16(o[dj][1] * inv0, h1, lo1);
        split_bf16(o[dj][2] * inv1, h2, lo2);
        split_bf16(o[dj][3] * inv1, h3, lo3);
        *(uint32_t*)(outh + row0 * DIM_ + col)       = pack2u(h0, h1);
        *(uint32_t*)(outh + (row0 + 8) * DIM_ + col) = pack2u(h2, h3);
        *(uint32_t*)(outl + row0 * DIM_ + col)       = pack2u(lo0, lo1);
        *(uint32_t*)(outl + (row0 + 8) * DIM_ + col) = pack2u(lo2, lo3);
    }
}

// ---------------------------------------------------------------------------
// Launch
// ---------------------------------------------------------------------------
extern "C" void kernel_launch(void* const* d_in, const int* in_sizes, int n_in,
                              void* d_out, int out_size)
{
    const float* x      = (const float*)d_in[0];
    const float* w_qkv  = (const float*)d_in[1];
    const float* w_proj = (const float*)d_in[2];
    const float* b_proj = (const float*)d_in[3];
    float* out = (float*)d_out;

    bf16 *xh, *xl, *wqh, *wql, *wph, *wpl, *qkvh, *qkvl, *ah, *al;
    cudaGetSymbolAddress((void**)&xh, g_xh);
    cudaGetSymbolAddress((void**)&xl, g_xl);
    cudaGetSymbolAddress((void**)&wqh, g_wqh);
    cudaGetSymbolAddress((void**)&wql, g_wql);
    cudaGetSymbolAddress((void**)&wph, g_wph);
    cudaGetSymbolAddress((void**)&wpl, g_wpl);
    cudaGetSymbolAddress((void**)&qkvh, g_qkvh);
    cudaGetSymbolAddress((void**)&qkvl, g_qkvl);
    cudaGetSymbolAddress((void**)&ah, g_ah);
    cudaGetSymbolAddress((void**)&al, g_al);

    cudaFuncSetAttribute(flash_kernel,
                         cudaFuncAttributeMaxDynamicSharedMemorySize, FLASH_SMEM);

    // 0) converts
    {
        int n4 = M_TOT * DIM_ / 4;
        conv_split_kernel<<<(n4 + 255) / 256, 256>>>(x, xh, xl, n4);
        dim3 tb(32, 8);
        transpose_split_kernel<<<dim3(QKV_N / 32, DIM_ / 32), tb>>>(w_qkv, wqh, wql, DIM_, QKV_N);
        transpose_split_kernel<<<dim3(DIM_ / 32, DIM_ / 32), tb>>>(w_proj, wph, wpl, DIM_, DIM_);
    }

    // 1) QKV = X @ Wqkv -> split-bf16 planes, Q-scale folded in
    dim3 g1(QKV_N / 128, M_TOT / 128);
    tgemm_kernel<<<g1, 256>>>(xh, xl, wqh, wql,
                              nullptr, qkvh, qkvl,
                              M_TOT, QKV_N, DIM_, nullptr, DIM_);

    // 2) Flash attention
    dim3 g2(N_ / 128, B_ * H_);
    flash_kernel<<<g2, 256, FLASH_SMEM>>>(qkvh, qkvl, ah, al);

    // 3) OUT = ATTN @ Wproj + bias (fp32)
    dim3 g3(DIM_ / 128, M_TOT / 128);
    tgemm_kernel<<<g3, 256>>>(ah, al, wph, wpl,
                              out, nullptr, nullptr,
                              M_TOT, DIM_, DIM_, b_proj, 0);
}

// round 7
// speedup vs baseline: 2.6986x; 1.0361x over previous
#include <cuda_runtime.h>
#include <cuda_bf16.h>
#include <cstdint>

#define B_    4
#define N_    2048
#define DIM_  768
#define H_    12
#define DH_   64
#define M_TOT (B_ * N_)       // 8192
#define QKV_N (3 * DIM_)      // 2304
#define SCALE_ 0.125f
#define LOG2E_ 1.4426950408889634f

typedef __nv_bfloat16 bf16;

// --------------------------- device scratch (no allocs) --------------------
__device__ bf16 g_xh[(size_t)M_TOT * DIM_];
__device__ bf16 g_xl[(size_t)M_TOT * DIM_];
__device__ bf16 g_wqh[(size_t)QKV_N * DIM_];
__device__ bf16 g_wql[(size_t)QKV_N * DIM_];
__device__ bf16 g_wph[(size_t)DIM_ * DIM_];
__device__ bf16 g_wpl[(size_t)DIM_ * DIM_];
__device__ bf16 g_qkvh[(size_t)M_TOT * QKV_N];
__device__ bf16 g_qkvl[(size_t)M_TOT * QKV_N];
__device__ bf16 g_ah[(size_t)M_TOT * DIM_];
__device__ bf16 g_al[(size_t)M_TOT * DIM_];

// ===========================================================================
// helpers
// ===========================================================================
__device__ __forceinline__ uint32_t smem_u32(const void* p) {
    uint32_t a;
    asm("{ .reg .u64 t; cvta.to.shared.u64 t, %1; cvt.u32.u64 %0, t; }"
        : "=r"(a) : "l"(p));
    return a;
}
__device__ __forceinline__ void ldsm_x4(uint32_t* r, uint32_t addr) {
    asm volatile("ldmatrix.sync.aligned.m8n8.x4.shared.b16 {%0,%1,%2,%3}, [%4];"
                 : "=r"(r[0]), "=r"(r[1]), "=r"(r[2]), "=r"(r[3]) : "r"(addr));
}
__device__ __forceinline__ void ldsm_x4_t(uint32_t* r, uint32_t addr) {
    asm volatile("ldmatrix.sync.aligned.m8n8.x4.trans.shared.b16 {%0,%1,%2,%3}, [%4];"
                 : "=r"(r[0]), "=r"(r[1]), "=r"(r[2]), "=r"(r[3]) : "r"(addr));
}
__device__ __forceinline__ void mma_bf16(float* d, const uint32_t* a, const uint32_t* b) {
    asm volatile("mma.sync.aligned.m16n8k16.row.col.f32.bf16.bf16.f32 "
                 "{%0,%1,%2,%3}, {%4,%5,%6,%7}, {%8,%9}, {%0,%1,%2,%3};"
                 : "+f"(d[0]), "+f"(d[1]), "+f"(d[2]), "+f"(d[3])
                 : "r"(a[0]), "r"(a[1]), "r"(a[2]), "r"(a[3]), "r"(b[0]), "r"(b[1]));
}
__device__ __forceinline__ void split_bf16(float x, bf16& h, bf16& l) {
    h = __float2bfloat16_rn(x);
    l = __float2bfloat16_rn(x - __bfloat162float(h));
}
__device__ __forceinline__ uint32_t pack2u(bf16 a, bf16 b) {
    __nv_bfloat162 t = __halves2bfloat162(a, b);
    return *reinterpret_cast<uint32_t*>(&t);
}
__device__ __forceinline__ float ex2(float x) {
    float y; asm("ex2.approx.f32 %0, %1;" : "=f"(y) : "f"(x)); return y;
}
__device__ __forceinline__ void cp_async16(uint32_t dst, const void* src) {
    asm volatile("cp.async.cg.shared.global [%0], [%1], 16;" :: "r"(dst), "l"(src));
}
#define CP_COMMIT() asm volatile("cp.async.commit_group;" ::: "memory")
#define CP_WAIT0()  asm volatile("cp.async.wait_group 0;" ::: "memory")

// ===========================================================================
// convert kernels
// ===========================================================================
__global__ void conv_split_kernel(const float* __restrict__ X,
                                  bf16* __restrict__ Xh, bf16* __restrict__ Xl,
                                  int n4)
{
    int idx = blockIdx.x * blockDim.x + threadIdx.x;
    if (idx >= n4) return;
    float4 v = ((const float4*)X)[idx];
    bf16 h0, l0, h1, l1, h2, l2, h3, l3;
    split_bf16(v.x, h0, l0); split_bf16(v.y, h1, l1);
    split_bf16(v.z, h2, l2); split_bf16(v.w, h3, l3);
    ((uint32_t*)Xh)[idx * 2]     = pack2u(h0, h1);
    ((uint32_t*)Xh)[idx * 2 + 1] = pack2u(h2, h3);
    ((uint32_t*)Xl)[idx * 2]     = pack2u(l0, l1);
    ((uint32_t*)Xl)[idx * 2 + 1] = pack2u(l2, l3);
}

__global__ void transpose_split_kernel(const float* __restrict__ W,
                                       bf16* __restrict__ Th, bf16* __restrict__ Tl,
                                       int K, int Nw)
{
    __shared__ float t[32][33];
    const int n0 = blockIdx.x * 32, k0 = blockIdx.y * 32;
    const int tx = threadIdx.x, ty = threadIdx.y;   // (32, 8)
    #pragma unroll
    for (int i = 0; i < 32; i += 8)
        t[ty + i][tx] = W[(size_t)(k0 + ty + i) * Nw + n0 + tx];
    __syncthreads();
    #pragma unroll
    for (int i = 0; i < 32; i += 8) {
        float v = t[tx][ty + i];
        bf16 h, l;
        split_bf16(v, h, l);
        Th[(size_t)(n0 + ty + i) * K + k0 + tx] = h;
        Tl[(size_t)(n0 + ty + i) * K + k0 + tx] = l;
    }
}

// ===========================================================================
// tgemm: C[M,N] = A[M,K] @ B^T (B stored [N][K]), split-bf16 planes,
// cp.async 2-stage pipeline. 128x128 block, BK=32, 8 warps of 64x32.
// ===========================================================================
#define ASTR 40
#define TG_SMEM (2 * 4 * 128 * ASTR * 2)   // 81920 B

__global__ __launch_bounds__(256) void tgemm_kernel(
    const bf16* __restrict__ Aih, const bf16* __restrict__ Ail,
    const bf16* __restrict__ Bih, const bf16* __restrict__ Bil,
    float* __restrict__ Cf, bf16* __restrict__ Ch, bf16* __restrict__ Cl,
    int M, int N, int K, const float* __restrict__ bias, int qcols)
{
    extern __shared__ __align__(16) bf16 dsm[];
    const uint32_t base = smem_u32(dsm);

    const int tid  = threadIdx.x;
    const int lane = tid & 31;
    const int wid  = tid >> 5;
    const int wm   = (wid >> 2) * 64;
    const int wn   = (wid & 3) * 32;
    const int bm   = blockIdx.y * 128;
    const int bn   = blockIdx.x * 128;

    const int nc = K / 32;

    // stage chunk c into buffer cb via cp.async (8 chunks of 16B per thread)
    auto stage = [&](int c, int cb) {
        const int kc = c * 32;
        #pragma unroll
        for (int i = 0; i < 8; i++) {
            const int p   = i >> 1;                       // plane 0..3
            const int rem = (i & 1) * 256 + tid;          // 0..511
            const int row = rem >> 2;
            const int c8  = (rem & 3) * 8;
            const bf16* src;
            if      (p == 0) src = Aih + (size_t)(bm + row) * K + kc + c8;
            else if (p == 1) src = Ail + (size_t)(bm + row) * K + kc + c8;
            else if (p == 2) src = Bih + (size_t)(bn + row) * K + kc + c8;
            else             src = Bil + (size_t)(bn + row) * K + kc + c8;
            uint32_t dst = base + (uint32_t)(((cb * 4 + p) * 128 + row) * ASTR + c8) * 2;
            cp_async16(dst, src);
        }
    };

    float acc[4][4][4] = {};

    stage(0, 0);
    CP_COMMIT();

    for (int c = 0; c < nc; c++) {
        CP_WAIT0();
        __syncthreads();
        if (c + 1 < nc) {
            stage(c + 1, (c + 1) & 1);
            CP_COMMIT();
        }

        const int cb = c & 1;
        const uint32_t uAh = base + (uint32_t)((cb * 4 + 0) * 128 * ASTR) * 2;
        const uint32_t uAl = base + (uint32_t)((cb * 4 + 1) * 128 * ASTR) * 2;
        const uint32_t uBh = base + (uint32_t)((cb * 4 + 2) * 128 * ASTR) * 2;
        const uint32_t uBl = base + (uint32_t)((cb * 4 + 3) * 128 * ASTR) * 2;

        #pragma unroll
        for (int kb = 0; kb < 2; kb++) {
            const uint32_t aoff =
                (uint32_t)((wm + (lane & 15)) * (ASTR * 2) +
                           (kb * 16 + ((lane >> 4) << 3)) * 2);
            uint32_t ah[4][4], al[4][4];
            #pragma unroll
            for (int mi = 0; mi < 4; mi++) {
                ldsm_x4(ah[mi], uAh + aoff + mi * 16 * (ASTR * 2));
                ldsm_x4(al[mi], uAl + aoff + mi * 16 * (ASTR * 2));
            }
            #pragma unroll
            for (int njp = 0; njp < 2; njp++) {
                const uint32_t boff =
                    (uint32_t)((wn + njp * 16 + (lane & 7) + ((lane >> 4) << 3)) * (ASTR * 2) +
                               (kb * 16 + (((lane >> 3) & 1) << 3)) * 2);
                uint32_t bh4[4], bl4[4];
                ldsm_x4(bh4, uBh + boff);
                ldsm_x4(bl4, uBl + boff);
                #pragma unroll
                for (int mi = 0; mi < 4; mi++) {
                    #pragma unroll
                    for (int sub = 0; sub < 2; sub++) {
                        float* d = acc[mi][njp * 2 + sub];
                        mma_bf16(d, ah[mi], &bh4[sub * 2]);
                        mma_bf16(d, ah[mi], &bl4[sub * 2]);
                        mma_bf16(d, al[mi], &bh4[sub * 2]);
                    }
                }
            }
        }
    }

    // ---- epilogue ----
    const float sc = (bn < qcols) ? (SCALE_ * LOG2E_) : 1.0f;
    #pragma unroll
    for (int mi = 0; mi < 4; mi++) {
        #pragma unroll
        for (int nj = 0; nj < 4; nj++) {
            int row = bm + wm + mi * 16 + (lane >> 2);
            int col = bn + wn + nj * 8 + (lane & 3) * 2;
            if (Cf) {
                float b0 = bias ? bias[col] : 0.f;
                float b1 = bias ? bias[col + 1] : 0.f;
                float2 v0 = {acc[mi][nj][0] + b0, acc[mi][nj][1] + b1};
                float2 v1 = {acc[mi][nj][2] + b0, acc[mi][nj][3] + b1};
                *(float2*)(Cf + (size_t)row * N + col) = v0;
                *(float2*)(Cf + (size_t)(row + 8) * N + col) = v1;
            } else {
                bf16 h0, l0, h1, l1, h2, l2, h3, l3;
                split_bf16(acc[mi][nj][0] * sc, h0, l0);
                split_bf16(acc[mi][nj][1] * sc, h1, l1);
                split_bf16(acc[mi][nj][2] * sc, h2, l2);
                split_bf16(acc[mi][nj][3] * sc, h3, l3);
                *(uint32_t*)(Ch + (size_t)row * N + col)       = pack2u(h0, h1);
                *(uint32_t*)(Ch + (size_t)(row + 8) * N + col) = pack2u(h2, h3);
                *(uint32_t*)(Cl + (size_t)row * N + col)       = pack2u(l0, l1);
                *(uint32_t*)(Cl + (size_t)(row + 8) * N + col) = pack2u(l2, l3);
            }
        }
    }
}

// ===========================================================================
// Flash attention (tensor cores, split-bf16, cp.async KV pipeline).
// One CTA = 128 q rows of one (b,h). 8 warps x 16 q rows. kv tiles of 64.
// Q region is reused as KV buffer B after Q fragments move to registers.
// Scores are in log2 domain (log2e folded into Q scale upstream).
// ===========================================================================
#define FSTR 72
#define FREG  (4 * 64 * FSTR)              // bf16 units per KV region = 18432
#define FLASH_SMEM (2 * FREG * 2)          // 73728 B

__global__ __launch_bounds__(256) void flash_kernel(
    const bf16* __restrict__ qh_g, const bf16* __restrict__ ql_g,
    bf16* __restrict__ outh, bf16* __restrict__ outl)
{
    extern __shared__ __align__(16) bf16 fsm[];
    const uint32_t baseu = smem_u32(fsm);

    const int tid  = threadIdx.x;
    const int lane = tid & 31;
    const int w    = tid >> 5;
    const int bh   = blockIdx.y;
    const int b    = bh / H_;
    const int h    = bh % H_;
    const int q0   = blockIdx.x * 128;

    const size_t rowbase = (size_t)b * N_ * QKV_N;
    const int qoff = h * DH_;
    const int koff = DIM_ + h * DH_;
    const int voff = 2 * DIM_ + h * DH_;

    // region A = fsm[0 .. FREG), region B = fsm[FREG .. 2*FREG)
    // Q planes live in region A initially: Qh at 0, Ql at 9216 (bf16 units)

    // ---- stage Q tile (plain 16B copies) ----
    #pragma unroll
    for (int i = 0; i < 4; i++) {
        int idx = tid + i * 256;
        int row = idx >> 3, c8 = (idx & 7) * 8;
        size_t g = rowbase + (size_t)(q0 + row) * QKV_N + qoff + c8;
        *(float4*)&fsm[row * FSTR + c8]        = *(const float4*)(qh_g + g);
        *(float4*)&fsm[9216 + row * FSTR + c8] = *(const float4*)(ql_g + g);
    }
    __syncthreads();

    // KV staging into region reg (bf16-unit offset) via cp.async
    auto stage_kv = [&](int t, uint32_t reg) {
        const int kr0 = t * 64;
        #pragma unroll
        for (int i = 0; i < 8; i++) {
            const int p   = i >> 1;                   // 0:Kh 1:Kl 2:Vh 3:Vl
            const int rem = (i & 1) * 256 + tid;      // 0..511
            const int row = rem >> 3;
            const int c8  = (rem & 7) * 8;
            const size_t g = rowbase + (size_t)(kr0 + row) * QKV_N +
                             ((p < 2) ? koff : voff) + c8;
            const bf16* src = ((p & 1) ? ql_g : qh_g) + g;
            uint32_t dst = baseu + (reg + p * 4608 + row * FSTR + c8) * 2;
            cp_async16(dst, src);
        }
    };

    // prefetch KV tile 0 into region B while we read Q fragments from A
    stage_kv(0, FREG);
    CP_COMMIT();

    // ---- preload Q fragments from region A ----
    uint32_t qh[4][4], ql[4][4];
    #pragma unroll
    for (int kb = 0; kb < 4; kb++) {
        uint32_t off = (uint32_t)((w * 16 + (lane & 15)) * (FSTR * 2) +
                                  (kb * 16 + ((lane >> 4) << 3)) * 2);
        ldsm_x4(qh[kb], baseu + off);
        ldsm_x4(ql[kb], baseu + 9216 * 2 + off);
    }

    float o[8][4] = {};
    float m0 = -1e30f, m1 = -1e30f, l0 = 0.f, l1 = 0.f;

    for (int t = 0; t < N_ / 64; t++) {
        CP_WAIT0();
        __syncthreads();
        // prefetch next tile into the other region (freed: tile t-1 done,
        // and for t=0 the Q fragments are in registers)
        if (t + 1 < N_ / 64) {
            stage_kv(t + 1, ((t + 1) & 1) ? 0u : (uint32_t)FREG);
            CP_COMMIT();
        }

        const uint32_t reg = (t & 1) ? 0u : (uint32_t)FREG;
        const uint32_t uKh = baseu + reg * 2;
        const uint32_t uKl = baseu + (reg + 4608) * 2;
        const uint32_t uVh = baseu + (reg + 9216) * 2;
        const uint32_t uVl = baseu + (reg + 13824) * 2;

        // ---- S = Q @ K^T (log2 domain) ----
        float s[8][4] = {};
        #pragma unroll
        for (int kb = 0; kb < 4; kb++) {
            #pragma unroll
            for (int njp = 0; njp < 4; njp++) {
                uint32_t off = (uint32_t)((njp * 16 + (lane & 7) + ((lane >> 4) << 3)) * (FSTR * 2) +
                                          (kb * 16 + (((lane >> 3) & 1) << 3)) * 2);
                uint32_t kbh[4], kbl[4];
                ldsm_x4(kbh, uKh + off);
                ldsm_x4(kbl, uKl + off);
                #pragma unroll
                for (int sub = 0; sub < 2; sub++) {
                    float* d = s[njp * 2 + sub];
                    mma_bf16(d, qh[kb], &kbh[sub * 2]);
                    mma_bf16(d, qh[kb], &kbl[sub * 2]);
                    mma_bf16(d, ql[kb], &kbh[sub * 2]);
                }
            }
        }

        // ---- online softmax (base-2) ----
        float mx0 = -1e30f, mx1 = -1e30f;
        #pragma unroll
        for (int nj = 0; nj < 8; nj++) {
            mx0 = fmaxf(mx0, fmaxf(s[nj][0], s[nj][1]));
            mx1 = fmaxf(mx1, fmaxf(s[nj][2], s[nj][3]));
        }
        mx0 = fmaxf(mx0, __shfl_xor_sync(0xffffffffu, mx0, 1));
        mx0 = fmaxf(mx0, __shfl_xor_sync(0xffffffffu, mx0, 2));
        mx1 = fmaxf(mx1, __shfl_xor_sync(0xffffffffu, mx1, 1));
        mx1 = fmaxf(mx1, __shfl_xor_sync(0xffffffffu, mx1, 2));
        float mn0 = fmaxf(m0, mx0), mn1 = fmaxf(m1, mx1);
        float a0 = ex2(m0 - mn0), a1 = ex2(m1 - mn1);
        m0 = mn0; m1 = mn1;

        float sum0 = 0.f, sum1 = 0.f;
        #pragma unroll
        for (int nj = 0; nj < 8; nj++) {
            s[nj][0] = ex2(s[nj][0] - mn0);
            s[nj][1] = ex2(s[nj][1] - mn0);
            s[nj][2] = ex2(s[nj][2] - mn1);
            s[nj][3] = ex2(s[nj][3] - mn1);
            sum0 += s[nj][0] + s[nj][1];
            sum1 += s[nj][2] + s[nj][3];
        }
        sum0 += __shfl_xor_sync(0xffffffffu, sum0, 1);
        sum0 += __shfl_xor_sync(0xffffffffu, sum0, 2);
        sum1 += __shfl_xor_sync(0xffffffffu, sum1, 1);
        sum1 += __shfl_xor_sync(0xffffffffu, sum1, 2);
        l0 = l0 * a0 + sum0;
        l1 = l1 * a1 + sum1;

        #pragma unroll
        for (int dj = 0; dj < 8; dj++) {
            o[dj][0] *= a0; o[dj][1] *= a0;
            o[dj][2] *= a1; o[dj][3] *= a1;
        }

        // ---- P fragments (in-register, split) ----
        uint32_t pah[4][4], pal[4][4];
        #pragma unroll
        for (int kb = 0; kb < 4; kb++) {
            #pragma unroll
            for (int half = 0; half < 2; half++) {
                const float* sc = s[2 * kb + half];
                bf16 h0, lo0, h1, lo1, h2, lo2, h3, lo3;
                split_bf16(sc[0], h0, lo0); split_bf16(sc[1], h1, lo1);
                split_bf16(sc[2], h2, lo2); split_bf16(sc[3], h3, lo3);
                pah[kb][half * 2 + 0] = pack2u(h0, h1);
                pah[kb][half * 2 + 1] = pack2u(h2, h3);
                pal[kb][half * 2 + 0] = pack2u(lo0, lo1);
                pal[kb][half * 2 + 1] = pack2u(lo2, lo3);
            }
        }

        // ---- O += P @ V ----
        #pragma unroll
        for (int kb = 0; kb < 4; kb++) {
            #pragma unroll
            for (int djp = 0; djp < 4; djp++) {
                uint32_t off = (uint32_t)((kb * 16 + (lane & 7) + (((lane >> 3) & 1) << 3)) * (FSTR * 2) +
                                          (djp * 16 + ((lane >> 4) << 3)) * 2);
                uint32_t vbh[4], vbl[4];
                ldsm_x4_t(vbh, uVh + off);
                ldsm_x4_t(vbl, uVl + off);
                #pragma unroll
                for (int sub = 0; sub < 2; sub++) {
                    float* d = o[djp * 2 + sub];
                    mma_bf16(d, pah[kb], &vbh[sub * 2]);
                    mma_bf16(d, pah[kb], &vbl[sub * 2]);
                    mma_bf16(d, pal[kb], &vbh[sub * 2]);
                }
            }
        }
    }

    // ---- normalize + split-bf16 write ----
    float inv0 = 1.0f / l0, inv1 = 1.0f / l1;
    size_t row0 = (size_t)(b * N_ + q0 + w * 16 + (lane >> 2));
    #pragma unroll
    for (int dj = 0; dj < 8; dj++) {
        int col = h * DH_ + dj * 8 + (lane & 3) * 2;
        bf16 h0, lo0, h1, lo1, h2, lo2, h3, lo3;
        split_bf16(o[dj][0] * inv0, h0, lo0);
        split_bf16(o[dj][1] * inv0, h1, lo1);
        split_bf16(o[dj][2] * inv1, h2, lo2);
        split_bf16(o[dj][3] * inv1, h3, lo3);
        *(uint32_t*)(outh + row0 * DIM_ + col)       = pack2u(h0, h1);
        *(uint32_t*)(outh + (row0 + 8) * DIM_ + col) = pack2u(h2, h3);
        *(uint32_t*)(outl + row0 * DIM_ + col)       = pack2u(lo0, lo1);
        *(uint32_t*)(outl + (row0 + 8) * DIM_ + col) = pack2u(lo2, lo3);
    }
}

// ---------------------------------------------------------------------------
// Launch
// ---------------------------------------------------------------------------
extern "C" void kernel_launch(void* const* d_in, const int* in_sizes, int n_in,
                              void* d_out, int out_size)
{
    const float* x      = (const float*)d_in[0];
    const float* w_qkv  = (const float*)d_in[1];
    const float* w_proj = (const float*)d_in[2];
    const float* b_proj = (const float*)d_in[3];
    float* out = (float*)d_out;

    bf16 *xh, *xl, *wqh, *wql, *wph, *wpl, *qkvh, *qkvl, *ah, *al;
    cudaGetSymbolAddress((void**)&xh, g_xh);
    cudaGetSymbolAddress((void**)&xl, g_xl);
    cudaGetSymbolAddress((void**)&wqh, g_wqh);
    cudaGetSymbolAddress((void**)&wql, g_wql);
    cudaGetSymbolAddress((void**)&wph, g_wph);
    cudaGetSymbolAddress((void**)&wpl, g_wpl);
    cudaGetSymbolAddress((void**)&qkvh, g_qkvh);
    cudaGetSymbolAddress((void**)&qkvl, g_qkvl);
    cudaGetSymbolAddress((void**)&ah, g_ah);
    cudaGetSymbolAddress((void**)&al, g_al);

    cudaFuncSetAttribute(tgemm_kernel,
                         cudaFuncAttributeMaxDynamicSharedMemorySize, TG_SMEM);
    cudaFuncSetAttribute(flash_kernel,
                         cudaFuncAttributeMaxDynamicSharedMemorySize, FLASH_SMEM);

    // 0) converts
    {
        int n4 = M_TOT * DIM_ / 4;
        conv_split_kernel<<<(n4 + 255) / 256, 256>>>(x, xh, xl, n4);
        dim3 tb(32, 8);
        transpose_split_kernel<<<dim3(QKV_N / 32, DIM_ / 32), tb>>>(w_qkv, wqh, wql, DIM_, QKV_N);
        transpose_split_kernel<<<dim3(DIM_ / 32, DIM_ / 32), tb>>>(w_proj, wph, wpl, DIM_, DIM_);
    }

    // 1) QKV = X @ Wqkv -> split-bf16 planes (Q scaled by 0.125*log2e)
    dim3 g1(QKV_N / 128, M_TOT / 128);
    tgemm_kernel<<<g1, 256, TG_SMEM>>>(xh, xl, wqh, wql,
                                       nullptr, qkvh, qkvl,
                                       M_TOT, QKV_N, DIM_, nullptr, DIM_);

    // 2) Flash attention
    dim3 g2(N_ / 128, B_ * H_);
    flash_kernel<<<g2, 256, FLASH_SMEM>>>(qkvh, qkvl, ah, al);

    // 3) OUT = ATTN @ Wproj + bias (fp32)
    dim3 g3(DIM_ / 128, M_TOT / 128);
    tgemm_kernel<<<g3, 256, TG_SMEM>>>(ah, al, wph, wpl,
                                       out, nullptr, nullptr,
                                       M_TOT, DIM_, DIM_, b_proj, 0);
}

// round 8
// speedup vs baseline: 3.8976x; 1.4443x over previous
#include <cuda_runtime.h>
#include <cuda_fp16.h>
#include <cstdint>

#define B_    4
#define N_    2048
#define DIM_  768
#define H_    12
#define DH_   64
#define M_TOT (B_ * N_)       // 8192
#define QKV_N (3 * DIM_)      // 2304
#define SCALE_ 0.125f
#define LOG2E_ 1.4426950408889634f

typedef __half half_t;

// --------------------------- device scratch (no allocs) --------------------
__device__ half_t g_xh[(size_t)M_TOT * DIM_];     // X fp16 (A operand, 1 plane)
__device__ half_t g_wqh[(size_t)QKV_N * DIM_];    // Wqkv^T hi [2304,768]
__device__ half_t g_wql[(size_t)QKV_N * DIM_];    // Wqkv^T lo
__device__ half_t g_wph[(size_t)DIM_ * DIM_];     // Wproj^T hi
__device__ half_t g_wpl[(size_t)DIM_ * DIM_];     // Wproj^T lo
__device__ half_t g_qkvh[(size_t)M_TOT * QKV_N];  // QKV hi (Q pre-scaled)
__device__ half_t g_qkvl[(size_t)M_TOT * QKV_N];  // QKV lo (K,V used)
__device__ half_t g_ah[(size_t)M_TOT * DIM_];     // attn-out fp16 (1 plane)

// ===========================================================================
// helpers
// ===========================================================================
__device__ __forceinline__ uint32_t smem_u32(const void* p) {
    uint32_t a;
    asm("{ .reg .u64 t; cvta.to.shared.u64 t, %1; cvt.u32.u64 %0, t; }"
        : "=r"(a) : "l"(p));
    return a;
}
__device__ __forceinline__ void ldsm_x4(uint32_t* r, uint32_t addr) {
    asm volatile("ldmatrix.sync.aligned.m8n8.x4.shared.b16 {%0,%1,%2,%3}, [%4];"
                 : "=r"(r[0]), "=r"(r[1]), "=r"(r[2]), "=r"(r[3]) : "r"(addr));
}
__device__ __forceinline__ void ldsm_x4_t(uint32_t* r, uint32_t addr) {
    asm volatile("ldmatrix.sync.aligned.m8n8.x4.trans.shared.b16 {%0,%1,%2,%3}, [%4];"
                 : "=r"(r[0]), "=r"(r[1]), "=r"(r[2]), "=r"(r[3]) : "r"(addr));
}
__device__ __forceinline__ void mma_f16(float* d, const uint32_t* a, const uint32_t* b) {
    asm volatile("mma.sync.aligned.m16n8k16.row.col.f32.f16.f16.f32 "
                 "{%0,%1,%2,%3}, {%4,%5,%6,%7}, {%8,%9}, {%0,%1,%2,%3};"
                 : "+f"(d[0]), "+f"(d[1]), "+f"(d[2]), "+f"(d[3])
                 : "r"(a[0]), "r"(a[1]), "r"(a[2]), "r"(a[3]), "r"(b[0]), "r"(b[1]));
}
__device__ __forceinline__ void split_f16(float x, half_t& h, half_t& l) {
    h = __float2half_rn(x);
    l = __float2half_rn(x - __half2float(h));
}
__device__ __forceinline__ uint32_t pack2h(half_t a, half_t b) {
    __half2 t = __halves2half2(a, b);
    return *reinterpret_cast<uint32_t*>(&t);
}
__device__ __forceinline__ uint32_t packf2h(float a, float b) {
    __half2 t = __floats2half2_rn(a, b);   // .x = a
    return *reinterpret_cast<uint32_t*>(&t);
}
__device__ __forceinline__ float ex2(float x) {
    float y; asm("ex2.approx.f32 %0, %1;" : "=f"(y) : "f"(x)); return y;
}
__device__ __forceinline__ void cp_async16(uint32_t dst, const void* src) {
    asm volatile("cp.async.cg.shared.global [%0], [%1], 16;" :: "r"(dst), "l"(src));
}
#define CP_COMMIT() asm volatile("cp.async.commit_group;" ::: "memory")
#define CP_WAIT0()  asm volatile("cp.async.wait_group 0;" ::: "memory")

// ===========================================================================
// convert kernels
// ===========================================================================
__global__ void conv_f16_kernel(const float* __restrict__ X,
                                half_t* __restrict__ Xh, int n4)
{
    int idx = blockIdx.x * blockDim.x + threadIdx.x;
    if (idx >= n4) return;
    float4 v = ((const float4*)X)[idx];
    ((uint32_t*)Xh)[idx * 2]     = packf2h(v.x, v.y);
    ((uint32_t*)Xh)[idx * 2 + 1] = packf2h(v.z, v.w);
}

// W [K][Nw] fp32 -> Th/Tl [Nw][K] fp16 (transpose + split)
__global__ void transpose_split_kernel(const float* __restrict__ W,
                                       half_t* __restrict__ Th, half_t* __restrict__ Tl,
                                       int K, int Nw)
{
    __shared__ float t[32][33];
    const int n0 = blockIdx.x * 32, k0 = blockIdx.y * 32;
    const int tx = threadIdx.x, ty = threadIdx.y;   // (32, 8)
    #pragma unroll
    for (int i = 0; i < 32; i += 8)
        t[ty + i][tx] = W[(size_t)(k0 + ty + i) * Nw + n0 + tx];
    __syncthreads();
    #pragma unroll
    for (int i = 0; i < 32; i += 8) {
        float v = t[tx][ty + i];
        half_t h, l;
        split_f16(v, h, l);
        Th[(size_t)(n0 + ty + i) * K + k0 + tx] = h;
        Tl[(size_t)(n0 + ty + i) * K + k0 + tx] = l;
    }
}

// ===========================================================================
// tgemm: C[M,N] = A[M,K] @ B^T (B stored [N][K] in 2 fp16 planes; A 1 plane).
// 128x128 block, BK=32, 8 warps of 64x32. cp.async 2-stage pipeline.
// 2 MMAs per k16: d += ah*bh; d += ah*bl.
// ===========================================================================
#define ASTR 40
#define TG_SMEM (2 * 3 * 128 * ASTR * 2)   // 61440 B

__global__ __launch_bounds__(256) void tgemm_kernel(
    const half_t* __restrict__ Aih,
    const half_t* __restrict__ Bih, const half_t* __restrict__ Bil,
    float* __restrict__ Cf, half_t* __restrict__ Ch, half_t* __restrict__ Cl,
    int M, int N, int K, const float* __restrict__ bias, int qcols)
{
    extern __shared__ __align__(16) half_t dsm[];
    const uint32_t base = smem_u32(dsm);

    const int tid  = threadIdx.x;
    const int lane = tid & 31;
    const int wid  = tid >> 5;
    const int wm   = (wid >> 2) * 64;
    const int wn   = (wid & 3) * 32;
    const int bm   = blockIdx.y * 128;
    const int bn   = blockIdx.x * 128;

    const int nc = K / 32;

    // stage chunk c into buffer cb (3 planes: A, Bh, Bl)
    auto stage = [&](int c, int cb) {
        const int kc = c * 32;
        #pragma unroll
        for (int i = 0; i < 6; i++) {
            const int p   = i >> 1;                      // 0:A 1:Bh 2:Bl
            const int rem = (i & 1) * 256 + tid;         // 0..511
            const int row = rem >> 2;
            const int c8  = (rem & 3) * 8;
            const half_t* src;
            if      (p == 0) src = Aih + (size_t)(bm + row) * K + kc + c8;
            else if (p == 1) src = Bih + (size_t)(bn + row) * K + kc + c8;
            else             src = Bil + (size_t)(bn + row) * K + kc + c8;
            uint32_t dst = base + (uint32_t)(((cb * 3 + p) * 128 + row) * ASTR + c8) * 2;
            cp_async16(dst, src);
        }
    };

    float acc[4][4][4] = {};

    stage(0, 0);
    CP_COMMIT();

    for (int c = 0; c < nc; c++) {
        CP_WAIT0();
        __syncthreads();
        if (c + 1 < nc) {
            stage(c + 1, (c + 1) & 1);
            CP_COMMIT();
        }

        const int cb = c & 1;
        const uint32_t uA  = base + (uint32_t)((cb * 3 + 0) * 128 * ASTR) * 2;
        const uint32_t uBh = base + (uint32_t)((cb * 3 + 1) * 128 * ASTR) * 2;
        const uint32_t uBl = base + (uint32_t)((cb * 3 + 2) * 128 * ASTR) * 2;

        #pragma unroll
        for (int kb = 0; kb < 2; kb++) {
            const uint32_t aoff =
                (uint32_t)((wm + (lane & 15)) * (ASTR * 2) +
                           (kb * 16 + ((lane >> 4) << 3)) * 2);
            uint32_t ah[4][4];
            #pragma unroll
            for (int mi = 0; mi < 4; mi++)
                ldsm_x4(ah[mi], uA + aoff + mi * 16 * (ASTR * 2));
            #pragma unroll
            for (int njp = 0; njp < 2; njp++) {
                const uint32_t boff =
                    (uint32_t)((wn + njp * 16 + (lane & 7) + ((lane >> 4) << 3)) * (ASTR * 2) +
                               (kb * 16 + (((lane >> 3) & 1) << 3)) * 2);
                uint32_t bh4[4], bl4[4];
                ldsm_x4(bh4, uBh + boff);
                ldsm_x4(bl4, uBl + boff);
                #pragma unroll
                for (int mi = 0; mi < 4; mi++) {
                    #pragma unroll
                    for (int sub = 0; sub < 2; sub++) {
                        float* d = acc[mi][njp * 2 + sub];
                        mma_f16(d, ah[mi], &bh4[sub * 2]);
                        mma_f16(d, ah[mi], &bl4[sub * 2]);
                    }
                }
            }
        }
    }

    // ---- epilogue ----
    const float sc = (bn < qcols) ? (SCALE_ * LOG2E_) : 1.0f;
    #pragma unroll
    for (int mi = 0; mi < 4; mi++) {
        #pragma unroll
        for (int nj = 0; nj < 4; nj++) {
            int row = bm + wm + mi * 16 + (lane >> 2);
            int col = bn + wn + nj * 8 + (lane & 3) * 2;
            if (Cf) {
                float b0 = bias ? bias[col] : 0.f;
                float b1 = bias ? bias[col + 1] : 0.f;
                float2 v0 = {acc[mi][nj][0] + b0, acc[mi][nj][1] + b1};
                float2 v1 = {acc[mi][nj][2] + b0, acc[mi][nj][3] + b1};
                *(float2*)(Cf + (size_t)row * N + col) = v0;
                *(float2*)(Cf + (size_t)(row + 8) * N + col) = v1;
            } else {
                half_t h0, l0, h1, l1, h2, l2, h3, l3;
                split_f16(acc[mi][nj][0] * sc, h0, l0);
                split_f16(acc[mi][nj][1] * sc, h1, l1);
                split_f16(acc[mi][nj][2] * sc, h2, l2);
                split_f16(acc[mi][nj][3] * sc, h3, l3);
                *(uint32_t*)(Ch + (size_t)row * N + col)       = pack2h(h0, h1);
                *(uint32_t*)(Ch + (size_t)(row + 8) * N + col) = pack2h(h2, h3);
                *(uint32_t*)(Cl + (size_t)row * N + col)       = pack2h(l0, l1);
                *(uint32_t*)(Cl + (size_t)(row + 8) * N + col) = pack2h(l2, l3);
            }
        }
    }
}

// ===========================================================================
// Flash attention (fp16 tensor cores). One CTA = 128 q rows of one (b,h).
// 8 warps x 16 q rows, kv tiles of 64. Q: 1 plane (pre-scaled by 0.125*log2e).
// K,V: 2 planes each. S = qh*kh + qh*kl; PV = p*vh + p*vl. log2-domain softmax.
// cp.async KV pipeline; Q smem region reused as KV buffer after frag preload.
// ===========================================================================
#define FSTR 72
#define FREG  (4 * 64 * FSTR)              // fp16 units per KV region = 18432
#define FLASH_SMEM (2 * FREG * 2)          // 73728 B

__global__ __launch_bounds__(256) void flash_kernel(
    const half_t* __restrict__ qh_g, const half_t* __restrict__ ql_g,
    half_t* __restrict__ outh)
{
    extern __shared__ __align__(16) half_t fsm[];
    const uint32_t baseu = smem_u32(fsm);

    const int tid  = threadIdx.x;
    const int lane = tid & 31;
    const int w    = tid >> 5;
    const int bh   = blockIdx.y;
    const int b    = bh / H_;
    const int h    = bh % H_;
    const int q0   = blockIdx.x * 128;

    const size_t rowbase = (size_t)b * N_ * QKV_N;
    const int qoff = h * DH_;
    const int koff = DIM_ + h * DH_;
    const int voff = 2 * DIM_ + h * DH_;

    // ---- stage Q tile (hi plane only) into region A ----
    #pragma unroll
    for (int i = 0; i < 4; i++) {
        int idx = tid + i * 256;
        int row = idx >> 3, c8 = (idx & 7) * 8;
        size_t g = rowbase + (size_t)(q0 + row) * QKV_N + qoff + c8;
        *(float4*)&fsm[row * FSTR + c8] = *(const float4*)(qh_g + g);
    }
    __syncthreads();

    // KV staging into region reg (fp16-unit offset): planes Kh,Kl,Vh,Vl
    auto stage_kv = [&](int t, uint32_t reg) {
        const int kr0 = t * 64;
        #pragma unroll
        for (int i = 0; i < 8; i++) {
            const int p   = i >> 1;                   // 0:Kh 1:Kl 2:Vh 3:Vl
            const int rem = (i & 1) * 256 + tid;      // 0..511
            const int row = rem >> 3;
            const int c8  = (rem & 7) * 8;
            const size_t g = rowbase + (size_t)(kr0 + row) * QKV_N +
                             ((p < 2) ? koff : voff) + c8;
            const half_t* src = ((p & 1) ? ql_g : qh_g) + g;
            uint32_t dst = baseu + (reg + p * 4608 + row * FSTR + c8) * 2;
            cp_async16(dst, src);
        }
    };

    stage_kv(0, FREG);
    CP_COMMIT();

    // ---- preload Q fragments ----
    uint32_t qh[4][4];
    #pragma unroll
    for (int kb = 0; kb < 4; kb++) {
        uint32_t off = (uint32_t)((w * 16 + (lane & 15)) * (FSTR * 2) +
                                  (kb * 16 + ((lane >> 4) << 3)) * 2);
        ldsm_x4(qh[kb], baseu + off);
    }

    float o[8][4] = {};
    float m0 = -1e30f, m1 = -1e30f, l0 = 0.f, l1 = 0.f;

    for (int t = 0; t < N_ / 64; t++) {
        CP_WAIT0();
        __syncthreads();
        if (t + 1 < N_ / 64) {
            stage_kv(t + 1, ((t + 1) & 1) ? 0u : (uint32_t)FREG);
            CP_COMMIT();
        }

        const uint32_t reg = (t & 1) ? 0u : (uint32_t)FREG;
        const uint32_t uKh = baseu + reg * 2;
        const uint32_t uKl = baseu + (reg + 4608) * 2;
        const uint32_t uVh = baseu + (reg + 9216) * 2;
        const uint32_t uVl = baseu + (reg + 13824) * 2;

        // ---- S = Q @ (Kh + Kl)^T  (log2 domain) ----
        float s[8][4] = {};
        #pragma unroll
        for (int kb = 0; kb < 4; kb++) {
            #pragma unroll
            for (int njp = 0; njp < 4; njp++) {
                uint32_t off = (uint32_t)((njp * 16 + (lane & 7) + ((lane >> 4) << 3)) * (FSTR * 2) +
                                          (kb * 16 + (((lane >> 3) & 1) << 3)) * 2);
                uint32_t kbh[4], kbl[4];
                ldsm_x4(kbh, uKh + off);
                ldsm_x4(kbl, uKl + off);
                #pragma unroll
                for (int sub = 0; sub < 2; sub++) {
                    float* d = s[njp * 2 + sub];
                    mma_f16(d, qh[kb], &kbh[sub * 2]);
                    mma_f16(d, qh[kb], &kbl[sub * 2]);
                }
            }
        }

        // ---- online softmax (base-2) ----
        float mx0 = -1e30f, mx1 = -1e30f;
        #pragma unroll
        for (int nj = 0; nj < 8; nj++) {
            mx0 = fmaxf(mx0, fmaxf(s[nj][0], s[nj][1]));
            mx1 = fmaxf(mx1, fmaxf(s[nj][2], s[nj][3]));
        }
        mx0 = fmaxf(mx0, __shfl_xor_sync(0xffffffffu, mx0, 1));
        mx0 = fmaxf(mx0, __shfl_xor_sync(0xffffffffu, mx0, 2));
        mx1 = fmaxf(mx1, __shfl_xor_sync(0xffffffffu, mx1, 1));
        mx1 = fmaxf(mx1, __shfl_xor_sync(0xffffffffu, mx1, 2));
        float mn0 = fmaxf(m0, mx0), mn1 = fmaxf(m1, mx1);
        float a0 = ex2(m0 - mn0), a1 = ex2(m1 - mn1);
        m0 = mn0; m1 = mn1;

        float sum0 = 0.f, sum1 = 0.f;
        #pragma unroll
        for (int nj = 0; nj < 8; nj++) {
            s[nj][0] = ex2(s[nj][0] - mn0);
            s[nj][1] = ex2(s[nj][1] - mn0);
            s[nj][2] = ex2(s[nj][2] - mn1);
            s[nj][3] = ex2(s[nj][3] - mn1);
            sum0 += s[nj][0] + s[nj][1];
            sum1 += s[nj][2] + s[nj][3];
        }
        sum0 += __shfl_xor_sync(0xffffffffu, sum0, 1);
        sum0 += __shfl_xor_sync(0xffffffffu, sum0, 2);
        sum1 += __shfl_xor_sync(0xffffffffu, sum1, 1);
        sum1 += __shfl_xor_sync(0xffffffffu, sum1, 2);
        l0 = l0 * a0 + sum0;
        l1 = l1 * a1 + sum1;

        #pragma unroll
        for (int dj = 0; dj < 8; dj++) {
            o[dj][0] *= a0; o[dj][1] *= a0;
            o[dj][2] *= a1; o[dj][3] *= a1;
        }

        // ---- P fragments (plain fp16, in-register) ----
        uint32_t pa[4][4];
        #pragma unroll
        for (int kb = 0; kb < 4; kb++) {
            #pragma unroll
            for (int half = 0; half < 2; half++) {
                const float* sc = s[2 * kb + half];
                pa[kb][half * 2 + 0] = packf2h(sc[0], sc[1]);
                pa[kb][half * 2 + 1] = packf2h(sc[2], sc[3]);
            }
        }

        // ---- O += P @ (Vh + Vl) ----
        #pragma unroll
        for (int kb = 0; kb < 4; kb++) {
            #pragma unroll
            for (int djp = 0; djp < 4; djp++) {
                uint32_t off = (uint32_t)((kb * 16 + (lane & 7) + (((lane >> 3) & 1) << 3)) * (FSTR * 2) +
                                          (djp * 16 + ((lane >> 4) << 3)) * 2);
                uint32_t vbh[4], vbl[4];
                ldsm_x4_t(vbh, uVh + off);
                ldsm_x4_t(vbl, uVl + off);
                #pragma unroll
                for (int sub = 0; sub < 2; sub++) {
                    float* d = o[djp * 2 + sub];
                    mma_f16(d, pa[kb], &vbh[sub * 2]);
                    mma_f16(d, pa[kb], &vbl[sub * 2]);
                }
            }
        }
    }

    // ---- normalize + fp16 write (1 plane) ----
    float inv0 = 1.0f / l0, inv1 = 1.0f / l1;
    size_t row0 = (size_t)(b * N_ + q0 + w * 16 + (lane >> 2));
    #pragma unroll
    for (int dj = 0; dj < 8; dj++) {
        int col = h * DH_ + dj * 8 + (lane & 3) * 2;
        *(uint32_t*)(outh + row0 * DIM_ + col) =
            packf2h(o[dj][0] * inv0, o[dj][1] * inv0);
        *(uint32_t*)(outh + (row0 + 8) * DIM_ + col) =
            packf2h(o[dj][2] * inv1, o[dj][3] * inv1);
    }
}

// ---------------------------------------------------------------------------
// Launch
// ---------------------------------------------------------------------------
extern "C" void kernel_launch(void* const* d_in, const int* in_sizes, int n_in,
                              void* d_out, int out_size)
{
    const float* x      = (const float*)d_in[0];
    const float* w_qkv  = (const float*)d_in[1];
    const float* w_proj = (const float*)d_in[2];
    const float* b_proj = (const float*)d_in[3];
    float* out = (float*)d_out;

    half_t *xh, *wqh, *wql, *wph, *wpl, *qkvh, *qkvl, *ah;
    cudaGetSymbolAddress((void**)&xh, g_xh);
    cudaGetSymbolAddress((void**)&wqh, g_wqh);
    cudaGetSymbolAddress((void**)&wql, g_wql);
    cudaGetSymbolAddress((void**)&wph, g_wph);
    cudaGetSymbolAddress((void**)&wpl, g_wpl);
    cudaGetSymbolAddress((void**)&qkvh, g_qkvh);
    cudaGetSymbolAddress((void**)&qkvl, g_qkvl);
    cudaGetSymbolAddress((void**)&ah, g_ah);

    cudaFuncSetAttribute(tgemm_kernel,
                         cudaFuncAttributeMaxDynamicSharedMemorySize, TG_SMEM);
    cudaFuncSetAttribute(flash_kernel,
                         cudaFuncAttributeMaxDynamicSharedMemorySize, FLASH_SMEM);

    // 0) converts
    {
        int n4 = M_TOT * DIM_ / 4;
        conv_f16_kernel<<<(n4 + 255) / 256, 256>>>(x, xh, n4);
        dim3 tb(32, 8);
        transpose_split_kernel<<<dim3(QKV_N / 32, DIM_ / 32), tb>>>(w_qkv, wqh, wql, DIM_, QKV_N);
        transpose_split_kernel<<<dim3(DIM_ / 32, DIM_ / 32), tb>>>(w_proj, wph, wpl, DIM_, DIM_);
    }

    // 1) QKV = X @ Wqkv -> fp16 planes (Q cols scaled by 0.125*log2e)
    dim3 g1(QKV_N / 128, M_TOT / 128);
    tgemm_kernel<<<g1, 256, TG_SMEM>>>(xh, wqh, wql,
                                       nullptr, qkvh, qkvl,
                                       M_TOT, QKV_N, DIM_, nullptr, DIM_);

    // 2) Flash attention
    dim3 g2(N_ / 128, B_ * H_);
    flash_kernel<<<g2, 256, FLASH_SMEM>>>(qkvh, qkvl, ah);

    // 3) OUT = ATTN @ Wproj + bias (fp32)
    dim3 g3(DIM_ / 128, M_TOT / 128);
    tgemm_kernel<<<g3, 256, TG_SMEM>>>(ah, wph, wpl,
                                       out, nullptr, nullptr,
                                       M_TOT, DIM_, DIM_, b_proj, 0);
}

// round 9
// speedup vs baseline: 4.2165x; 1.0818x over previous
#include <cuda_runtime.h>
#include <cuda_fp16.h>
#include <cstdint>

#define B_    4
#define N_    2048
#define DIM_  768
#define H_    12
#define DH_   64
#define M_TOT (B_ * N_)       // 8192
#define QKV_N (3 * DIM_)      // 2304
#define SCALE_ 0.125f
#define LOG2E_ 1.4426950408889634f

typedef __half half_t;

// --------------------------- device scratch (no allocs) --------------------
__device__ half_t g_xh[(size_t)M_TOT * DIM_];     // X fp16 (A operand, 1 plane)
__device__ half_t g_wqh[(size_t)QKV_N * DIM_];    // Wqkv^T hi [2304,768]
__device__ half_t g_wql[(size_t)QKV_N * DIM_];    // Wqkv^T lo
__device__ half_t g_wph[(size_t)DIM_ * DIM_];     // Wproj^T hi
__device__ half_t g_wpl[(size_t)DIM_ * DIM_];     // Wproj^T lo
__device__ half_t g_qkvh[(size_t)M_TOT * QKV_N];  // QKV hi (Q pre-scaled)
__device__ half_t g_qkvl[(size_t)M_TOT * QKV_N];  // QKV lo (K,V used)
__device__ half_t g_ah[(size_t)M_TOT * DIM_];     // attn-out fp16 (1 plane)

// ===========================================================================
// helpers
// ===========================================================================
__device__ __forceinline__ uint32_t smem_u32(const void* p) {
    uint32_t a;
    asm("{ .reg .u64 t; cvta.to.shared.u64 t, %1; cvt.u32.u64 %0, t; }"
        : "=r"(a) : "l"(p));
    return a;
}
__device__ __forceinline__ void ldsm_x4(uint32_t* r, uint32_t addr) {
    asm volatile("ldmatrix.sync.aligned.m8n8.x4.shared.b16 {%0,%1,%2,%3}, [%4];"
                 : "=r"(r[0]), "=r"(r[1]), "=r"(r[2]), "=r"(r[3]) : "r"(addr));
}
__device__ __forceinline__ void ldsm_x4_t(uint32_t* r, uint32_t addr) {
    asm volatile("ldmatrix.sync.aligned.m8n8.x4.trans.shared.b16 {%0,%1,%2,%3}, [%4];"
                 : "=r"(r[0]), "=r"(r[1]), "=r"(r[2]), "=r"(r[3]) : "r"(addr));
}
__device__ __forceinline__ void mma_f16(float* d, const uint32_t* a, const uint32_t* b) {
    asm volatile("mma.sync.aligned.m16n8k16.row.col.f32.f16.f16.f32 "
                 "{%0,%1,%2,%3}, {%4,%5,%6,%7}, {%8,%9}, {%0,%1,%2,%3};"
                 : "+f"(d[0]), "+f"(d[1]), "+f"(d[2]), "+f"(d[3])
                 : "r"(a[0]), "r"(a[1]), "r"(a[2]), "r"(a[3]), "r"(b[0]), "r"(b[1]));
}
__device__ __forceinline__ void split_f16(float x, half_t& h, half_t& l) {
    h = __float2half_rn(x);
    l = __float2half_rn(x - __half2float(h));
}
__device__ __forceinline__ uint32_t pack2h(half_t a, half_t b) {
    __half2 t = __halves2half2(a, b);
    return *reinterpret_cast<uint32_t*>(&t);
}
__device__ __forceinline__ uint32_t packf2h(float a, float b) {
    __half2 t = __floats2half2_rn(a, b);   // .x = a
    return *reinterpret_cast<uint32_t*>(&t);
}
__device__ __forceinline__ float ex2(float x) {
    float y; asm("ex2.approx.f32 %0, %1;" : "=f"(y) : "f"(x)); return y;
}
__device__ __forceinline__ void cp_async16(uint32_t dst, const void* src) {
    asm volatile("cp.async.cg.shared.global [%0], [%1], 16;" :: "r"(dst), "l"(src));
}
#define CP_COMMIT() asm volatile("cp.async.commit_group;" ::: "memory")
#define CP_WAIT0()  asm volatile("cp.async.wait_group 0;" ::: "memory")

// ===========================================================================
// convert kernels
// ===========================================================================
__global__ void conv_f16_kernel(const float* __restrict__ X,
                                half_t* __restrict__ Xh, int n4)
{
    int idx = blockIdx.x * blockDim.x + threadIdx.x;
    if (idx >= n4) return;
    float4 v = ((const float4*)X)[idx];
    ((uint32_t*)Xh)[idx * 2]     = packf2h(v.x, v.y);
    ((uint32_t*)Xh)[idx * 2 + 1] = packf2h(v.z, v.w);
}

// W [K][Nw] fp32 -> Th/Tl [Nw][K] fp16 (transpose + split)
__global__ void transpose_split_kernel(const float* __restrict__ W,
                                       half_t* __restrict__ Th, half_t* __restrict__ Tl,
                                       int K, int Nw)
{
    __shared__ float t[32][33];
    const int n0 = blockIdx.x * 32, k0 = blockIdx.y * 32;
    const int tx = threadIdx.x, ty = threadIdx.y;   // (32, 8)
    #pragma unroll
    for (int i = 0; i < 32; i += 8)
        t[ty + i][tx] = W[(size_t)(k0 + ty + i) * Nw + n0 + tx];
    __syncthreads();
    #pragma unroll
    for (int i = 0; i < 32; i += 8) {
        float v = t[tx][ty + i];
        half_t h, l;
        split_f16(v, h, l);
        Th[(size_t)(n0 + ty + i) * K + k0 + tx] = h;
        Tl[(size_t)(n0 + ty + i) * K + k0 + tx] = l;
    }
}

// ===========================================================================
// tgemm: C[M,N] = A[M,K] @ B^T (B stored [N][K] in 2 fp16 planes; A 1 plane).
// 128x128 block, BK=32, 8 warps of 64x32. cp.async 2-stage pipeline.
// 2 MMAs per k16: d += ah*bh; d += ah*bl.   2 CTAs/SM.
// ===========================================================================
#define ASTR 40
#define TG_SMEM (2 * 3 * 128 * ASTR * 2)   // 61440 B

__global__ __launch_bounds__(256, 2) void tgemm_kernel(
    const half_t* __restrict__ Aih,
    const half_t* __restrict__ Bih, const half_t* __restrict__ Bil,
    float* __restrict__ Cf, half_t* __restrict__ Ch, half_t* __restrict__ Cl,
    int M, int N, int K, const float* __restrict__ bias, int qcols)
{
    extern __shared__ __align__(16) half_t dsm[];
    const uint32_t base = smem_u32(dsm);

    const int tid  = threadIdx.x;
    const int lane = tid & 31;
    const int wid  = tid >> 5;
    const int wm   = (wid >> 2) * 64;
    const int wn   = (wid & 3) * 32;
    const int bm   = blockIdx.y * 128;
    const int bn   = blockIdx.x * 128;

    const int nc = K / 32;

    // stage chunk c into buffer cb (3 planes: A, Bh, Bl)
    auto stage = [&](int c, int cb) {
        const int kc = c * 32;
        #pragma unroll
        for (int i = 0; i < 6; i++) {
            const int p   = i >> 1;                      // 0:A 1:Bh 2:Bl
            const int rem = (i & 1) * 256 + tid;         // 0..511
            const int row = rem >> 2;
            const int c8  = (rem & 3) * 8;
            const half_t* src;
            if      (p == 0) src = Aih + (size_t)(bm + row) * K + kc + c8;
            else if (p == 1) src = Bih + (size_t)(bn + row) * K + kc + c8;
            else             src = Bil + (size_t)(bn + row) * K + kc + c8;
            uint32_t dst = base + (uint32_t)(((cb * 3 + p) * 128 + row) * ASTR + c8) * 2;
            cp_async16(dst, src);
        }
    };

    float acc[4][4][4] = {};

    stage(0, 0);
    CP_COMMIT();

    for (int c = 0; c < nc; c++) {
        CP_WAIT0();
        __syncthreads();
        if (c + 1 < nc) {
            stage(c + 1, (c + 1) & 1);
            CP_COMMIT();
        }

        const int cb = c & 1;
        const uint32_t uA  = base + (uint32_t)((cb * 3 + 0) * 128 * ASTR) * 2;
        const uint32_t uBh = base + (uint32_t)((cb * 3 + 1) * 128 * ASTR) * 2;
        const uint32_t uBl = base + (uint32_t)((cb * 3 + 2) * 128 * ASTR) * 2;

        #pragma unroll
        for (int kb = 0; kb < 2; kb++) {
            const uint32_t aoff =
                (uint32_t)((wm + (lane & 15)) * (ASTR * 2) +
                           (kb * 16 + ((lane >> 4) << 3)) * 2);
            uint32_t ah[4][4];
            #pragma unroll
            for (int mi = 0; mi < 4; mi++)
                ldsm_x4(ah[mi], uA + aoff + mi * 16 * (ASTR * 2));
            #pragma unroll
            for (int njp = 0; njp < 2; njp++) {
                const uint32_t boff =
                    (uint32_t)((wn + njp * 16 + (lane & 7) + ((lane >> 4) << 3)) * (ASTR * 2) +
                               (kb * 16 + (((lane >> 3) & 1) << 3)) * 2);
                uint32_t bh4[4], bl4[4];
                ldsm_x4(bh4, uBh + boff);
                ldsm_x4(bl4, uBl + boff);
                #pragma unroll
                for (int mi = 0; mi < 4; mi++) {
                    #pragma unroll
                    for (int sub = 0; sub < 2; sub++) {
                        float* d = acc[mi][njp * 2 + sub];
                        mma_f16(d, ah[mi], &bh4[sub * 2]);
                        mma_f16(d, ah[mi], &bl4[sub * 2]);
                    }
                }
            }
        }
    }

    // ---- epilogue ----
    const float sc = (bn < qcols) ? (SCALE_ * LOG2E_) : 1.0f;
    #pragma unroll
    for (int mi = 0; mi < 4; mi++) {
        #pragma unroll
        for (int nj = 0; nj < 4; nj++) {
            int row = bm + wm + mi * 16 + (lane >> 2);
            int col = bn + wn + nj * 8 + (lane & 3) * 2;
            if (Cf) {
                float b0 = bias ? bias[col] : 0.f;
                float b1 = bias ? bias[col + 1] : 0.f;
                float2 v0 = {acc[mi][nj][0] + b0, acc[mi][nj][1] + b1};
                float2 v1 = {acc[mi][nj][2] + b0, acc[mi][nj][3] + b1};
                *(float2*)(Cf + (size_t)row * N + col) = v0;
                *(float2*)(Cf + (size_t)(row + 8) * N + col) = v1;
            } else {
                half_t h0, l0, h1, l1, h2, l2, h3, l3;
                split_f16(acc[mi][nj][0] * sc, h0, l0);
                split_f16(acc[mi][nj][1] * sc, h1, l1);
                split_f16(acc[mi][nj][2] * sc, h2, l2);
                split_f16(acc[mi][nj][3] * sc, h3, l3);
                *(uint32_t*)(Ch + (size_t)row * N + col)       = pack2h(h0, h1);
                *(uint32_t*)(Ch + (size_t)(row + 8) * N + col) = pack2h(h2, h3);
                *(uint32_t*)(Cl + (size_t)row * N + col)       = pack2h(l0, l1);
                *(uint32_t*)(Cl + (size_t)(row + 8) * N + col) = pack2h(l2, l3);
            }
        }
    }
}

// ===========================================================================
// Flash attention (fp16 tensor cores). One CTA = 128 q rows of one (b,h).
// 8 warps x 16 q rows, kv tiles of 64. Q: 1 plane (pre-scaled by 0.125*log2e).
// K,V: 2 planes each. log2-domain softmax. cp.async KV pipeline. 2 CTAs/SM.
// ===========================================================================
#define FSTR 72
#define FREG  (4 * 64 * FSTR)              // fp16 units per KV region = 18432
#define FLASH_SMEM (2 * FREG * 2)          // 73728 B

__global__ __launch_bounds__(256, 2) void flash_kernel(
    const half_t* __restrict__ qh_g, const half_t* __restrict__ ql_g,
    half_t* __restrict__ outh)
{
    extern __shared__ __align__(16) half_t fsm[];
    const uint32_t baseu = smem_u32(fsm);

    const int tid  = threadIdx.x;
    const int lane = tid & 31;
    const int w    = tid >> 5;
    const int bh   = blockIdx.y;
    const int b    = bh / H_;
    const int h    = bh % H_;
    const int q0   = blockIdx.x * 128;

    const size_t rowbase = (size_t)b * N_ * QKV_N;
    const int qoff = h * DH_;
    const int koff = DIM_ + h * DH_;
    const int voff = 2 * DIM_ + h * DH_;

    // ---- stage Q tile (hi plane only) into region A ----
    #pragma unroll
    for (int i = 0; i < 4; i++) {
        int idx = tid + i * 256;
        int row = idx >> 3, c8 = (idx & 7) * 8;
        size_t g = rowbase + (size_t)(q0 + row) * QKV_N + qoff + c8;
        *(float4*)&fsm[row * FSTR + c8] = *(const float4*)(qh_g + g);
    }
    __syncthreads();

    // KV staging into region reg (fp16-unit offset): planes Kh,Kl,Vh,Vl
    auto stage_kv = [&](int t, uint32_t reg) {
        const int kr0 = t * 64;
        #pragma unroll
        for (int i = 0; i < 8; i++) {
            const int p   = i >> 1;                   // 0:Kh 1:Kl 2:Vh 3:Vl
            const int rem = (i & 1) * 256 + tid;      // 0..511
            const int row = rem >> 3;
            const int c8  = (rem & 7) * 8;
            const size_t g = rowbase + (size_t)(kr0 + row) * QKV_N +
                             ((p < 2) ? koff : voff) + c8;
            const half_t* src = ((p & 1) ? ql_g : qh_g) + g;
            uint32_t dst = baseu + (reg + p * 4608 + row * FSTR + c8) * 2;
            cp_async16(dst, src);
        }
    };

    stage_kv(0, FREG);
    CP_COMMIT();

    // ---- preload Q fragments ----
    uint32_t qh[4][4];
    #pragma unroll
    for (int kb = 0; kb < 4; kb++) {
        uint32_t off = (uint32_t)((w * 16 + (lane & 15)) * (FSTR * 2) +
                                  (kb * 16 + ((lane >> 4) << 3)) * 2);
        ldsm_x4(qh[kb], baseu + off);
    }

    float o[8][4] = {};
    float m0 = -1e30f, m1 = -1e30f, l0 = 0.f, l1 = 0.f;

    for (int t = 0; t < N_ / 64; t++) {
        CP_WAIT0();
        __syncthreads();
        if (t + 1 < N_ / 64) {
            stage_kv(t + 1, ((t + 1) & 1) ? 0u : (uint32_t)FREG);
            CP_COMMIT();
        }

        const uint32_t reg = (t & 1) ? 0u : (uint32_t)FREG;
        const uint32_t uKh = baseu + reg * 2;
        const uint32_t uKl = baseu + (reg + 4608) * 2;
        const uint32_t uVh = baseu + (reg + 9216) * 2;
        const uint32_t uVl = baseu + (reg + 13824) * 2;

        // ---- S = Q @ (Kh + Kl)^T  (log2 domain) ----
        float s[8][4] = {};
        #pragma unroll
        for (int kb = 0; kb < 4; kb++) {
            #pragma unroll
            for (int njp = 0; njp < 4; njp++) {
                uint32_t off = (uint32_t)((njp * 16 + (lane & 7) + ((lane >> 4) << 3)) * (FSTR * 2) +
                                          (kb * 16 + (((lane >> 3) & 1) << 3)) * 2);
                uint32_t kbh[4], kbl[4];
                ldsm_x4(kbh, uKh + off);
                ldsm_x4(kbl, uKl + off);
                #pragma unroll
                for (int sub = 0; sub < 2; sub++) {
                    float* d = s[njp * 2 + sub];
                    mma_f16(d, qh[kb], &kbh[sub * 2]);
                    mma_f16(d, qh[kb], &kbl[sub * 2]);
                }
            }
        }

        // ---- online softmax (base-2) ----
        float mx0 = -1e30f, mx1 = -1e30f;
        #pragma unroll
        for (int nj = 0; nj < 8; nj++) {
            mx0 = fmaxf(mx0, fmaxf(s[nj][0], s[nj][1]));
            mx1 = fmaxf(mx1, fmaxf(s[nj][2], s[nj][3]));
        }
        mx0 = fmaxf(mx0, __shfl_xor_sync(0xffffffffu, mx0, 1));
        mx0 = fmaxf(mx0, __shfl_xor_sync(0xffffffffu, mx0, 2));
        mx1 = fmaxf(mx1, __shfl_xor_sync(0xffffffffu, mx1, 1));
        mx1 = fmaxf(mx1, __shfl_xor_sync(0xffffffffu, mx1, 2));
        float mn0 = fmaxf(m0, mx0), mn1 = fmaxf(m1, mx1);
        float a0 = ex2(m0 - mn0), a1 = ex2(m1 - mn1);
        m0 = mn0; m1 = mn1;

        float sum0 = 0.f, sum1 = 0.f;
        #pragma unroll
        for (int nj = 0; nj < 8; nj++) {
            s[nj][0] = ex2(s[nj][0] - mn0);
            s[nj][1] = ex2(s[nj][1] - mn0);
            s[nj][2] = ex2(s[nj][2] - mn1);
            s[nj][3] = ex2(s[nj][3] - mn1);
            sum0 += s[nj][0] + s[nj][1];
            sum1 += s[nj][2] + s[nj][3];
        }
        sum0 += __shfl_xor_sync(0xffffffffu, sum0, 1);
        sum0 += __shfl_xor_sync(0xffffffffu, sum0, 2);
        sum1 += __shfl_xor_sync(0xffffffffu, sum1, 1);
        sum1 += __shfl_xor_sync(0xffffffffu, sum1, 2);
        l0 = l0 * a0 + sum0;
        l1 = l1 * a1 + sum1;

        #pragma unroll
        for (int dj = 0; dj < 8; dj++) {
            o[dj][0] *= a0; o[dj][1] *= a0;
            o[dj][2] *= a1; o[dj][3] *= a1;
        }

        // ---- P fragments (plain fp16, in-register) ----
        uint32_t pa[4][4];
        #pragma unroll
        for (int kb = 0; kb < 4; kb++) {
            #pragma unroll
            for (int half = 0; half < 2; half++) {
                const float* sc = s[2 * kb + half];
                pa[kb][half * 2 + 0] = packf2h(sc[0], sc[1]);
                pa[kb][half * 2 + 1] = packf2h(sc[2], sc[3]);
            }
        }

        // ---- O += P @ (Vh + Vl) ----
        #pragma unroll
        for (int kb = 0; kb < 4; kb++) {
            #pragma unroll
            for (int djp = 0; djp < 4; djp++) {
                uint32_t off = (uint32_t)((kb * 16 + (lane & 7) + (((lane >> 3) & 1) << 3)) * (FSTR * 2) +
                                          (djp * 16 + ((lane >> 4) << 3)) * 2);
                uint32_t vbh[4], vbl[4];
                ldsm_x4_t(vbh, uVh + off);
                ldsm_x4_t(vbl, uVl + off);
                #pragma unroll
                for (int sub = 0; sub < 2; sub++) {
                    float* d = o[djp * 2 + sub];
                    mma_f16(d, pa[kb], &vbh[sub * 2]);
                    mma_f16(d, pa[kb], &vbl[sub * 2]);
                }
            }
        }
    }

    // ---- normalize + fp16 write (1 plane) ----
    float inv0 = 1.0f / l0, inv1 = 1.0f / l1;
    size_t row0 = (size_t)(b * N_ + q0 + w * 16 + (lane >> 2));
    #pragma unroll
    for (int dj = 0; dj < 8; dj++) {
        int col = h * DH_ + dj * 8 + (lane & 3) * 2;
        *(uint32_t*)(outh + row0 * DIM_ + col) =
            packf2h(o[dj][0] * inv0, o[dj][1] * inv0);
        *(uint32_t*)(outh + (row0 + 8) * DIM_ + col) =
            packf2h(o[dj][2] * inv1, o[dj][3] * inv1);
    }
}

// ---------------------------------------------------------------------------
// Launch
// ---------------------------------------------------------------------------
extern "C" void kernel_launch(void* const* d_in, const int* in_sizes, int n_in,
                              void* d_out, int out_size)
{
    const float* x      = (const float*)d_in[0];
    const float* w_qkv  = (const float*)d_in[1];
    const float* w_proj = (const float*)d_in[2];
    const float* b_proj = (const float*)d_in[3];
    float* out = (float*)d_out;

    half_t *xh, *wqh, *wql, *wph, *wpl, *qkvh, *qkvl, *ah;
    cudaGetSymbolAddress((void**)&xh, g_xh);
    cudaGetSymbolAddress((void**)&wqh, g_wqh);
    cudaGetSymbolAddress((void**)&wql, g_wql);
    cudaGetSymbolAddress((void**)&wph, g_wph);
    cudaGetSymbolAddress((void**)&wpl, g_wpl);
    cudaGetSymbolAddress((void**)&qkvh, g_qkvh);
    cudaGetSymbolAddress((void**)&qkvl, g_qkvl);
    cudaGetSymbolAddress((void**)&ah, g_ah);

    cudaFuncSetAttribute(tgemm_kernel,
                         cudaFuncAttributeMaxDynamicSharedMemorySize, TG_SMEM);
    cudaFuncSetAttribute(flash_kernel,
                         cudaFuncAttributeMaxDynamicSharedMemorySize, FLASH_SMEM);

    // 0) converts
    {
        int n4 = M_TOT * DIM_ / 4;
        conv_f16_kernel<<<(n4 + 255) / 256, 256>>>(x, xh, n4);
        dim3 tb(32, 8);
        transpose_split_kernel<<<dim3(QKV_N / 32, DIM_ / 32), tb>>>(w_qkv, wqh, wql, DIM_, QKV_N);
        transpose_split_kernel<<<dim3(DIM_ / 32, DIM_ / 32), tb>>>(w_proj, wph, wpl, DIM_, DIM_);
    }

    // 1) QKV = X @ Wqkv -> fp16 planes (Q cols scaled by 0.125*log2e)
    dim3 g1(QKV_N / 128, M_TOT / 128);
    tgemm_kernel<<<g1, 256, TG_SMEM>>>(xh, wqh, wql,
                                       nullptr, qkvh, qkvl,
                                       M_TOT, QKV_N, DIM_, nullptr, DIM_);

    // 2) Flash attention
    dim3 g2(N_ / 128, B_ * H_);
    flash_kernel<<<g2, 256, FLASH_SMEM>>>(qkvh, qkvl, ah);

    // 3) OUT = ATTN @ Wproj + bias (fp32)
    dim3 g3(DIM_ / 128, M_TOT / 128);
    tgemm_kernel<<<g3, 256, TG_SMEM>>>(ah, wph, wpl,
                                       out, nullptr, nullptr,
                                       M_TOT, DIM_, DIM_, b_proj, 0);
}

// round 10
// speedup vs baseline: 4.4197x; 1.0482x over previous
#include <cuda_runtime.h>
#include <cuda_fp16.h>
#include <cstdint>

#define B_    4
#define N_    2048
#define DIM_  768
#define H_    12
#define DH_   64
#define M_TOT (B_ * N_)       // 8192
#define QKV_N (3 * DIM_)      // 2304
#define SCALE_ 0.125f
#define LOG2E_ 1.4426950408889634f

typedef __half half_t;

// --------------------------- device scratch (no allocs) --------------------
__device__ half_t g_xh[(size_t)M_TOT * DIM_];     // X fp16 (A operand, 1 plane)
__device__ half_t g_wqh[(size_t)QKV_N * DIM_];    // Wqkv^T hi [2304,768]
__device__ half_t g_wql[(size_t)QKV_N * DIM_];    // Wqkv^T lo
__device__ half_t g_wph[(size_t)DIM_ * DIM_];     // Wproj^T hi
__device__ half_t g_wpl[(size_t)DIM_ * DIM_];     // Wproj^T lo
__device__ half_t g_qkvh[(size_t)M_TOT * QKV_N];  // QKV hi (Q pre-scaled)
__device__ half_t g_qkvl[(size_t)M_TOT * QKV_N];  // QKV lo (K,V used)
__device__ half_t g_ah[(size_t)M_TOT * DIM_];     // attn-out fp16 (1 plane)

// ===========================================================================
// helpers
// ===========================================================================
__device__ __forceinline__ uint32_t smem_u32(const void* p) {
    uint32_t a;
    asm("{ .reg .u64 t; cvta.to.shared.u64 t, %1; cvt.u32.u64 %0, t; }"
        : "=r"(a) : "l"(p));
    return a;
}
__device__ __forceinline__ void ldsm_x4(uint32_t* r, uint32_t addr) {
    asm volatile("ldmatrix.sync.aligned.m8n8.x4.shared.b16 {%0,%1,%2,%3}, [%4];"
                 : "=r"(r[0]), "=r"(r[1]), "=r"(r[2]), "=r"(r[3]) : "r"(addr));
}
__device__ __forceinline__ void ldsm_x4_t(uint32_t* r, uint32_t addr) {
    asm volatile("ldmatrix.sync.aligned.m8n8.x4.trans.shared.b16 {%0,%1,%2,%3}, [%4];"
                 : "=r"(r[0]), "=r"(r[1]), "=r"(r[2]), "=r"(r[3]) : "r"(addr));
}
__device__ __forceinline__ void mma_f16(float* d, const uint32_t* a, const uint32_t* b) {
    asm volatile("mma.sync.aligned.m16n8k16.row.col.f32.f16.f16.f32 "
                 "{%0,%1,%2,%3}, {%4,%5,%6,%7}, {%8,%9}, {%0,%1,%2,%3};"
                 : "+f"(d[0]), "+f"(d[1]), "+f"(d[2]), "+f"(d[3])
                 : "r"(a[0]), "r"(a[1]), "r"(a[2]), "r"(a[3]), "r"(b[0]), "r"(b[1]));
}
__device__ __forceinline__ void split_f16(float x, half_t& h, half_t& l) {
    h = __float2half_rn(x);
    l = __float2half_rn(x - __half2float(h));
}
__device__ __forceinline__ uint32_t pack2h(half_t a, half_t b) {
    __half2 t = __halves2half2(a, b);
    return *reinterpret_cast<uint32_t*>(&t);
}
__device__ __forceinline__ uint32_t packf2h(float a, float b) {
    __half2 t = __floats2half2_rn(a, b);   // .x = a
    return *reinterpret_cast<uint32_t*>(&t);
}
__device__ __forceinline__ float ex2(float x) {
    float y; asm("ex2.approx.f32 %0, %1;" : "=f"(y) : "f"(x)); return y;
}
__device__ __forceinline__ void cp_async16(uint32_t dst, const void* src) {
    asm volatile("cp.async.cg.shared.global [%0], [%1], 16;" :: "r"(dst), "l"(src));
}
#define CP_COMMIT() asm volatile("cp.async.commit_group;" ::: "memory")
#define CP_WAIT0()  asm volatile("cp.async.wait_group 0;" ::: "memory")

// ===========================================================================
// convert kernels
// ===========================================================================
__global__ void conv_f16_kernel(const float* __restrict__ X,
                                half_t* __restrict__ Xh, int n4)
{
    int idx = blockIdx.x * blockDim.x + threadIdx.x;
    if (idx >= n4) return;
    float4 v = ((const float4*)X)[idx];
    ((uint32_t*)Xh)[idx * 2]     = packf2h(v.x, v.y);
    ((uint32_t*)Xh)[idx * 2 + 1] = packf2h(v.z, v.w);
}

// W [K][Nw] fp32 -> Th/Tl [Nw][K] fp16 (transpose + split)
__global__ void transpose_split_kernel(const float* __restrict__ W,
                                       half_t* __restrict__ Th, half_t* __restrict__ Tl,
                                       int K, int Nw)
{
    __shared__ float t[32][33];
    const int n0 = blockIdx.x * 32, k0 = blockIdx.y * 32;
    const int tx = threadIdx.x, ty = threadIdx.y;   // (32, 8)
    #pragma unroll
    for (int i = 0; i < 32; i += 8)
        t[ty + i][tx] = W[(size_t)(k0 + ty + i) * Nw + n0 + tx];
    __syncthreads();
    #pragma unroll
    for (int i = 0; i < 32; i += 8) {
        float v = t[tx][ty + i];
        half_t h, l;
        split_f16(v, h, l);
        Th[(size_t)(n0 + ty + i) * K + k0 + tx] = h;
        Tl[(size_t)(n0 + ty + i) * K + k0 + tx] = l;
    }
}

// ===========================================================================
// tgemm: C[M,N] = A[M,K] @ B^T (B stored [N][K] in 2 fp16 planes; A 1 plane).
// 128x128 block, BK=64, 8 warps of 64x32. cp.async 2-stage pipeline.
// 2 MMAs per k16.  2 CTAs/SM. One __syncthreads per 64-wide chunk.
// ===========================================================================
#define ASTR 72
#define PL   (128 * ASTR)                  // fp16 units per plane = 9216
#define TG_SMEM (2 * 3 * PL * 2)           // 110592 B

__global__ __launch_bounds__(256, 2) void tgemm_kernel(
    const half_t* __restrict__ Aih,
    const half_t* __restrict__ Bih, const half_t* __restrict__ Bil,
    float* __restrict__ Cf, half_t* __restrict__ Ch, half_t* __restrict__ Cl,
    int M, int N, int K, const float* __restrict__ bias, int qcols)
{
    extern __shared__ __align__(16) half_t dsm[];
    const uint32_t base = smem_u32(dsm);

    const int tid  = threadIdx.x;
    const int lane = tid & 31;
    const int wid  = tid >> 5;
    const int wm   = (wid >> 2) * 64;
    const int wn   = (wid & 3) * 32;
    const int bm   = blockIdx.y * 128;
    const int bn   = blockIdx.x * 128;

    const int nc = K / 64;

    // stage 64-wide chunk c into buffer cb (3 planes: A, Bh, Bl)
    auto stage = [&](int c, int cb) {
        const int kc = c * 64;
        #pragma unroll
        for (int i = 0; i < 12; i++) {
            const int p   = i >> 2;                      // 0:A 1:Bh 2:Bl
            const int rem = (i & 3) * 256 + tid;         // 0..1023
            const int row = rem >> 3;
            const int c8  = (rem & 7) * 8;
            const half_t* src;
            if      (p == 0) src = Aih + (size_t)(bm + row) * K + kc + c8;
            else if (p == 1) src = Bih + (size_t)(bn + row) * K + kc + c8;
            else             src = Bil + (size_t)(bn + row) * K + kc + c8;
            uint32_t dst = base + (uint32_t)((cb * 3 + p) * PL + row * ASTR + c8) * 2;
            cp_async16(dst, src);
        }
    };

    float acc[4][4][4] = {};

    stage(0, 0);
    CP_COMMIT();

    // invariant pieces of ldsm addresses
    const uint32_t aoff0 =
        (uint32_t)((wm + (lane & 15)) * (ASTR * 2) + (((lane >> 4) << 3)) * 2);
    const uint32_t boff0 =
        (uint32_t)((wn + (lane & 7) + ((lane >> 4) << 3)) * (ASTR * 2) +
                   ((((lane >> 3) & 1) << 3)) * 2);

    for (int c = 0; c < nc; c++) {
        CP_WAIT0();
        __syncthreads();
        if (c + 1 < nc) {
            stage(c + 1, (c + 1) & 1);
            CP_COMMIT();
        }

        const int cb = c & 1;
        const uint32_t uA  = base + (uint32_t)((cb * 3 + 0) * PL) * 2;
        const uint32_t uBh = base + (uint32_t)((cb * 3 + 1) * PL) * 2;
        const uint32_t uBl = base + (uint32_t)((cb * 3 + 2) * PL) * 2;

        #pragma unroll
        for (int kb = 0; kb < 4; kb++) {
            const uint32_t aoff = aoff0 + kb * 32;      // 16 fp16 per kb
            uint32_t ah[4][4];
            #pragma unroll
            for (int mi = 0; mi < 4; mi++)
                ldsm_x4(ah[mi], uA + aoff + mi * 16 * (ASTR * 2));
            #pragma unroll
            for (int njp = 0; njp < 2; njp++) {
                const uint32_t boff = boff0 + njp * 16 * (ASTR * 2) + kb * 32;
                uint32_t bh4[4], bl4[4];
                ldsm_x4(bh4, uBh + boff);
                ldsm_x4(bl4, uBl + boff);
                #pragma unroll
                for (int mi = 0; mi < 4; mi++) {
                    #pragma unroll
                    for (int sub = 0; sub < 2; sub++) {
                        float* d = acc[mi][njp * 2 + sub];
                        mma_f16(d, ah[mi], &bh4[sub * 2]);
                        mma_f16(d, ah[mi], &bl4[sub * 2]);
                    }
                }
            }
        }
    }

    // ---- epilogue ----
    const float sc = (bn < qcols) ? (SCALE_ * LOG2E_) : 1.0f;
    #pragma unroll
    for (int mi = 0; mi < 4; mi++) {
        #pragma unroll
        for (int nj = 0; nj < 4; nj++) {
            int row = bm + wm + mi * 16 + (lane >> 2);
            int col = bn + wn + nj * 8 + (lane & 3) * 2;
            if (Cf) {
                float b0 = bias ? bias[col] : 0.f;
                float b1 = bias ? bias[col + 1] : 0.f;
                float2 v0 = {acc[mi][nj][0] + b0, acc[mi][nj][1] + b1};
                float2 v1 = {acc[mi][nj][2] + b0, acc[mi][nj][3] + b1};
                *(float2*)(Cf + (size_t)row * N + col) = v0;
                *(float2*)(Cf + (size_t)(row + 8) * N + col) = v1;
            } else {
                half_t h0, l0, h1, l1, h2, l2, h3, l3;
                split_f16(acc[mi][nj][0] * sc, h0, l0);
                split_f16(acc[mi][nj][1] * sc, h1, l1);
                split_f16(acc[mi][nj][2] * sc, h2, l2);
                split_f16(acc[mi][nj][3] * sc, h3, l3);
                *(uint32_t*)(Ch + (size_t)row * N + col)       = pack2h(h0, h1);
                *(uint32_t*)(Ch + (size_t)(row + 8) * N + col) = pack2h(h2, h3);
                *(uint32_t*)(Cl + (size_t)row * N + col)       = pack2h(l0, l1);
                *(uint32_t*)(Cl + (size_t)(row + 8) * N + col) = pack2h(l2, l3);
            }
        }
    }
}

// ===========================================================================
// Flash attention (fp16 tensor cores). One CTA = 128 q rows of one (b,h).
// 8 warps x 16 q rows, kv tiles of 64. Q: 1 plane (pre-scaled by 0.125*log2e).
// K,V: 2 planes each. log2-domain softmax. cp.async KV pipeline. 2 CTAs/SM.
// ===========================================================================
#define FSTR 72
#define FREG  (4 * 64 * FSTR)              // fp16 units per KV region = 18432
#define FLASH_SMEM (2 * FREG * 2)          // 73728 B

__global__ __launch_bounds__(256, 2) void flash_kernel(
    const half_t* __restrict__ qh_g, const half_t* __restrict__ ql_g,
    half_t* __restrict__ outh)
{
    extern __shared__ __align__(16) half_t fsm[];
    const uint32_t baseu = smem_u32(fsm);

    const int tid  = threadIdx.x;
    const int lane = tid & 31;
    const int w    = tid >> 5;
    const int bh   = blockIdx.y;
    const int b    = bh / H_;
    const int h    = bh % H_;
    const int q0   = blockIdx.x * 128;

    const size_t rowbase = (size_t)b * N_ * QKV_N;
    const int qoff = h * DH_;
    const int koff = DIM_ + h * DH_;
    const int voff = 2 * DIM_ + h * DH_;

    // ---- stage Q tile (hi plane only) into region A ----
    #pragma unroll
    for (int i = 0; i < 4; i++) {
        int idx = tid + i * 256;
        int row = idx >> 3, c8 = (idx & 7) * 8;
        size_t g = rowbase + (size_t)(q0 + row) * QKV_N + qoff + c8;
        *(float4*)&fsm[row * FSTR + c8] = *(const float4*)(qh_g + g);
    }
    __syncthreads();

    // KV staging into region reg (fp16-unit offset): planes Kh,Kl,Vh,Vl
    auto stage_kv = [&](int t, uint32_t reg) {
        const int kr0 = t * 64;
        #pragma unroll
        for (int i = 0; i < 8; i++) {
            const int p   = i >> 1;                   // 0:Kh 1:Kl 2:Vh 3:Vl
            const int rem = (i & 1) * 256 + tid;      // 0..511
            const int row = rem >> 3;
            const int c8  = (rem & 7) * 8;
            const size_t g = rowbase + (size_t)(kr0 + row) * QKV_N +
                             ((p < 2) ? koff : voff) + c8;
            const half_t* src = ((p & 1) ? ql_g : qh_g) + g;
            uint32_t dst = baseu + (reg + p * 4608 + row * FSTR + c8) * 2;
            cp_async16(dst, src);
        }
    };

    stage_kv(0, FREG);
    CP_COMMIT();

    // ---- preload Q fragments ----
    uint32_t qh[4][4];
    #pragma unroll
    for (int kb = 0; kb < 4; kb++) {
        uint32_t off = (uint32_t)((w * 16 + (lane & 15)) * (FSTR * 2) +
                                  (kb * 16 + ((lane >> 4) << 3)) * 2);
        ldsm_x4(qh[kb], baseu + off);
    }

    // invariant address parts
    const uint32_t koff0 = (uint32_t)(((lane & 7) + ((lane >> 4) << 3)) * (FSTR * 2) +
                                      ((((lane >> 3) & 1) << 3)) * 2);
    const uint32_t voff0 = (uint32_t)(((lane & 7) + (((lane >> 3) & 1) << 3)) * (FSTR * 2) +
                                      (((lane >> 4) << 3)) * 2);

    float o[8][4] = {};
    float m0 = -1e30f, m1 = -1e30f, l0 = 0.f, l1 = 0.f;

    for (int t = 0; t < N_ / 64; t++) {
        CP_WAIT0();
        __syncthreads();
        if (t + 1 < N_ / 64) {
            stage_kv(t + 1, ((t + 1) & 1) ? 0u : (uint32_t)FREG);
            CP_COMMIT();
        }

        const uint32_t reg = (t & 1) ? 0u : (uint32_t)FREG;
        const uint32_t uKh = baseu + reg * 2;
        const uint32_t uKl = baseu + (reg + 4608) * 2;
        const uint32_t uVh = baseu + (reg + 9216) * 2;
        const uint32_t uVl = baseu + (reg + 13824) * 2;

        // ---- S = Q @ (Kh + Kl)^T  (log2 domain) ----
        float s[8][4] = {};
        #pragma unroll
        for (int kb = 0; kb < 4; kb++) {
            #pragma unroll
            for (int njp = 0; njp < 4; njp++) {
                uint32_t off = koff0 + njp * 16 * (FSTR * 2) + kb * 32;
                uint32_t kbh[4], kbl[4];
                ldsm_x4(kbh, uKh + off);
                ldsm_x4(kbl, uKl + off);
                #pragma unroll
                for (int sub = 0; sub < 2; sub++) {
                    float* d = s[njp * 2 + sub];
                    mma_f16(d, qh[kb], &kbh[sub * 2]);
                    mma_f16(d, qh[kb], &kbl[sub * 2]);
                }
            }
        }

        // ---- online softmax (base-2) ----
        float mx0 = -1e30f, mx1 = -1e30f;
        #pragma unroll
        for (int nj = 0; nj < 8; nj++) {
            mx0 = fmaxf(mx0, fmaxf(s[nj][0], s[nj][1]));
            mx1 = fmaxf(mx1, fmaxf(s[nj][2], s[nj][3]));
        }
        mx0 = fmaxf(mx0, __shfl_xor_sync(0xffffffffu, mx0, 1));
        mx0 = fmaxf(mx0, __shfl_xor_sync(0xffffffffu, mx0, 2));
        mx1 = fmaxf(mx1, __shfl_xor_sync(0xffffffffu, mx1, 1));
        mx1 = fmaxf(mx1, __shfl_xor_sync(0xffffffffu, mx1, 2));
        float mn0 = fmaxf(m0, mx0), mn1 = fmaxf(m1, mx1);
        float a0 = ex2(m0 - mn0), a1 = ex2(m1 - mn1);
        m0 = mn0; m1 = mn1;

        float sum0 = 0.f, sum1 = 0.f;
        #pragma unroll
        for (int nj = 0; nj < 8; nj++) {
            s[nj][0] = ex2(s[nj][0] - mn0);
            s[nj][1] = ex2(s[nj][1] - mn0);
            s[nj][2] = ex2(s[nj][2] - mn1);
            s[nj][3] = ex2(s[nj][3] - mn1);
            sum0 += s[nj][0] + s[nj][1];
            sum1 += s[nj][2] + s[nj][3];
        }
        sum0 += __shfl_xor_sync(0xffffffffu, sum0, 1);
        sum0 += __shfl_xor_sync(0xffffffffu, sum0, 2);
        sum1 += __shfl_xor_sync(0xffffffffu, sum1, 1);
        sum1 += __shfl_xor_sync(0xffffffffu, sum1, 2);
        l0 = l0 * a0 + sum0;
        l1 = l1 * a1 + sum1;

        #pragma unroll
        for (int dj = 0; dj < 8; dj++) {
            o[dj][0] *= a0; o[dj][1] *= a0;
            o[dj][2] *= a1; o[dj][3] *= a1;
        }

        // ---- P fragments (plain fp16, in-register) ----
        uint32_t pa[4][4];
        #pragma unroll
        for (int kb = 0; kb < 4; kb++) {
            #pragma unroll
            for (int half = 0; half < 2; half++) {
                const float* sc = s[2 * kb + half];
                pa[kb][half * 2 + 0] = packf2h(sc[0], sc[1]);
                pa[kb][half * 2 + 1] = packf2h(sc[2], sc[3]);
            }
        }

        // ---- O += P @ (Vh + Vl) ----
        #pragma unroll
        for (int kb = 0; kb < 4; kb++) {
            #pragma unroll
            for (int djp = 0; djp < 4; djp++) {
                uint32_t off = voff0 + kb * 16 * (FSTR * 2) + djp * 32;
                uint32_t vbh[4], vbl[4];
                ldsm_x4_t(vbh, uVh + off);
                ldsm_x4_t(vbl, uVl + off);
                #pragma unroll
                for (int sub = 0; sub < 2; sub++) {
                    float* d = o[djp * 2 + sub];
                    mma_f16(d, pa[kb], &vbh[sub * 2]);
                    mma_f16(d, pa[kb], &vbl[sub * 2]);
                }
            }
        }
    }

    // ---- normalize + fp16 write (1 plane) ----
    float inv0 = 1.0f / l0, inv1 = 1.0f / l1;
    size_t row0 = (size_t)(b * N_ + q0 + w * 16 + (lane >> 2));
    #pragma unroll
    for (int dj = 0; dj < 8; dj++) {
        int col = h * DH_ + dj * 8 + (lane & 3) * 2;
        *(uint32_t*)(outh + row0 * DIM_ + col) =
            packf2h(o[dj][0] * inv0, o[dj][1] * inv0);
        *(uint32_t*)(outh + (row0 + 8) * DIM_ + col) =
            packf2h(o[dj][2] * inv1, o[dj][3] * inv1);
    }
}

// ---------------------------------------------------------------------------
// Launch
// ---------------------------------------------------------------------------
extern "C" void kernel_launch(void* const* d_in, const int* in_sizes, int n_in,
                              void* d_out, int out_size)
{
    const float* x      = (const float*)d_in[0];
    const float* w_qkv  = (const float*)d_in[1];
    const float* w_proj = (const float*)d_in[2];
    const float* b_proj = (const float*)d_in[3];
    float* out = (float*)d_out;

    half_t *xh, *wqh, *wql, *wph, *wpl, *qkvh, *qkvl, *ah;
    cudaGetSymbolAddress((void**)&xh, g_xh);
    cudaGetSymbolAddress((void**)&wqh, g_wqh);
    cudaGetSymbolAddress((void**)&wql, g_wql);
    cudaGetSymbolAddress((void**)&wph, g_wph);
    cudaGetSymbolAddress((void**)&wpl, g_wpl);
    cudaGetSymbolAddress((void**)&qkvh, g_qkvh);
    cudaGetSymbolAddress((void**)&qkvl, g_qkvl);
    cudaGetSymbolAddress((void**)&ah, g_ah);

    cudaFuncSetAttribute(tgemm_kernel,
                         cudaFuncAttributeMaxDynamicSharedMemorySize, TG_SMEM);
    cudaFuncSetAttribute(flash_kernel,
                         cudaFuncAttributeMaxDynamicSharedMemorySize, FLASH_SMEM);

    // 0) converts
    {
        int n4 = M_TOT * DIM_ / 4;
        conv_f16_kernel<<<(n4 + 255) / 256, 256>>>(x, xh, n4);
        dim3 tb(32, 8);
        transpose_split_kernel<<<dim3(QKV_N / 32, DIM_ / 32), tb>>>(w_qkv, wqh, wql, DIM_, QKV_N);
        transpose_split_kernel<<<dim3(DIM_ / 32, DIM_ / 32), tb>>>(w_proj, wph, wpl, DIM_, DIM_);
    }

    // 1) QKV = X @ Wqkv -> fp16 planes (Q cols scaled by 0.125*log2e)
    dim3 g1(QKV_N / 128, M_TOT / 128);
    tgemm_kernel<<<g1, 256, TG_SMEM>>>(xh, wqh, wql,
                                       nullptr, qkvh, qkvl,
                                       M_TOT, QKV_N, DIM_, nullptr, DIM_);

    // 2) Flash attention
    dim3 g2(N_ / 128, B_ * H_);
    flash_kernel<<<g2, 256, FLASH_SMEM>>>(qkvh, qkvl, ah);

    // 3) OUT = ATTN @ Wproj + bias (fp32)
    dim3 g3(DIM_ / 128, M_TOT / 128);
    tgemm_kernel<<<g3, 256, TG_SMEM>>>(ah, wph, wpl,
                                       out, nullptr, nullptr,
                                       M_TOT, DIM_, DIM_, b_proj, 0);
}

// round 11
// speedup vs baseline: 4.4994x; 1.0180x over previous
#include <cuda_runtime.h>
#include <cuda_fp16.h>
#include <cstdint>

#define B_    4
#define N_    2048
#define DIM_  768
#define H_    12
#define DH_   64
#define M_TOT (B_ * N_)       // 8192
#define QKV_N (3 * DIM_)      // 2304
#define SCALE_ 0.125f
#define LOG2E_ 1.4426950408889634f

typedef __half half_t;

// --------------------------- device scratch (no allocs) --------------------
__device__ half_t g_xh[(size_t)M_TOT * DIM_];     // X fp16 (A operand, 1 plane)
__device__ half_t g_wqh[(size_t)QKV_N * DIM_];    // Wqkv^T hi [2304,768]
__device__ half_t g_wql[(size_t)QKV_N * DIM_];    // Wqkv^T lo
__device__ half_t g_wph[(size_t)DIM_ * DIM_];     // Wproj^T hi
__device__ half_t g_wpl[(size_t)DIM_ * DIM_];     // Wproj^T lo
__device__ half_t g_qkvh[(size_t)M_TOT * QKV_N];  // QKV hi (Q pre-scaled)
__device__ half_t g_qkvl[(size_t)M_TOT * QKV_N];  // QKV lo (K,V used)
__device__ half_t g_ah[(size_t)M_TOT * DIM_];     // attn-out fp16 (1 plane)

// ===========================================================================
// helpers
// ===========================================================================
__device__ __forceinline__ uint32_t smem_u32(const void* p) {
    uint32_t a;
    asm("{ .reg .u64 t; cvta.to.shared.u64 t, %1; cvt.u32.u64 %0, t; }"
        : "=r"(a) : "l"(p));
    return a;
}
__device__ __forceinline__ void ldsm_x4(uint32_t* r, uint32_t addr) {
    asm volatile("ldmatrix.sync.aligned.m8n8.x4.shared.b16 {%0,%1,%2,%3}, [%4];"
                 : "=r"(r[0]), "=r"(r[1]), "=r"(r[2]), "=r"(r[3]) : "r"(addr));
}
__device__ __forceinline__ void ldsm_x4_t(uint32_t* r, uint32_t addr) {
    asm volatile("ldmatrix.sync.aligned.m8n8.x4.trans.shared.b16 {%0,%1,%2,%3}, [%4];"
                 : "=r"(r[0]), "=r"(r[1]), "=r"(r[2]), "=r"(r[3]) : "r"(addr));
}
__device__ __forceinline__ void mma_f16(float* d, const uint32_t* a, const uint32_t* b) {
    asm volatile("mma.sync.aligned.m16n8k16.row.col.f32.f16.f16.f32 "
                 "{%0,%1,%2,%3}, {%4,%5,%6,%7}, {%8,%9}, {%0,%1,%2,%3};"
                 : "+f"(d[0]), "+f"(d[1]), "+f"(d[2]), "+f"(d[3])
                 : "r"(a[0]), "r"(a[1]), "r"(a[2]), "r"(a[3]), "r"(b[0]), "r"(b[1]));
}
__device__ __forceinline__ void split_f16(float x, half_t& h, half_t& l) {
    h = __float2half_rn(x);
    l = __float2half_rn(x - __half2float(h));
}
__device__ __forceinline__ uint32_t pack2h(half_t a, half_t b) {
    __half2 t = __halves2half2(a, b);
    return *reinterpret_cast<uint32_t*>(&t);
}
__device__ __forceinline__ uint32_t packf2h(float a, float b) {
    __half2 t = __floats2half2_rn(a, b);   // .x = a
    return *reinterpret_cast<uint32_t*>(&t);
}
__device__ __forceinline__ float ex2(float x) {
    float y; asm("ex2.approx.f32 %0, %1;" : "=f"(y) : "f"(x)); return y;
}
__device__ __forceinline__ uint32_t ex2_h2(uint32_t x) {
    uint32_t y; asm("ex2.approx.f16x2 %0, %1;" : "=r"(y) : "r"(x)); return y;
}
__device__ __forceinline__ void cp_async16(uint32_t dst, const void* src) {
    asm volatile("cp.async.cg.shared.global [%0], [%1], 16;" :: "r"(dst), "l"(src));
}
#define CP_COMMIT() asm volatile("cp.async.commit_group;" ::: "memory")
#define CP_WAIT0()  asm volatile("cp.async.wait_group 0;" ::: "memory")
#define CP_WAIT1()  asm volatile("cp.async.wait_group 1;" ::: "memory")

// ===========================================================================
// convert kernels
// ===========================================================================
__global__ void conv_f16_kernel(const float* __restrict__ X,
                                half_t* __restrict__ Xh, int n4)
{
    int idx = blockIdx.x * blockDim.x + threadIdx.x;
    if (idx >= n4) return;
    float4 v = ((const float4*)X)[idx];
    ((uint32_t*)Xh)[idx * 2]     = packf2h(v.x, v.y);
    ((uint32_t*)Xh)[idx * 2 + 1] = packf2h(v.z, v.w);
}

// W [K][Nw] fp32 -> Th/Tl [Nw][K] fp16 (transpose + split)
__global__ void transpose_split_kernel(const float* __restrict__ W,
                                       half_t* __restrict__ Th, half_t* __restrict__ Tl,
                                       int K, int Nw)
{
    __shared__ float t[32][33];
    const int n0 = blockIdx.x * 32, k0 = blockIdx.y * 32;
    const int tx = threadIdx.x, ty = threadIdx.y;   // (32, 8)
    #pragma unroll
    for (int i = 0; i < 32; i += 8)
        t[ty + i][tx] = W[(size_t)(k0 + ty + i) * Nw + n0 + tx];
    __syncthreads();
    #pragma unroll
    for (int i = 0; i < 32; i += 8) {
        float v = t[tx][ty + i];
        half_t h, l;
        split_f16(v, h, l);
        Th[(size_t)(n0 + ty + i) * K + k0 + tx] = h;
        Tl[(size_t)(n0 + ty + i) * K + k0 + tx] = l;
    }
}

// ===========================================================================
// tgemm: C[M,N] = A[M,K] @ B^T (B stored [N][K] in 2 fp16 planes; A 1 plane).
// 128x128 block, BK=64, 8 warps of 64x32. cp.async 2-stage pipeline.
// 2 MMAs per k16.  2 CTAs/SM. One __syncthreads per 64-wide chunk.
// ===========================================================================
#define ASTR 72
#define PL   (128 * ASTR)                  // fp16 units per plane = 9216
#define TG_SMEM (2 * 3 * PL * 2)           // 110592 B

__global__ __launch_bounds__(256, 2) void tgemm_kernel(
    const half_t* __restrict__ Aih,
    const half_t* __restrict__ Bih, const half_t* __restrict__ Bil,
    float* __restrict__ Cf, half_t* __restrict__ Ch, half_t* __restrict__ Cl,
    int M, int N, int K, const float* __restrict__ bias, int qcols)
{
    extern __shared__ __align__(16) half_t dsm[];
    const uint32_t base = smem_u32(dsm);

    const int tid  = threadIdx.x;
    const int lane = tid & 31;
    const int wid  = tid >> 5;
    const int wm   = (wid >> 2) * 64;
    const int wn   = (wid & 3) * 32;
    const int bm   = blockIdx.y * 128;
    const int bn   = blockIdx.x * 128;

    const int nc = K / 64;

    // stage 64-wide chunk c into buffer cb (3 planes: A, Bh, Bl)
    auto stage = [&](int c, int cb) {
        const int kc = c * 64;
        #pragma unroll
        for (int i = 0; i < 12; i++) {
            const int p   = i >> 2;                      // 0:A 1:Bh 2:Bl
            const int rem = (i & 3) * 256 + tid;         // 0..1023
            const int row = rem >> 3;
            const int c8  = (rem & 7) * 8;
            const half_t* src;
            if      (p == 0) src = Aih + (size_t)(bm + row) * K + kc + c8;
            else if (p == 1) src = Bih + (size_t)(bn + row) * K + kc + c8;
            else             src = Bil + (size_t)(bn + row) * K + kc + c8;
            uint32_t dst = base + (uint32_t)((cb * 3 + p) * PL + row * ASTR + c8) * 2;
            cp_async16(dst, src);
        }
    };

    float acc[4][4][4] = {};

    stage(0, 0);
    CP_COMMIT();

    // invariant pieces of ldsm addresses
    const uint32_t aoff0 =
        (uint32_t)((wm + (lane & 15)) * (ASTR * 2) + (((lane >> 4) << 3)) * 2);
    const uint32_t boff0 =
        (uint32_t)((wn + (lane & 7) + ((lane >> 4) << 3)) * (ASTR * 2) +
                   ((((lane >> 3) & 1) << 3)) * 2);

    for (int c = 0; c < nc; c++) {
        CP_WAIT0();
        __syncthreads();
        if (c + 1 < nc) {
            stage(c + 1, (c + 1) & 1);
            CP_COMMIT();
        }

        const int cb = c & 1;
        const uint32_t uA  = base + (uint32_t)((cb * 3 + 0) * PL) * 2;
        const uint32_t uBh = base + (uint32_t)((cb * 3 + 1) * PL) * 2;
        const uint32_t uBl = base + (uint32_t)((cb * 3 + 2) * PL) * 2;

        #pragma unroll
        for (int kb = 0; kb < 4; kb++) {
            const uint32_t aoff = aoff0 + kb * 32;      // 16 fp16 per kb
            uint32_t ah[4][4];
            #pragma unroll
            for (int mi = 0; mi < 4; mi++)
                ldsm_x4(ah[mi], uA + aoff + mi * 16 * (ASTR * 2));
            #pragma unroll
            for (int njp = 0; njp < 2; njp++) {
                const uint32_t boff = boff0 + njp * 16 * (ASTR * 2) + kb * 32;
                uint32_t bh4[4], bl4[4];
                ldsm_x4(bh4, uBh + boff);
                ldsm_x4(bl4, uBl + boff);
                #pragma unroll
                for (int mi = 0; mi < 4; mi++) {
                    #pragma unroll
                    for (int sub = 0; sub < 2; sub++) {
                        float* d = acc[mi][njp * 2 + sub];
                        mma_f16(d, ah[mi], &bh4[sub * 2]);
                        mma_f16(d, ah[mi], &bl4[sub * 2]);
                    }
                }
            }
        }
    }

    // ---- epilogue ----
    const float sc = (bn < qcols) ? (SCALE_ * LOG2E_) : 1.0f;
    #pragma unroll
    for (int mi = 0; mi < 4; mi++) {
        #pragma unroll
        for (int nj = 0; nj < 4; nj++) {
            int row = bm + wm + mi * 16 + (lane >> 2);
            int col = bn + wn + nj * 8 + (lane & 3) * 2;
            if (Cf) {
                float b0 = bias ? bias[col] : 0.f;
                float b1 = bias ? bias[col + 1] : 0.f;
                float2 v0 = {acc[mi][nj][0] + b0, acc[mi][nj][1] + b1};
                float2 v1 = {acc[mi][nj][2] + b0, acc[mi][nj][3] + b1};
                *(float2*)(Cf + (size_t)row * N + col) = v0;
                *(float2*)(Cf + (size_t)(row + 8) * N + col) = v1;
            } else {
                half_t h0, l0, h1, l1, h2, l2, h3, l3;
                split_f16(acc[mi][nj][0] * sc, h0, l0);
                split_f16(acc[mi][nj][1] * sc, h1, l1);
                split_f16(acc[mi][nj][2] * sc, h2, l2);
                split_f16(acc[mi][nj][3] * sc, h3, l3);
                *(uint32_t*)(Ch + (size_t)row * N + col)       = pack2h(h0, h1);
                *(uint32_t*)(Ch + (size_t)(row + 8) * N + col) = pack2h(h2, h3);
                *(uint32_t*)(Cl + (size_t)row * N + col)       = pack2h(l0, l1);
                *(uint32_t*)(Cl + (size_t)(row + 8) * N + col) = pack2h(l2, l3);
            }
        }
    }
}

// ===========================================================================
// Flash attention (fp16 tensor cores). One CTA = 128 q rows of one (b,h).
// 8 warps x 16 q rows, kv tiles of 64. Q: 1 plane (pre-scaled by 0.125*log2e).
// K,V: 2 planes each. fp16x2 ex2 softmax; row-sum l via ones-MMA.
// 3-region cp.async ring (prefetch distance 2). 2 CTAs/SM.
// ===========================================================================
#define FSTR 72
#define FREG  (4 * 64 * FSTR)              // fp16 units per KV region = 18432
#define FLASH_SMEM (3 * FREG * 2)          // 110592 B

__global__ __launch_bounds__(256, 2) void flash_kernel(
    const half_t* __restrict__ qh_g, const half_t* __restrict__ ql_g,
    half_t* __restrict__ outh)
{
    extern __shared__ __align__(16) half_t fsm[];
    const uint32_t baseu = smem_u32(fsm);

    const int tid  = threadIdx.x;
    const int lane = tid & 31;
    const int w    = tid >> 5;
    const int bh   = blockIdx.y;
    const int b    = bh / H_;
    const int h    = bh % H_;
    const int q0   = blockIdx.x * 128;

    const size_t rowbase = (size_t)b * N_ * QKV_N;
    const int qoff = h * DH_;
    const int koff = DIM_ + h * DH_;
    const int voff = 2 * DIM_ + h * DH_;

    const int NT = N_ / 64;   // 32 kv tiles

    // KV staging into region base offset reg (fp16 units): planes Kh,Kl,Vh,Vl
    auto stage_kv = [&](int t, uint32_t reg) {
        const int kr0 = t * 64;
        #pragma unroll
        for (int i = 0; i < 8; i++) {
            const int p   = i >> 1;                   // 0:Kh 1:Kl 2:Vh 3:Vl
            const int rem = (i & 1) * 256 + tid;      // 0..511
            const int row = rem >> 3;
            const int c8  = (rem & 7) * 8;
            const size_t g = rowbase + (size_t)(kr0 + row) * QKV_N +
                             ((p < 2) ? koff : voff) + c8;
            const half_t* src = ((p & 1) ? ql_g : qh_g) + g;
            uint32_t dst = baseu + (reg + p * 4608 + row * FSTR + c8) * 2;
            cp_async16(dst, src);
        }
    };

    // prefetch tiles 0 and 1 into regions 0, 1
    stage_kv(0, 0);
    CP_COMMIT();
    stage_kv(1, FREG);
    CP_COMMIT();

    // ---- stage Q tile (hi plane only) into region 2 (plain stores) ----
    #pragma unroll
    for (int i = 0; i < 4; i++) {
        int idx = tid + i * 256;
        int row = idx >> 3, c8 = (idx & 7) * 8;
        size_t g = rowbase + (size_t)(q0 + row) * QKV_N + qoff + c8;
        *(float4*)&fsm[2 * FREG + row * FSTR + c8] = *(const float4*)(qh_g + g);
    }
    __syncthreads();

    // ---- preload Q fragments from region 2 ----
    uint32_t qh[4][4];
    #pragma unroll
    for (int kb = 0; kb < 4; kb++) {
        uint32_t off = (uint32_t)((w * 16 + (lane & 15)) * (FSTR * 2) +
                                  (kb * 16 + ((lane >> 4) << 3)) * 2);
        ldsm_x4(qh[kb], baseu + 2 * FREG * 2 + off);
    }

    // invariant address parts
    const uint32_t koff0 = (uint32_t)(((lane & 7) + ((lane >> 4) << 3)) * (FSTR * 2) +
                                      ((((lane >> 3) & 1) << 3)) * 2);
    const uint32_t voff0 = (uint32_t)(((lane & 7) + (((lane >> 3) & 1) << 3)) * (FSTR * 2) +
                                      (((lane >> 4) << 3)) * 2);
    const uint32_t ones2[2] = {0x3C003C00u, 0x3C003C00u};

    float o[8][4] = {};
    float m0 = -1e30f, m1 = -1e30f, l0 = 0.f, l1 = 0.f;

    int region = 0;   // region index of tile t (cycles 0,1,2)

    for (int t = 0; t < NT; t++) {
        if (t < NT - 1) { CP_WAIT1(); } else { CP_WAIT0(); }
        __syncthreads();
        if (t + 2 < NT) {
            int r2 = region + 2; if (r2 >= 3) r2 -= 3;
            stage_kv(t + 2, (uint32_t)r2 * FREG);
            CP_COMMIT();
        }

        const uint32_t reg = (uint32_t)region * FREG;
        const uint32_t uKh = baseu + reg * 2;
        const uint32_t uKl = baseu + (reg + 4608) * 2;
        const uint32_t uVh = baseu + (reg + 9216) * 2;
        const uint32_t uVl = baseu + (reg + 13824) * 2;

        // ---- S = Q @ (Kh + Kl)^T  (log2 domain) ----
        float s[8][4] = {};
        #pragma unroll
        for (int kb = 0; kb < 4; kb++) {
            #pragma unroll
            for (int njp = 0; njp < 4; njp++) {
                uint32_t off = koff0 + njp * 16 * (FSTR * 2) + kb * 32;
                uint32_t kbh[4], kbl[4];
                ldsm_x4(kbh, uKh + off);
                ldsm_x4(kbl, uKl + off);
                #pragma unroll
                for (int sub = 0; sub < 2; sub++) {
                    float* d = s[njp * 2 + sub];
                    mma_f16(d, qh[kb], &kbh[sub * 2]);
                    mma_f16(d, qh[kb], &kbl[sub * 2]);
                }
            }
        }

        // ---- online softmax (base-2): max reduction in fp32 ----
        float mx0 = -1e30f, mx1 = -1e30f;
        #pragma unroll
        for (int nj = 0; nj < 8; nj++) {
            mx0 = fmaxf(mx0, fmaxf(s[nj][0], s[nj][1]));
            mx1 = fmaxf(mx1, fmaxf(s[nj][2], s[nj][3]));
        }
        mx0 = fmaxf(mx0, __shfl_xor_sync(0xffffffffu, mx0, 1));
        mx0 = fmaxf(mx0, __shfl_xor_sync(0xffffffffu, mx0, 2));
        mx1 = fmaxf(mx1, __shfl_xor_sync(0xffffffffu, mx1, 1));
        mx1 = fmaxf(mx1, __shfl_xor_sync(0xffffffffu, mx1, 2));
        float mn0 = fmaxf(m0, mx0), mn1 = fmaxf(m1, mx1);
        float a0 = ex2(m0 - mn0), a1 = ex2(m1 - mn1);
        m0 = mn0; m1 = mn1;

        // ---- P = exp2(s - m) directly in fp16x2 (P fragments) ----
        uint32_t pa[4][4];
        #pragma unroll
        for (int kb = 0; kb < 4; kb++) {
            #pragma unroll
            for (int hf = 0; hf < 2; hf++) {
                const float* sc = s[2 * kb + hf];
                pa[kb][hf * 2 + 0] = ex2_h2(packf2h(sc[0] - mn0, sc[1] - mn0));
                pa[kb][hf * 2 + 1] = ex2_h2(packf2h(sc[2] - mn1, sc[3] - mn1));
            }
        }

        // ---- row sums l via ones-MMA (exact fp32 sum of the fp16 P) ----
        float lacc[4] = {0.f, 0.f, 0.f, 0.f};
        #pragma unroll
        for (int kb = 0; kb < 4; kb++)
            mma_f16(lacc, pa[kb], ones2);
        l0 = l0 * a0 + lacc[0];
        l1 = l1 * a1 + lacc[2];

        #pragma unroll
        for (int dj = 0; dj < 8; dj++) {
            o[dj][0] *= a0; o[dj][1] *= a0;
            o[dj][2] *= a1; o[dj][3] *= a1;
        }

        // ---- O += P @ (Vh + Vl) ----
        #pragma unroll
        for (int kb = 0; kb < 4; kb++) {
            #pragma unroll
            for (int djp = 0; djp < 4; djp++) {
                uint32_t off = voff0 + kb * 16 * (FSTR * 2) + djp * 32;
                uint32_t vbh[4], vbl[4];
                ldsm_x4_t(vbh, uVh + off);
                ldsm_x4_t(vbl, uVl + off);
                #pragma unroll
                for (int sub = 0; sub < 2; sub++) {
                    float* d = o[djp * 2 + sub];
                    mma_f16(d, pa[kb], &vbh[sub * 2]);
                    mma_f16(d, pa[kb], &vbl[sub * 2]);
                }
            }
        }

        region++; if (region >= 3) region = 0;
    }

    // ---- normalize + fp16 write (1 plane) ----
    float inv0 = 1.0f / l0, inv1 = 1.0f / l1;
    size_t row0 = (size_t)(b * N_ + q0 + w * 16 + (lane >> 2));
    #pragma unroll
    for (int dj = 0; dj < 8; dj++) {
        int col = h * DH_ + dj * 8 + (lane & 3) * 2;
        *(uint32_t*)(outh + row0 * DIM_ + col) =
            packf2h(o[dj][0] * inv0, o[dj][1] * inv0);
        *(uint32_t*)(outh + (row0 + 8) * DIM_ + col) =
            packf2h(o[dj][2] * inv1, o[dj][3] * inv1);
    }
}

// ---------------------------------------------------------------------------
// Launch
// ---------------------------------------------------------------------------
extern "C" void kernel_launch(void* const* d_in, const int* in_sizes, int n_in,
                              void* d_out, int out_size)
{
    const float* x      = (const float*)d_in[0];
    const float* w_qkv  = (const float*)d_in[1];
    const float* w_proj = (const float*)d_in[2];
    const float* b_proj = (const float*)d_in[3];
    float* out = (float*)d_out;

    half_t *xh, *wqh, *wql, *wph, *wpl, *qkvh, *qkvl, *ah;
    cudaGetSymbolAddress((void**)&xh, g_xh);
    cudaGetSymbolAddress((void**)&wqh, g_wqh);
    cudaGetSymbolAddress((void**)&wql, g_wql);
    cudaGetSymbolAddress((void**)&wph, g_wph);
    cudaGetSymbolAddress((void**)&wpl, g_wpl);
    cudaGetSymbolAddress((void**)&qkvh, g_qkvh);
    cudaGetSymbolAddress((void**)&qkvl, g_qkvl);
    cudaGetSymbolAddress((void**)&ah, g_ah);

    cudaFuncSetAttribute(tgemm_kernel,
                         cudaFuncAttributeMaxDynamicSharedMemorySize, TG_SMEM);
    cudaFuncSetAttribute(flash_kernel,
                         cudaFuncAttributeMaxDynamicSharedMemorySize, FLASH_SMEM);

    // 0) converts
    {
        int n4 = M_TOT * DIM_ / 4;
        conv_f16_kernel<<<(n4 + 255) / 256, 256>>>(x, xh, n4);
        dim3 tb(32, 8);
        transpose_split_kernel<<<dim3(QKV_N / 32, DIM_ / 32), tb>>>(w_qkv, wqh, wql, DIM_, QKV_N);
        transpose_split_kernel<<<dim3(DIM_ / 32, DIM_ / 32), tb>>>(w_proj, wph, wpl, DIM_, DIM_);
    }

    // 1) QKV = X @ Wqkv -> fp16 planes (Q cols scaled by 0.125*log2e)
    dim3 g1(QKV_N / 128, M_TOT / 128);
    tgemm_kernel<<<g1, 256, TG_SMEM>>>(xh, wqh, wql,
                                       nullptr, qkvh, qkvl,
                                       M_TOT, QKV_N, DIM_, nullptr, DIM_);

    // 2) Flash attention
    dim3 g2(N_ / 128, B_ * H_);
    flash_kernel<<<g2, 256, FLASH_SMEM>>>(qkvh, qkvl, ah);

    // 3) OUT = ATTN @ Wproj + bias (fp32)
    dim3 g3(DIM_ / 128, M_TOT / 128);
    tgemm_kernel<<<g3, 256, TG_SMEM>>>(ah, wph, wpl,
                                       out, nullptr, nullptr,
                                       M_TOT, DIM_, DIM_, b_proj, 0);
}

// round 12
// speedup vs baseline: 5.3514x; 1.1894x over previous
#include <cuda_runtime.h>
#include <cuda_fp16.h>
#include <cstdint>

#define B_    4
#define N_    2048
#define DIM_  768
#define H_    12
#define DH_   64
#define M_TOT (B_ * N_)       // 8192
#define QKV_N (3 * DIM_)      // 2304
#define SCALE_ 0.125f
#define LOG2E_ 1.4426950408889634f

typedef __half half_t;

// --------------------------- device scratch (no allocs) --------------------
__device__ half_t g_xh[(size_t)M_TOT * DIM_];     // X fp16 (A operand, 1 plane)
__device__ half_t g_wqh[(size_t)QKV_N * DIM_];    // Wqkv^T hi [2304,768]
__device__ half_t g_wql[(size_t)QKV_N * DIM_];    // Wqkv^T lo
__device__ half_t g_wph[(size_t)DIM_ * DIM_];     // Wproj^T hi (lo dropped)
__device__ half_t g_qkvh[(size_t)M_TOT * QKV_N];  // QKV hi (Q pre-scaled)
__device__ half_t g_qkvl[(size_t)M_TOT * QKV_N];  // QKV lo (K used; V hi only)
__device__ half_t g_ah[(size_t)M_TOT * DIM_];     // attn-out fp16 (1 plane)

// ===========================================================================
// helpers
// ===========================================================================
__device__ __forceinline__ uint32_t smem_u32(const void* p) {
    uint32_t a;
    asm("{ .reg .u64 t; cvta.to.shared.u64 t, %1; cvt.u32.u64 %0, t; }"
        : "=r"(a) : "l"(p));
    return a;
}
__device__ __forceinline__ void ldsm_x4(uint32_t* r, uint32_t addr) {
    asm volatile("ldmatrix.sync.aligned.m8n8.x4.shared.b16 {%0,%1,%2,%3}, [%4];"
                 : "=r"(r[0]), "=r"(r[1]), "=r"(r[2]), "=r"(r[3]) : "r"(addr));
}
__device__ __forceinline__ void ldsm_x4_t(uint32_t* r, uint32_t addr) {
    asm volatile("ldmatrix.sync.aligned.m8n8.x4.trans.shared.b16 {%0,%1,%2,%3}, [%4];"
                 : "=r"(r[0]), "=r"(r[1]), "=r"(r[2]), "=r"(r[3]) : "r"(addr));
}
__device__ __forceinline__ void mma_f16(float* d, const uint32_t* a, const uint32_t* b) {
    asm volatile("mma.sync.aligned.m16n8k16.row.col.f32.f16.f16.f32 "
                 "{%0,%1,%2,%3}, {%4,%5,%6,%7}, {%8,%9}, {%0,%1,%2,%3};"
                 : "+f"(d[0]), "+f"(d[1]), "+f"(d[2]), "+f"(d[3])
                 : "r"(a[0]), "r"(a[1]), "r"(a[2]), "r"(a[3]), "r"(b[0]), "r"(b[1]));
}
__device__ __forceinline__ void split_f16(float x, half_t& h, half_t& l) {
    h = __float2half_rn(x);
    l = __float2half_rn(x - __half2float(h));
}
__device__ __forceinline__ uint32_t pack2h(half_t a, half_t b) {
    __half2 t = __halves2half2(a, b);
    return *reinterpret_cast<uint32_t*>(&t);
}
__device__ __forceinline__ uint32_t packf2h(float a, float b) {
    __half2 t = __floats2half2_rn(a, b);   // .x = a
    return *reinterpret_cast<uint32_t*>(&t);
}
__device__ __forceinline__ float ex2(float x) {
    float y; asm("ex2.approx.f32 %0, %1;" : "=f"(y) : "f"(x)); return y;
}
__device__ __forceinline__ uint32_t ex2_h2(uint32_t x) {
    uint32_t y; asm("ex2.approx.f16x2 %0, %1;" : "=r"(y) : "r"(x)); return y;
}
__device__ __forceinline__ void cp_async16(uint32_t dst, const void* src) {
    asm volatile("cp.async.cg.shared.global [%0], [%1], 16;" :: "r"(dst), "l"(src));
}
#define CP_COMMIT() asm volatile("cp.async.commit_group;" ::: "memory")
#define CP_WAIT0()  asm volatile("cp.async.wait_group 0;" ::: "memory")
#define CP_WAIT1()  asm volatile("cp.async.wait_group 1;" ::: "memory")

// ===========================================================================
// convert kernels
// ===========================================================================
__global__ void conv_f16_kernel(const float* __restrict__ X,
                                half_t* __restrict__ Xh, int n4)
{
    int idx = blockIdx.x * blockDim.x + threadIdx.x;
    if (idx >= n4) return;
    float4 v = ((const float4*)X)[idx];
    ((uint32_t*)Xh)[idx * 2]     = packf2h(v.x, v.y);
    ((uint32_t*)Xh)[idx * 2 + 1] = packf2h(v.z, v.w);
}

// W [K][Nw] fp32 -> Th (+optional Tl) [Nw][K] fp16 (transpose + split)
__global__ void transpose_split_kernel(const float* __restrict__ W,
                                       half_t* __restrict__ Th, half_t* __restrict__ Tl,
                                       int K, int Nw)
{
    __shared__ float t[32][33];
    const int n0 = blockIdx.x * 32, k0 = blockIdx.y * 32;
    const int tx = threadIdx.x, ty = threadIdx.y;   // (32, 8)
    #pragma unroll
    for (int i = 0; i < 32; i += 8)
        t[ty + i][tx] = W[(size_t)(k0 + ty + i) * Nw + n0 + tx];
    __syncthreads();
    #pragma unroll
    for (int i = 0; i < 32; i += 8) {
        float v = t[tx][ty + i];
        half_t h, l;
        split_f16(v, h, l);
        Th[(size_t)(n0 + ty + i) * K + k0 + tx] = h;
        if (Tl) Tl[(size_t)(n0 + ty + i) * K + k0 + tx] = l;
    }
}

// ===========================================================================
// tgemm<PLANES>: C[M,N] = A[M,K] @ B^T (B stored [N][K] in PLANES fp16 planes;
// A 1 plane). 128x128 block, BK=64, 8 warps of 64x32. cp.async 2-stage
// pipeline, (1+PLANES) planes per buffer. 2 CTAs/SM.
// ===========================================================================
#define ASTR 72
#define PL   (128 * ASTR)                  // fp16 units per plane = 9216
#define TG_SMEM2 (2 * 3 * PL * 2)          // 110592 B (PLANES=2)
#define TG_SMEM1 (2 * 2 * PL * 2)          // 73728 B  (PLANES=1)

template <int PLANES>
__global__ __launch_bounds__(256, 2) void tgemm_kernel(
    const half_t* __restrict__ Aih,
    const half_t* __restrict__ Bih, const half_t* __restrict__ Bil,
    float* __restrict__ Cf, half_t* __restrict__ Ch, half_t* __restrict__ Cl,
    int M, int N, int K, const float* __restrict__ bias, int qcols)
{
    constexpr int PPB = 1 + PLANES;        // planes per buffer
    extern __shared__ __align__(16) half_t dsm[];
    const uint32_t base = smem_u32(dsm);

    const int tid  = threadIdx.x;
    const int lane = tid & 31;
    const int wid  = tid >> 5;
    const int wm   = (wid >> 2) * 64;
    const int wn   = (wid & 3) * 32;
    const int bm   = blockIdx.y * 128;
    const int bn   = blockIdx.x * 128;

    const int nc = K / 64;

    // stage 64-wide chunk c into buffer cb (planes: A, Bh[, Bl])
    auto stage = [&](int c, int cb) {
        const int kc = c * 64;
        #pragma unroll
        for (int i = 0; i < 4 * PPB; i++) {
            const int p   = i >> 2;                      // 0:A 1:Bh 2:Bl
            const int rem = (i & 3) * 256 + tid;         // 0..1023
            const int row = rem >> 3;
            const int c8  = (rem & 7) * 8;
            const half_t* src;
            if      (p == 0) src = Aih + (size_t)(bm + row) * K + kc + c8;
            else if (p == 1) src = Bih + (size_t)(bn + row) * K + kc + c8;
            else             src = Bil + (size_t)(bn + row) * K + kc + c8;
            uint32_t dst = base + (uint32_t)((cb * PPB + p) * PL + row * ASTR + c8) * 2;
            cp_async16(dst, src);
        }
    };

    float acc[4][4][4] = {};

    stage(0, 0);
    CP_COMMIT();

    // invariant pieces of ldsm addresses
    const uint32_t aoff0 =
        (uint32_t)((wm + (lane & 15)) * (ASTR * 2) + (((lane >> 4) << 3)) * 2);
    const uint32_t boff0 =
        (uint32_t)((wn + (lane & 7) + ((lane >> 4) << 3)) * (ASTR * 2) +
                   ((((lane >> 3) & 1) << 3)) * 2);

    for (int c = 0; c < nc; c++) {
        CP_WAIT0();
        __syncthreads();
        if (c + 1 < nc) {
            stage(c + 1, (c + 1) & 1);
            CP_COMMIT();
        }

        const int cb = c & 1;
        const uint32_t uA  = base + (uint32_t)((cb * PPB + 0) * PL) * 2;
        const uint32_t uBh = base + (uint32_t)((cb * PPB + 1) * PL) * 2;
        const uint32_t uBl = base + (uint32_t)((cb * PPB + 2) * PL) * 2;

        #pragma unroll
        for (int kb = 0; kb < 4; kb++) {
            const uint32_t aoff = aoff0 + kb * 32;      // 16 fp16 per kb
            uint32_t ah[4][4];
            #pragma unroll
            for (int mi = 0; mi < 4; mi++)
                ldsm_x4(ah[mi], uA + aoff + mi * 16 * (ASTR * 2));
            #pragma unroll
            for (int njp = 0; njp < 2; njp++) {
                const uint32_t boff = boff0 + njp * 16 * (ASTR * 2) + kb * 32;
                uint32_t bh4[4], bl4[4];
                ldsm_x4(bh4, uBh + boff);
                if (PLANES == 2) ldsm_x4(bl4, uBl + boff);
                #pragma unroll
                for (int mi = 0; mi < 4; mi++) {
                    #pragma unroll
                    for (int sub = 0; sub < 2; sub++) {
                        float* d = acc[mi][njp * 2 + sub];
                        mma_f16(d, ah[mi], &bh4[sub * 2]);
                        if (PLANES == 2) mma_f16(d, ah[mi], &bl4[sub * 2]);
                    }
                }
            }
        }
    }

    // ---- epilogue ----
    const float sc = (bn < qcols) ? (SCALE_ * LOG2E_) : 1.0f;
    #pragma unroll
    for (int mi = 0; mi < 4; mi++) {
        #pragma unroll
        for (int nj = 0; nj < 4; nj++) {
            int row = bm + wm + mi * 16 + (lane >> 2);
            int col = bn + wn + nj * 8 + (lane & 3) * 2;
            if (Cf) {
                float b0 = bias ? bias[col] : 0.f;
                float b1 = bias ? bias[col + 1] : 0.f;
                float2 v0 = {acc[mi][nj][0] + b0, acc[mi][nj][1] + b1};
                float2 v1 = {acc[mi][nj][2] + b0, acc[mi][nj][3] + b1};
                *(float2*)(Cf + (size_t)row * N + col) = v0;
                *(float2*)(Cf + (size_t)(row + 8) * N + col) = v1;
            } else {
                half_t h0, l0, h1, l1, h2, l2, h3, l3;
                split_f16(acc[mi][nj][0] * sc, h0, l0);
                split_f16(acc[mi][nj][1] * sc, h1, l1);
                split_f16(acc[mi][nj][2] * sc, h2, l2);
                split_f16(acc[mi][nj][3] * sc, h3, l3);
                *(uint32_t*)(Ch + (size_t)row * N + col)       = pack2h(h0, h1);
                *(uint32_t*)(Ch + (size_t)(row + 8) * N + col) = pack2h(h2, h3);
                *(uint32_t*)(Cl + (size_t)row * N + col)       = pack2h(l0, l1);
                *(uint32_t*)(Cl + (size_t)(row + 8) * N + col) = pack2h(l2, l3);
            }
        }
    }
}

// ===========================================================================
// Flash attention (fp16 tensor cores). One CTA = 128 q rows of one (b,h).
// 8 warps x 16 q rows, kv tiles of 64. Q: 1 plane (pre-scaled by 0.125*log2e).
// K: 2 planes; V: 1 plane (hi). fp16x2 ex2 softmax; row-sum l via ones-MMA.
// 3-region cp.async ring (prefetch distance 2). 2 CTAs/SM.
// ===========================================================================
#define FSTR 72
#define FPLANE (64 * FSTR)                 // 4608 fp16 units
#define FREG  (3 * FPLANE)                 // Kh,Kl,Vh = 13824 units
#define FLASH_SMEM (3 * FREG * 2)          // 82944 B

__global__ __launch_bounds__(256, 2) void flash_kernel(
    const half_t* __restrict__ qh_g, const half_t* __restrict__ ql_g,
    half_t* __restrict__ outh)
{
    extern __shared__ __align__(16) half_t fsm[];
    const uint32_t baseu = smem_u32(fsm);

    const int tid  = threadIdx.x;
    const int lane = tid & 31;
    const int w    = tid >> 5;
    const int bh   = blockIdx.y;
    const int b    = bh / H_;
    const int h    = bh % H_;
    const int q0   = blockIdx.x * 128;

    const size_t rowbase = (size_t)b * N_ * QKV_N;
    const int qoff = h * DH_;
    const int koff = DIM_ + h * DH_;
    const int voff = 2 * DIM_ + h * DH_;

    const int NT = N_ / 64;   // 32 kv tiles

    // KV staging into region base offset reg (fp16 units): planes Kh,Kl,Vh
    auto stage_kv = [&](int t, uint32_t reg) {
        const int kr0 = t * 64;
        #pragma unroll
        for (int i = 0; i < 6; i++) {
            const int p   = i >> 1;                   // 0:Kh 1:Kl 2:Vh
            const int rem = (i & 1) * 256 + tid;      // 0..511
            const int row = rem >> 3;
            const int c8  = (rem & 7) * 8;
            const size_t g = rowbase + (size_t)(kr0 + row) * QKV_N +
                             ((p < 2) ? koff : voff) + c8;
            const half_t* src = ((p == 1) ? ql_g : qh_g) + g;
            uint32_t dst = baseu + (reg + p * FPLANE + row * FSTR + c8) * 2;
            cp_async16(dst, src);
        }
    };

    // prefetch tiles 0 and 1 into regions 0, 1
    stage_kv(0, 0);
    CP_COMMIT();
    stage_kv(1, FREG);
    CP_COMMIT();

    // ---- stage Q tile (hi plane only) into region 2 (plain stores) ----
    #pragma unroll
    for (int i = 0; i < 4; i++) {
        int idx = tid + i * 256;
        int row = idx >> 3, c8 = (idx & 7) * 8;
        size_t g = rowbase + (size_t)(q0 + row) * QKV_N + qoff + c8;
        *(float4*)&fsm[2 * FREG + row * FSTR + c8] = *(const float4*)(qh_g + g);
    }
    __syncthreads();

    // ---- preload Q fragments from region 2 ----
    uint32_t qh[4][4];
    #pragma unroll
    for (int kb = 0; kb < 4; kb++) {
        uint32_t off = (uint32_t)((w * 16 + (lane & 15)) * (FSTR * 2) +
                                  (kb * 16 + ((lane >> 4) << 3)) * 2);
        ldsm_x4(qh[kb], baseu + 2 * FREG * 2 + off);
    }

    // invariant address parts
    const uint32_t koff0 = (uint32_t)(((lane & 7) + ((lane >> 4) << 3)) * (FSTR * 2) +
                                      ((((lane >> 3) & 1) << 3)) * 2);
    const uint32_t voff0 = (uint32_t)(((lane & 7) + (((lane >> 3) & 1) << 3)) * (FSTR * 2) +
                                      (((lane >> 4) << 3)) * 2);
    const uint32_t ones2[2] = {0x3C003C00u, 0x3C003C00u};

    float o[8][4] = {};
    float m0 = -1e30f, m1 = -1e30f, l0 = 0.f, l1 = 0.f;

    int region = 0;   // region index of tile t (cycles 0,1,2)

    for (int t = 0; t < NT; t++) {
        if (t < NT - 1) { CP_WAIT1(); } else { CP_WAIT0(); }
        __syncthreads();
        if (t + 2 < NT) {
            int r2 = region + 2; if (r2 >= 3) r2 -= 3;
            stage_kv(t + 2, (uint32_t)r2 * FREG);
            CP_COMMIT();
        }

        const uint32_t reg = (uint32_t)region * FREG;
        const uint32_t uKh = baseu + reg * 2;
        const uint32_t uKl = baseu + (reg + FPLANE) * 2;
        const uint32_t uVh = baseu + (reg + 2 * FPLANE) * 2;

        // ---- S = Q @ (Kh + Kl)^T  (log2 domain) ----
        float s[8][4] = {};
        #pragma unroll
        for (int kb = 0; kb < 4; kb++) {
            #pragma unroll
            for (int njp = 0; njp < 4; njp++) {
                uint32_t off = koff0 + njp * 16 * (FSTR * 2) + kb * 32;
                uint32_t kbh[4], kbl[4];
                ldsm_x4(kbh, uKh + off);
                ldsm_x4(kbl, uKl + off);
                #pragma unroll
                for (int sub = 0; sub < 2; sub++) {
                    float* d = s[njp * 2 + sub];
                    mma_f16(d, qh[kb], &kbh[sub * 2]);
                    mma_f16(d, qh[kb], &kbl[sub * 2]);
                }
            }
        }

        // ---- online softmax (base-2): max reduction in fp32 ----
        float mx0 = -1e30f, mx1 = -1e30f;
        #pragma unroll
        for (int nj = 0; nj < 8; nj++) {
            mx0 = fmaxf(mx0, fmaxf(s[nj][0], s[nj][1]));
            mx1 = fmaxf(mx1, fmaxf(s[nj][2], s[nj][3]));
        }
        mx0 = fmaxf(mx0, __shfl_xor_sync(0xffffffffu, mx0, 1));
        mx0 = fmaxf(mx0, __shfl_xor_sync(0xffffffffu, mx0, 2));
        mx1 = fmaxf(mx1, __shfl_xor_sync(0xffffffffu, mx1, 1));
        mx1 = fmaxf(mx1, __shfl_xor_sync(0xffffffffu, mx1, 2));
        float mn0 = fmaxf(m0, mx0), mn1 = fmaxf(m1, mx1);
        float a0 = ex2(m0 - mn0), a1 = ex2(m1 - mn1);
        m0 = mn0; m1 = mn1;

        // ---- P = exp2(s - m) directly in fp16x2 (P fragments) ----
        uint32_t pa[4][4];
        #pragma unroll
        for (int kb = 0; kb < 4; kb++) {
            #pragma unroll
            for (int hf = 0; hf < 2; hf++) {
                const float* sc = s[2 * kb + hf];
                pa[kb][hf * 2 + 0] = ex2_h2(packf2h(sc[0] - mn0, sc[1] - mn0));
                pa[kb][hf * 2 + 1] = ex2_h2(packf2h(sc[2] - mn1, sc[3] - mn1));
            }
        }

        // ---- row sums l via ones-MMA (exact fp32 sum of the fp16 P) ----
        float lacc[4] = {0.f, 0.f, 0.f, 0.f};
        #pragma unroll
        for (int kb = 0; kb < 4; kb++)
            mma_f16(lacc, pa[kb], ones2);
        l0 = l0 * a0 + lacc[0];
        l1 = l1 * a1 + lacc[2];

        #pragma unroll
        for (int dj = 0; dj < 8; dj++) {
            o[dj][0] *= a0; o[dj][1] *= a0;
            o[dj][2] *= a1; o[dj][3] *= a1;
        }

        // ---- O += P @ Vh (single plane) ----
        #pragma unroll
        for (int kb = 0; kb < 4; kb++) {
            #pragma unroll
            for (int djp = 0; djp < 4; djp++) {
                uint32_t off = voff0 + kb * 16 * (FSTR * 2) + djp * 32;
                uint32_t vbh[4];
                ldsm_x4_t(vbh, uVh + off);
                #pragma unroll
                for (int sub = 0; sub < 2; sub++) {
                    float* d = o[djp * 2 + sub];
                    mma_f16(d, pa[kb], &vbh[sub * 2]);
                }
            }
        }

        region++; if (region >= 3) region = 0;
    }

    // ---- normalize + fp16 write (1 plane) ----
    float inv0 = 1.0f / l0, inv1 = 1.0f / l1;
    size_t row0 = (size_t)(b * N_ + q0 + w * 16 + (lane >> 2));
    #pragma unroll
    for (int dj = 0; dj < 8; dj++) {
        int col = h * DH_ + dj * 8 + (lane & 3) * 2;
        *(uint32_t*)(outh + row0 * DIM_ + col) =
            packf2h(o[dj][0] * inv0, o[dj][1] * inv0);
        *(uint32_t*)(outh + (row0 + 8) * DIM_ + col) =
            packf2h(o[dj][2] * inv1, o[dj][3] * inv1);
    }
}

// ---------------------------------------------------------------------------
// Launch
// ---------------------------------------------------------------------------
extern "C" void kernel_launch(void* const* d_in, const int* in_sizes, int n_in,
                              void* d_out, int out_size)
{
    const float* x      = (const float*)d_in[0];
    const float* w_qkv  = (const float*)d_in[1];
    const float* w_proj = (const float*)d_in[2];
    const float* b_proj = (const float*)d_in[3];
    float* out = (float*)d_out;

    half_t *xh, *wqh, *wql, *wph, *qkvh, *qkvl, *ah;
    cudaGetSymbolAddress((void**)&xh, g_xh);
    cudaGetSymbolAddress((void**)&wqh, g_wqh);
    cudaGetSymbolAddress((void**)&wql, g_wql);
    cudaGetSymbolAddress((void**)&wph, g_wph);
    cudaGetSymbolAddress((void**)&qkvh, g_qkvh);
    cudaGetSymbolAddress((void**)&qkvl, g_qkvl);
    cudaGetSymbolAddress((void**)&ah, g_ah);

    cudaFuncSetAttribute(tgemm_kernel<2>,
                         cudaFuncAttributeMaxDynamicSharedMemorySize, TG_SMEM2);
    cudaFuncSetAttribute(tgemm_kernel<1>,
                         cudaFuncAttributeMaxDynamicSharedMemorySize, TG_SMEM1);
    cudaFuncSetAttribute(flash_kernel,
                         cudaFuncAttributeMaxDynamicSharedMemorySize, FLASH_SMEM);

    // 0) converts
    {
        int n4 = M_TOT * DIM_ / 4;
        conv_f16_kernel<<<(n4 + 255) / 256, 256>>>(x, xh, n4);
        dim3 tb(32, 8);
        transpose_split_kernel<<<dim3(QKV_N / 32, DIM_ / 32), tb>>>(w_qkv, wqh, wql, DIM_, QKV_N);
        transpose_split_kernel<<<dim3(DIM_ / 32, DIM_ / 32), tb>>>(w_proj, wph, nullptr, DIM_, DIM_);
    }

    // 1) QKV = X @ Wqkv -> fp16 planes (Q cols scaled by 0.125*log2e)
    dim3 g1(QKV_N / 128, M_TOT / 128);
    tgemm_kernel<2><<<g1, 256, TG_SMEM2>>>(xh, wqh, wql,
                                           nullptr, qkvh, qkvl,
                                           M_TOT, QKV_N, DIM_, nullptr, DIM_);

    // 2) Flash attention
    dim3 g2(N_ / 128, B_ * H_);
    flash_kernel<<<g2, 256, FLASH_SMEM>>>(qkvh, qkvl, ah);

    // 3) OUT = ATTN @ Wproj + bias (fp32), single-plane weights
    dim3 g3(DIM_ / 128, M_TOT / 128);
    tgemm_kernel<1><<<g3, 256, TG_SMEM1>>>(ah, wph, nullptr,
                                           out, nullptr, nullptr,
                                           M_TOT, DIM_, DIM_, b_proj, 0);
}

// round 13
// speedup vs baseline: 7.7969x; 1.4570x over previous
#include <cuda_runtime.h>
#include <cuda_fp16.h>
#include <cstdint>

#define B_    4
#define N_    2048
#define DIM_  768
#define H_    12
#define DH_   64
#define M_TOT (B_ * N_)       // 8192
#define QKV_N (3 * DIM_)      // 2304
#define SCALE_ 0.125f
#define LOG2E_ 1.4426950408889634f

typedef __half half_t;

// --------------------------- device scratch (no allocs) --------------------
__device__ half_t g_xh[(size_t)M_TOT * DIM_];     // X fp16
__device__ half_t g_wqh[(size_t)QKV_N * DIM_];    // Wqkv^T fp16 [2304,768]
__device__ half_t g_wph[(size_t)DIM_ * DIM_];     // Wproj^T fp16
__device__ half_t g_qkvh[(size_t)M_TOT * QKV_N];  // QKV fp16 (Q pre-scaled)
__device__ half_t g_ah[(size_t)M_TOT * DIM_];     // attn-out fp16

// ===========================================================================
// helpers
// ===========================================================================
__device__ __forceinline__ uint32_t smem_u32(const void* p) {
    uint32_t a;
    asm("{ .reg .u64 t; cvta.to.shared.u64 t, %1; cvt.u32.u64 %0, t; }"
        : "=r"(a) : "l"(p));
    return a;
}
__device__ __forceinline__ void ldsm_x4(uint32_t* r, uint32_t addr) {
    asm volatile("ldmatrix.sync.aligned.m8n8.x4.shared.b16 {%0,%1,%2,%3}, [%4];"
                 : "=r"(r[0]), "=r"(r[1]), "=r"(r[2]), "=r"(r[3]) : "r"(addr));
}
__device__ __forceinline__ void ldsm_x4_t(uint32_t* r, uint32_t addr) {
    asm volatile("ldmatrix.sync.aligned.m8n8.x4.trans.shared.b16 {%0,%1,%2,%3}, [%4];"
                 : "=r"(r[0]), "=r"(r[1]), "=r"(r[2]), "=r"(r[3]) : "r"(addr));
}
__device__ __forceinline__ void mma_f16(float* d, const uint32_t* a, const uint32_t* b) {
    asm volatile("mma.sync.aligned.m16n8k16.row.col.f32.f16.f16.f32 "
                 "{%0,%1,%2,%3}, {%4,%5,%6,%7}, {%8,%9}, {%0,%1,%2,%3};"
                 : "+f"(d[0]), "+f"(d[1]), "+f"(d[2]), "+f"(d[3])
                 : "r"(a[0]), "r"(a[1]), "r"(a[2]), "r"(a[3]), "r"(b[0]), "r"(b[1]));
}
__device__ __forceinline__ uint32_t packf2h(float a, float b) {
    __half2 t = __floats2half2_rn(a, b);   // .x = a
    return *reinterpret_cast<uint32_t*>(&t);
}
__device__ __forceinline__ float ex2(float x) {
    float y; asm("ex2.approx.f32 %0, %1;" : "=f"(y) : "f"(x)); return y;
}
__device__ __forceinline__ uint32_t ex2_h2(uint32_t x) {
    uint32_t y; asm("ex2.approx.f16x2 %0, %1;" : "=r"(y) : "r"(x)); return y;
}
__device__ __forceinline__ void cp_async16(uint32_t dst, const void* src) {
    asm volatile("cp.async.cg.shared.global [%0], [%1], 16;" :: "r"(dst), "l"(src));
}
#define CP_COMMIT() asm volatile("cp.async.commit_group;" ::: "memory")
#define CP_WAIT0()  asm volatile("cp.async.wait_group 0;" ::: "memory")
#define CP_WAIT1()  asm volatile("cp.async.wait_group 1;" ::: "memory")

// ===========================================================================
// convert kernels
// ===========================================================================
__global__ void conv_f16_kernel(const float* __restrict__ X,
                                half_t* __restrict__ Xh, int n4)
{
    int idx = blockIdx.x * blockDim.x + threadIdx.x;
    if (idx >= n4) return;
    float4 v = ((const float4*)X)[idx];
    ((uint32_t*)Xh)[idx * 2]     = packf2h(v.x, v.y);
    ((uint32_t*)Xh)[idx * 2 + 1] = packf2h(v.z, v.w);
}

// W [K][Nw] fp32 -> Th [Nw][K] fp16 (transpose)
__global__ void transpose_f16_kernel(const float* __restrict__ W,
                                     half_t* __restrict__ Th, int K, int Nw)
{
    __shared__ float t[32][33];
    const int n0 = blockIdx.x * 32, k0 = blockIdx.y * 32;
    const int tx = threadIdx.x, ty = threadIdx.y;   // (32, 8)
    #pragma unroll
    for (int i = 0; i < 32; i += 8)
        t[ty + i][tx] = W[(size_t)(k0 + ty + i) * Nw + n0 + tx];
    __syncthreads();
    #pragma unroll
    for (int i = 0; i < 32; i += 8)
        Th[(size_t)(n0 + ty + i) * K + k0 + tx] = __float2half_rn(t[tx][ty + i]);
}

// ===========================================================================
// tgemm: C[M,N] = A[M,K] @ B^T (B stored [N][K] fp16; A fp16). 128x128 block,
// BK=64, 8 warps of 64x32. cp.async 2-stage pipeline, 2 planes per buffer.
// 2 CTAs/SM. Output: fp32+bias (Cf) or single fp16 plane (Ch).
// ===========================================================================
#define ASTR 72
#define PL   (128 * ASTR)                  // fp16 units per plane = 9216
#define TG_SMEM (2 * 2 * PL * 2)           // 73728 B

__global__ __launch_bounds__(256, 2) void tgemm_kernel(
    const half_t* __restrict__ Aih, const half_t* __restrict__ Bih,
    float* __restrict__ Cf, half_t* __restrict__ Ch,
    int M, int N, int K, const float* __restrict__ bias, int qcols)
{
    extern __shared__ __align__(16) half_t dsm[];
    const uint32_t base = smem_u32(dsm);

    const int tid  = threadIdx.x;
    const int lane = tid & 31;
    const int wid  = tid >> 5;
    const int wm   = (wid >> 2) * 64;
    const int wn   = (wid & 3) * 32;
    const int bm   = blockIdx.y * 128;
    const int bn   = blockIdx.x * 128;

    const int nc = K / 64;

    // stage 64-wide chunk c into buffer cb (2 planes: A, B)
    auto stage = [&](int c, int cb) {
        const int kc = c * 64;
        #pragma unroll
        for (int i = 0; i < 8; i++) {
            const int p   = i >> 2;                      // 0:A 1:B
            const int rem = (i & 3) * 256 + tid;         // 0..1023
            const int row = rem >> 3;
            const int c8  = (rem & 7) * 8;
            const half_t* src = (p == 0)
                ? Aih + (size_t)(bm + row) * K + kc + c8
                : Bih + (size_t)(bn + row) * K + kc + c8;
            uint32_t dst = base + (uint32_t)((cb * 2 + p) * PL + row * ASTR + c8) * 2;
            cp_async16(dst, src);
        }
    };

    float acc[4][4][4] = {};

    stage(0, 0);
    CP_COMMIT();

    const uint32_t aoff0 =
        (uint32_t)((wm + (lane & 15)) * (ASTR * 2) + (((lane >> 4) << 3)) * 2);
    const uint32_t boff0 =
        (uint32_t)((wn + (lane & 7) + ((lane >> 4) << 3)) * (ASTR * 2) +
                   ((((lane >> 3) & 1) << 3)) * 2);

    for (int c = 0; c < nc; c++) {
        CP_WAIT0();
        __syncthreads();
        if (c + 1 < nc) {
            stage(c + 1, (c + 1) & 1);
            CP_COMMIT();
        }

        const int cb = c & 1;
        const uint32_t uA = base + (uint32_t)((cb * 2 + 0) * PL) * 2;
        const uint32_t uB = base + (uint32_t)((cb * 2 + 1) * PL) * 2;

        #pragma unroll
        for (int kb = 0; kb < 4; kb++) {
            const uint32_t aoff = aoff0 + kb * 32;
            uint32_t ah[4][4];
            #pragma unroll
            for (int mi = 0; mi < 4; mi++)
                ldsm_x4(ah[mi], uA + aoff + mi * 16 * (ASTR * 2));
            #pragma unroll
            for (int njp = 0; njp < 2; njp++) {
                const uint32_t boff = boff0 + njp * 16 * (ASTR * 2) + kb * 32;
                uint32_t bh4[4];
                ldsm_x4(bh4, uB + boff);
                #pragma unroll
                for (int mi = 0; mi < 4; mi++) {
                    #pragma unroll
                    for (int sub = 0; sub < 2; sub++)
                        mma_f16(acc[mi][njp * 2 + sub], ah[mi], &bh4[sub * 2]);
                }
            }
        }
    }

    // ---- epilogue ----
    const float sc = (bn < qcols) ? (SCALE_ * LOG2E_) : 1.0f;
    #pragma unroll
    for (int mi = 0; mi < 4; mi++) {
        #pragma unroll
        for (int nj = 0; nj < 4; nj++) {
            int row = bm + wm + mi * 16 + (lane >> 2);
            int col = bn + wn + nj * 8 + (lane & 3) * 2;
            if (Cf) {
                float b0 = bias ? bias[col] : 0.f;
                float b1 = bias ? bias[col + 1] : 0.f;
                float2 v0 = {acc[mi][nj][0] + b0, acc[mi][nj][1] + b1};
                float2 v1 = {acc[mi][nj][2] + b0, acc[mi][nj][3] + b1};
                *(float2*)(Cf + (size_t)row * N + col) = v0;
                *(float2*)(Cf + (size_t)(row + 8) * N + col) = v1;
            } else {
                *(uint32_t*)(Ch + (size_t)row * N + col) =
                    packf2h(acc[mi][nj][0] * sc, acc[mi][nj][1] * sc);
                *(uint32_t*)(Ch + (size_t)(row + 8) * N + col) =
                    packf2h(acc[mi][nj][2] * sc, acc[mi][nj][3] * sc);
            }
        }
    }
}

// ===========================================================================
// Flash attention (pure fp16 tensor cores). One CTA = 128 q rows of one (b,h).
// 8 warps x 16 q rows, kv tiles of 64. Q,K,V all single fp16 planes.
// fp16x2 ex2 softmax; row-sum l via ones-MMA. 3-region cp.async ring
// (prefetch distance 2; Q parks in region 2). 2 CTAs/SM.
// ===========================================================================
#define FSTR 72
#define FPLANE (64 * FSTR)                 // 4608 fp16 units
#define FREG  (2 * FPLANE)                 // K,V = 9216 units (== Q tile size)
#define FLASH_SMEM (3 * FREG * 2)          // 55296 B

__global__ __launch_bounds__(256, 2) void flash_kernel(
    const half_t* __restrict__ qkv_g, half_t* __restrict__ outh)
{
    extern __shared__ __align__(16) half_t fsm[];
    const uint32_t baseu = smem_u32(fsm);

    const int tid  = threadIdx.x;
    const int lane = tid & 31;
    const int w    = tid >> 5;
    const int bh   = blockIdx.y;
    const int b    = bh / H_;
    const int h    = bh % H_;
    const int q0   = blockIdx.x * 128;

    const size_t rowbase = (size_t)b * N_ * QKV_N;
    const int qoff = h * DH_;
    const int koff = DIM_ + h * DH_;
    const int voff = 2 * DIM_ + h * DH_;

    const int NT = N_ / 64;   // 32 kv tiles

    // KV staging into region base offset reg (fp16 units): planes K, V
    auto stage_kv = [&](int t, uint32_t reg) {
        const int kr0 = t * 64;
        #pragma unroll
        for (int i = 0; i < 4; i++) {
            const int p   = i >> 1;                   // 0:K 1:V
            const int rem = (i & 1) * 256 + tid;      // 0..511
            const int row = rem >> 3;
            const int c8  = (rem & 7) * 8;
            const size_t g = rowbase + (size_t)(kr0 + row) * QKV_N +
                             ((p == 0) ? koff : voff) + c8;
            uint32_t dst = baseu + (reg + p * FPLANE + row * FSTR + c8) * 2;
            cp_async16(dst, qkv_g + g);
        }
    };

    // prefetch tiles 0 and 1 into regions 0, 1
    stage_kv(0, 0);
    CP_COMMIT();
    stage_kv(1, FREG);
    CP_COMMIT();

    // ---- stage Q tile into region 2 (plain stores) ----
    #pragma unroll
    for (int i = 0; i < 4; i++) {
        int idx = tid + i * 256;
        int row = idx >> 3, c8 = (idx & 7) * 8;
        size_t g = rowbase + (size_t)(q0 + row) * QKV_N + qoff + c8;
        *(float4*)&fsm[2 * FREG + row * FSTR + c8] = *(const float4*)(qkv_g + g);
    }
    __syncthreads();

    // ---- preload Q fragments from region 2 ----
    uint32_t qh[4][4];
    #pragma unroll
    for (int kb = 0; kb < 4; kb++) {
        uint32_t off = (uint32_t)((w * 16 + (lane & 15)) * (FSTR * 2) +
                                  (kb * 16 + ((lane >> 4) << 3)) * 2);
        ldsm_x4(qh[kb], baseu + 2 * FREG * 2 + off);
    }

    const uint32_t koff0 = (uint32_t)(((lane & 7) + ((lane >> 4) << 3)) * (FSTR * 2) +
                                      ((((lane >> 3) & 1) << 3)) * 2);
    const uint32_t voff0 = (uint32_t)(((lane & 7) + (((lane >> 3) & 1) << 3)) * (FSTR * 2) +
                                      (((lane >> 4) << 3)) * 2);
    const uint32_t ones2[2] = {0x3C003C00u, 0x3C003C00u};

    float o[8][4] = {};
    float m0 = -1e30f, m1 = -1e30f, l0 = 0.f, l1 = 0.f;

    int region = 0;

    for (int t = 0; t < NT; t++) {
        if (t < NT - 1) { CP_WAIT1(); } else { CP_WAIT0(); }
        __syncthreads();
        if (t + 2 < NT) {
            int r2 = region + 2; if (r2 >= 3) r2 -= 3;
            stage_kv(t + 2, (uint32_t)r2 * FREG);
            CP_COMMIT();
        }

        const uint32_t reg = (uint32_t)region * FREG;
        const uint32_t uK = baseu + reg * 2;
        const uint32_t uV = baseu + (reg + FPLANE) * 2;

        // ---- S = Q @ K^T  (log2 domain) ----
        float s[8][4] = {};
        #pragma unroll
        for (int kb = 0; kb < 4; kb++) {
            #pragma unroll
            for (int njp = 0; njp < 4; njp++) {
                uint32_t off = koff0 + njp * 16 * (FSTR * 2) + kb * 32;
                uint32_t kb4[4];
                ldsm_x4(kb4, uK + off);
                #pragma unroll
                for (int sub = 0; sub < 2; sub++)
                    mma_f16(s[njp * 2 + sub], qh[kb], &kb4[sub * 2]);
            }
        }

        // ---- online softmax (base-2): max reduction in fp32 ----
        float mx0 = -1e30f, mx1 = -1e30f;
        #pragma unroll
        for (int nj = 0; nj < 8; nj++) {
            mx0 = fmaxf(mx0, fmaxf(s[nj][0], s[nj][1]));
            mx1 = fmaxf(mx1, fmaxf(s[nj][2], s[nj][3]));
        }
        mx0 = fmaxf(mx0, __shfl_xor_sync(0xffffffffu, mx0, 1));
        mx0 = fmaxf(mx0, __shfl_xor_sync(0xffffffffu, mx0, 2));
        mx1 = fmaxf(mx1, __shfl_xor_sync(0xffffffffu, mx1, 1));
        mx1 = fmaxf(mx1, __shfl_xor_sync(0xffffffffu, mx1, 2));
        float mn0 = fmaxf(m0, mx0), mn1 = fmaxf(m1, mx1);
        float a0 = ex2(m0 - mn0), a1 = ex2(m1 - mn1);
        m0 = mn0; m1 = mn1;

        // ---- P = exp2(s - m) directly in fp16x2 ----
        uint32_t pa[4][4];
        #pragma unroll
        for (int kb = 0; kb < 4; kb++) {
            #pragma unroll
            for (int hf = 0; hf < 2; hf++) {
                const float* sc = s[2 * kb + hf];
                pa[kb][hf * 2 + 0] = ex2_h2(packf2h(sc[0] - mn0, sc[1] - mn0));
                pa[kb][hf * 2 + 1] = ex2_h2(packf2h(sc[2] - mn1, sc[3] - mn1));
            }
        }

        // ---- row sums l via ones-MMA ----
        float lacc[4] = {0.f, 0.f, 0.f, 0.f};
        #pragma unroll
        for (int kb = 0; kb < 4; kb++)
            mma_f16(lacc, pa[kb], ones2);
        l0 = l0 * a0 + lacc[0];
        l1 = l1 * a1 + lacc[2];

        #pragma unroll
        for (int dj = 0; dj < 8; dj++) {
            o[dj][0] *= a0; o[dj][1] *= a0;
            o[dj][2] *= a1; o[dj][3] *= a1;
        }

        // ---- O += P @ V ----
        #pragma unroll
        for (int kb = 0; kb < 4; kb++) {
            #pragma unroll
            for (int djp = 0; djp < 4; djp++) {
                uint32_t off = voff0 + kb * 16 * (FSTR * 2) + djp * 32;
                uint32_t vb4[4];
                ldsm_x4_t(vb4, uV + off);
                #pragma unroll
                for (int sub = 0; sub < 2; sub++)
                    mma_f16(o[djp * 2 + sub], pa[kb], &vb4[sub * 2]);
            }
        }

        region++; if (region >= 3) region = 0;
    }

    // ---- normalize + fp16 write ----
    float inv0 = 1.0f / l0, inv1 = 1.0f / l1;
    size_t row0 = (size_t)(b * N_ + q0 + w * 16 + (lane >> 2));
    #pragma unroll
    for (int dj = 0; dj < 8; dj++) {
        int col = h * DH_ + dj * 8 + (lane & 3) * 2;
        *(uint32_t*)(outh + row0 * DIM_ + col) =
            packf2h(o[dj][0] * inv0, o[dj][1] * inv0);
        *(uint32_t*)(outh + (row0 + 8) * DIM_ + col) =
            packf2h(o[dj][2] * inv1, o[dj][3] * inv1);
    }
}

// ---------------------------------------------------------------------------
// Launch
// ---------------------------------------------------------------------------
extern "C" void kernel_launch(void* const* d_in, const int* in_sizes, int n_in,
                              void* d_out, int out_size)
{
    const float* x      = (const float*)d_in[0];
    const float* w_qkv  = (const float*)d_in[1];
    const float* w_proj = (const float*)d_in[2];
    const float* b_proj = (const float*)d_in[3];
    float* out = (float*)d_out;

    half_t *xh, *wqh, *wph, *qkvh, *ah;
    cudaGetSymbolAddress((void**)&xh, g_xh);
    cudaGetSymbolAddress((void**)&wqh, g_wqh);
    cudaGetSymbolAddress((void**)&wph, g_wph);
    cudaGetSymbolAddress((void**)&qkvh, g_qkvh);
    cudaGetSymbolAddress((void**)&ah, g_ah);

    cudaFuncSetAttribute(tgemm_kernel,
                         cudaFuncAttributeMaxDynamicSharedMemorySize, TG_SMEM);
    cudaFuncSetAttribute(flash_kernel,
                         cudaFuncAttributeMaxDynamicSharedMemorySize, FLASH_SMEM);

    // 0) converts
    {
        int n4 = M_TOT * DIM_ / 4;
        conv_f16_kernel<<<(n4 + 255) / 256, 256>>>(x, xh, n4);
        dim3 tb(32, 8);
        transpose_f16_kernel<<<dim3(QKV_N / 32, DIM_ / 32), tb>>>(w_qkv, wqh, DIM_, QKV_N);
        transpose_f16_kernel<<<dim3(DIM_ / 32, DIM_ / 32), tb>>>(w_proj, wph, DIM_, DIM_);
    }

    // 1) QKV = X @ Wqkv -> fp16 (Q cols scaled by 0.125*log2e)
    dim3 g1(QKV_N / 128, M_TOT / 128);
    tgemm_kernel<<<g1, 256, TG_SMEM>>>(xh, wqh, nullptr, qkvh,
                                       M_TOT, QKV_N, DIM_, nullptr, DIM_);

    // 2) Flash attention
    dim3 g2(N_ / 128, B_ * H_);
    flash_kernel<<<g2, 256, FLASH_SMEM>>>(qkvh, ah);

    // 3) OUT = ATTN @ Wproj + bias (fp32)
    dim3 g3(DIM_ / 128, M_TOT / 128);
    tgemm_kernel<<<g3, 256, TG_SMEM>>>(ah, wph, out, nullptr,
                                       M_TOT, DIM_, DIM_, b_proj, 0);
}